// round 10
// baseline (speedup 1.0000x reference)
#include <cuda_runtime.h>
#include <cuda_bf16.h>
#include <math.h>

// Problem constants
#define Bsz  4
#define Tsz  4096
#define Dsz  1024
#define Hn   16
#define DIMh 64
#define Ln   8
#define KBn  4
#define Rn   16
#define Sn   128
#define BT   (Bsz*Tsz)      // 16384
#define BHn  (Bsz*Hn)       // 64

// ---------------- scratch (device globals: no allocation allowed) ----------
__device__ float g_Q  [(size_t)BT*Dsz];
__device__ float g_K  [(size_t)BT*Dsz];
__device__ float g_V  [(size_t)BT*Dsz];
__device__ float g_ATT[(size_t)BT*Dsz];
__device__ float g_bK [(size_t)BHn*Sn*DIMh];
__device__ float g_bV [(size_t)BHn*Sn*DIMh];
__device__ float g_bA [(size_t)BHn*Sn];

// ======================= bf16 mma.sync helpers ==============================
__device__ __forceinline__ void mma_bf16(float c[4], const unsigned a[4],
                                         const unsigned b[2]) {
    asm volatile(
        "mma.sync.aligned.m16n8k16.row.col.f32.bf16.bf16.f32 "
        "{%0,%1,%2,%3}, {%4,%5,%6,%7}, {%8,%9}, {%0,%1,%2,%3};"
        : "+f"(c[0]), "+f"(c[1]), "+f"(c[2]), "+f"(c[3])
        : "r"(a[0]), "r"(a[1]), "r"(a[2]), "r"(a[3]), "r"(b[0]), "r"(b[1]));
}

// ======================= bf16 split GEMM (projections) ======================
// C[16384,1024] = A[16384,1024] @ B[1024,1024] (*rowscale)(+bias)
#define BTSZ 1088       // words per split tile: 8 k-word rows * stride 136

template<int NSPLIT, int NPASS>
__global__ void __launch_bounds__(256, 2)
bf_gemm(const float* __restrict__ A, const float* __restrict__ Bm,
        float* __restrict__ C,
        const float* __restrict__ rowscale, const float* __restrict__ bias)
{
    extern __shared__ float sm[];
    unsigned* smu = (unsigned*)sm;
    const int tid  = threadIdx.x;
    const int warp = tid >> 5, lane = tid & 31;
    const int wm = warp >> 2, wn = warp & 3;       // 2 x 4 warp grid
    const int gid = lane >> 2, tig = lane & 3;
    const int m0 = blockIdx.y * 128, n0 = blockIdx.x * 128;

    constexpr int BUF = 2 * NSPLIT * BTSZ;
    constexpr int PA[6] = {0, 0, 1, 0, 2, 1};
    constexpr int PB[6] = {0, 1, 0, 2, 0, 1};

    const int am  = tid >> 2;
    const int akq = (tid & 3) << 2;
    const int bk2 = tid >> 5;
    const int bnq = (tid & 31) << 2;

    float cacc[16][4];
    #pragma unroll
    for (int i = 0; i < 16; i++)
        #pragma unroll
        for (int j = 0; j < 4; j++) cacc[i][j] = 0.f;

    float4 aR0, aR1, bR0, bR1;
    aR0 = *(const float4*)(A + (size_t)(m0 + am)      * 1024 + akq);
    aR1 = *(const float4*)(A + (size_t)(m0 + am + 64) * 1024 + akq);
    bR0 = *(const float4*)(Bm + (size_t)(2 * bk2)     * 1024 + n0 + bnq);
    bR1 = *(const float4*)(Bm + (size_t)(2 * bk2 + 1) * 1024 + n0 + bnq);

    for (int i = 0; i < 64; i++) {
        const int buf = i & 1;
        unsigned* dst = smu + buf * BUF;

        {
            float av[8] = {aR0.x, aR0.y, aR0.z, aR0.w, aR1.x, aR1.y, aR1.z, aR1.w};
            #pragma unroll
            for (int half = 0; half < 2; half++) {
                unsigned short hs[NSPLIT][4];
                #pragma unroll
                for (int e = 0; e < 4; e++) {
                    float rem = av[half * 4 + e];
                    #pragma unroll
                    for (int s = 0; s < NSPLIT; s++) {
                        __nv_bfloat16 b = __float2bfloat16_rn(rem);
                        hs[s][e] = __bfloat16_as_ushort(b);
                        rem -= __bfloat162float(b);
                    }
                }
                #pragma unroll
                for (int w = 0; w < 2; w++)
                    #pragma unroll
                    for (int s = 0; s < NSPLIT; s++)
                        dst[s * BTSZ + ((akq >> 1) + w) * 136 + am + half * 64] =
                            (unsigned)hs[s][2 * w] | ((unsigned)hs[s][2 * w + 1] << 16);
            }
        }
        {
            float b0v[4] = {bR0.x, bR0.y, bR0.z, bR0.w};
            float b1v[4] = {bR1.x, bR1.y, bR1.z, bR1.w};
            unsigned short cs[NSPLIT][4], ds[NSPLIT][4];
            #pragma unroll
            for (int e = 0; e < 4; e++) {
                float rem = b0v[e];
                #pragma unroll
                for (int s = 0; s < NSPLIT; s++) {
                    __nv_bfloat16 b = __float2bfloat16_rn(rem);
                    cs[s][e] = __bfloat16_as_ushort(b);
                    rem -= __bfloat162float(b);
                }
                rem = b1v[e];
                #pragma unroll
                for (int s = 0; s < NSPLIT; s++) {
                    __nv_bfloat16 b = __float2bfloat16_rn(rem);
                    ds[s][e] = __bfloat16_as_ushort(b);
                    rem -= __bfloat162float(b);
                }
            }
            #pragma unroll
            for (int s = 0; s < NSPLIT; s++) {
                uint4 wv;
                wv.x = (unsigned)cs[s][0] | ((unsigned)ds[s][0] << 16);
                wv.y = (unsigned)cs[s][1] | ((unsigned)ds[s][1] << 16);
                wv.z = (unsigned)cs[s][2] | ((unsigned)ds[s][2] << 16);
                wv.w = (unsigned)cs[s][3] | ((unsigned)ds[s][3] << 16);
                *(uint4*)&dst[(NSPLIT + s) * BTSZ + bk2 * 136 + bnq] = wv;
            }
        }
        __syncthreads();

        if (i < 63) {
            const int k0 = (i + 1) * 16;
            aR0 = *(const float4*)(A + (size_t)(m0 + am)      * 1024 + k0 + akq);
            aR1 = *(const float4*)(A + (size_t)(m0 + am + 64) * 1024 + k0 + akq);
            bR0 = *(const float4*)(Bm + (size_t)(k0 + 2 * bk2)     * 1024 + n0 + bnq);
            bR1 = *(const float4*)(Bm + (size_t)(k0 + 2 * bk2 + 1) * 1024 + n0 + bnq);
        }

        #pragma unroll
        for (int p = 0; p < NPASS; p++) {
            const unsigned* As = smu + buf * BUF + PA[p] * BTSZ;
            const unsigned* Bs = smu + buf * BUF + (NSPLIT + PB[p]) * BTSZ;
            unsigned af[4][4];
            #pragma unroll
            for (int mt = 0; mt < 4; mt++) {
                const int mb = wm * 64 + mt * 16 + gid;
                af[mt][0] = As[tig * 136 + mb];
                af[mt][1] = As[tig * 136 + mb + 8];
                af[mt][2] = As[(tig + 4) * 136 + mb];
                af[mt][3] = As[(tig + 4) * 136 + mb + 8];
            }
            unsigned bfr[4][2];
            #pragma unroll
            for (int nt = 0; nt < 4; nt++) {
                const int nb = wn * 32 + nt * 8 + gid;
                bfr[nt][0] = Bs[tig * 136 + nb];
                bfr[nt][1] = Bs[(tig + 4) * 136 + nb];
            }
            #pragma unroll
            for (int mt = 0; mt < 4; mt++)
                #pragma unroll
                for (int nt = 0; nt < 4; nt++)
                    mma_bf16(cacc[mt * 4 + nt], af[mt], bfr[nt]);
        }
        __syncthreads();
    }

    float* st = sm;
    #pragma unroll
    for (int mt = 0; mt < 4; mt++) {
        #pragma unroll
        for (int nt = 0; nt < 4; nt++) {
            const float* c = cacc[mt * 4 + nt];
            const int r  = wm * 64 + mt * 16 + gid;
            const int cc = wn * 32 + nt * 8 + (tig << 1);
            st[r * 129 + cc]           = c[0];
            st[r * 129 + cc + 1]       = c[1];
            st[(r + 8) * 129 + cc]     = c[2];
            st[(r + 8) * 129 + cc + 1] = c[3];
        }
    }
    __syncthreads();
    #pragma unroll 4
    for (int it = 0; it < 64; it++) {
        const int flat = tid + it * 256;
        const int rr = flat >> 7, cc = flat & 127;
        float v = st[rr * 129 + cc];
        if (rowscale) v *= rowscale[m0 + rr];
        if (bias)     v += bias[n0 + cc];
        C[(size_t)(m0 + rr) * 1024 + n0 + cc] = v;
    }
}

// ---------------- zero bucket accumulators (must re-zero every replay) -----
__global__ void zero_buckets(float* __restrict__ bK, float* __restrict__ bV,
                             float* __restrict__ bA)
{
    int n = BHn * Sn * DIMh;
    for (int i = blockIdx.x * blockDim.x + threadIdx.x; i < n;
         i += gridDim.x * blockDim.x) { bK[i] = 0.f; bV[i] = 0.f; }
    int na = BHn * Sn;
    for (int i = blockIdx.x * blockDim.x + threadIdx.x; i < na;
         i += gridDim.x * blockDim.x) bA[i] = 0.f;
}

// ================= routing + bucket accumulation via MMA ====================
// Block = (bh, chunk of 1024 tokens). Phase A: per-token routing -> compact
// (idx, w-split) lists in smem. Phase B: per 64-token tile, scatter assign^T
// into a bf16x2 smem tile and run m16n8k16 MMAs against token-pair-major
// K/V tiles (bf16x2, 3 passes). Register accum, one global-atomic flush.
#define RT_CHUNK   1024
#define RT_NCHUNK  (Tsz / RT_CHUNK)   // 4
#define RT_NTILE   (RT_CHUNK / 64)    // 16

// smem word offsets
#define OFF_SW    0                    // 1024*16 packed bf16x2 weights
#define OFF_SIDX  16384                // 1024*16 bytes (4096 words)
#define OFF_SA    20480                // 128
#define OFF_SPL   20608                // 64*32
#define OFF_SPR   22656                // 64
#define OFF_ASG0  22720                // 32*136
#define OFF_ASG1  27072                // 32*136
#define OFF_KT0   31424                // 32*72
#define OFF_KT1   33728
#define OFF_VT0   36032
#define OFF_VT1   38336
#define RT2_WORDS 40640
#define RT2_SMEM  (RT2_WORDS * 4)

__global__ void __launch_bounds__(256, 1)
route2_kernel(const float* __restrict__ K, const float* __restrict__ V,
              const float* __restrict__ planes_T,
              const float* __restrict__ protos_T,
              const float* __restrict__ ltemp,
              float* __restrict__ bK, float* __restrict__ bV,
              float* __restrict__ bA)
{
    extern __shared__ float smf[];
    unsigned* smw = (unsigned*)smf;
    unsigned char* sidxb = (unsigned char*)(smw + OFF_SIDX);
    unsigned* sw = smw + OFF_SW;
    float* sA  = smf + OFF_SA;
    float* spl = smf + OFF_SPL;
    float* spr = smf + OFF_SPR;

    const int tid   = threadIdx.x;
    const int warp  = tid >> 5, lane = tid & 31;
    const int gid   = lane >> 2, tig = lane & 3;
    const int bh    = blockIdx.x >> 2;
    const int chunk = blockIdx.x & 3;
    const int b = bh >> 4, h = bh & 15;

    for (int i = tid; i < Sn; i += 256) sA[i] = 0.f;
    for (int i = tid; i < DIMh * 32; i += 256) spl[i] = planes_T[i];
    for (int i = tid; i < KBn * Rn; i += 256) spr[i] = protos_T[i];
    __syncthreads();

    float scale = expf(ltemp[0]);
    scale = fminf(fmaxf(scale, 0.01f), 20.0f);
    const float inv_scale = 1.0f / scale;

    // ---------- Phase A: routing for 1024 tokens ----------
    for (int tt = 0; tt < 4; tt++) {
        const int tl = tt * 256 + tid;                 // 0..1023
        const int t  = chunk * RT_CHUNK + tl;
        const float* krow = K + ((size_t)(b * Tsz + t)) * Dsz + h * DIMh;

        float proj[32];
        #pragma unroll
        for (int p = 0; p < 32; p++) proj[p] = 0.f;
        #pragma unroll 4
        for (int d = 0; d < DIMh; d++) {
            float kd = krow[d];
            #pragma unroll
            for (int p = 0; p < 32; p++) proj[p] += kd * spl[d * 32 + p];
        }
        #pragma unroll
        for (int p = 0; p < 32; p++) proj[p] = tanhf(proj[p]) * inv_scale;

        #pragma unroll
        for (int l = 0; l < Ln; l++) {
            float e[16];
            float mx = -1e30f;
            #pragma unroll
            for (int r = 0; r < Rn; r++) {
                float lg = proj[l*4+0] * spr[0*Rn + r] + proj[l*4+1] * spr[1*Rn + r]
                         + proj[l*4+2] * spr[2*Rn + r] + proj[l*4+3] * spr[3*Rn + r];
                e[r] = lg;
                mx = fmaxf(mx, lg);
            }
            float Z = 0.f;
            #pragma unroll
            for (int r = 0; r < Rn; r++) { e[r] = expf(e[r] - mx); Z += e[r]; }
            int i1 = 0; float b1 = e[0];
            #pragma unroll
            for (int r = 1; r < Rn; r++) if (e[r] > b1) { b1 = e[r]; i1 = r; }
            int i2 = -1; float b2 = -1.f;
            #pragma unroll
            for (int r = 0; r < Rn; r++) if (r != i1 && e[r] > b2) { b2 = e[r]; i2 = r; }
            const float denom = 1.0f / (b1 + b2 + 1e-6f * Z);
            const float w1f = b1 * denom, w2f = b2 * denom;

            __nv_bfloat16 w10 = __float2bfloat16_rn(w1f);
            __nv_bfloat16 w11 = __float2bfloat16_rn(w1f - __bfloat162float(w10));
            __nv_bfloat16 w20 = __float2bfloat16_rn(w2f);
            __nv_bfloat16 w21 = __float2bfloat16_rn(w2f - __bfloat162float(w20));

            const int s1 = l * Rn + i1, s2 = l * Rn + i2;
            sidxb[tl * 16 + l * 2]     = (unsigned char)s1;
            sidxb[tl * 16 + l * 2 + 1] = (unsigned char)s2;
            sw[tl * 16 + l * 2] =
                (unsigned)__bfloat16_as_ushort(w10) |
                ((unsigned)__bfloat16_as_ushort(w11) << 16);
            sw[tl * 16 + l * 2 + 1] =
                (unsigned)__bfloat16_as_ushort(w20) |
                ((unsigned)__bfloat16_as_ushort(w21) << 16);
            atomicAdd(&sA[s1], w1f);
            atomicAdd(&sA[s2], w2f);
        }
    }
    __syncthreads();
    if (tid < Sn) atomicAdd(&bA[(size_t)bh * Sn + tid], sA[tid]);

    // ---------- Phase B: MMA bucketing ----------
    float acc[16][4];          // nt 0..7 = bucket_K dims, 8..15 = bucket_V dims
    #pragma unroll
    for (int i = 0; i < 16; i++)
        #pragma unroll
        for (int j = 0; j < 4; j++) acc[i][j] = 0.f;

    const int tok  = tid >> 2;              // 0..63 within tile
    const int dqq  = (tid & 3) * 16;        // d base for K/V loads
    const int tp_w = tok >> 1, half_w = tok & 1;

    for (int tile = 0; tile < RT_NTILE; tile++) {
        __syncthreads();   // prev MMA done before overwriting smem tiles

        // zero assign tiles (32*136 words each)
        {
            uint4 z = make_uint4(0u, 0u, 0u, 0u);
            uint4* a0 = (uint4*)(smw + OFF_ASG0);
            uint4* a1 = (uint4*)(smw + OFF_ASG1);
            for (int i = tid; i < 1088; i += 256) { a0[i] = z; a1[i] = z; }
        }
        __syncthreads();

        // scatter assign^T (token-pair-major words, stride 136)
        {
            unsigned short* a0h = (unsigned short*)(smw + OFF_ASG0);
            unsigned short* a1h = (unsigned short*)(smw + OFF_ASG1);
            #pragma unroll
            for (int it = 0; it < 4; it++) {
                const int e  = tid + it * 256;       // 0..1023
                const int tl = tile * 64 + (e >> 4);
                const int j  = e & 15;
                const int s  = sidxb[tl * 16 + j];
                const unsigned wp = sw[tl * 16 + j];
                const int tt2 = e >> 4;              // token within tile
                const int widx = ((tt2 >> 1) * 136 + s) * 2 + (tt2 & 1);
                a0h[widx] = (unsigned short)(wp & 0xffffu);
                a1h[widx] = (unsigned short)(wp >> 16);
            }
        }

        // load K/V tile, token-pair-major bf16x2 splits (stride 72 words)
        {
            const int tglob = chunk * RT_CHUNK + tile * 64 + tok;
            const float* kr = K + ((size_t)(b * Tsz + tglob)) * Dsz + h * DIMh;
            const float* vr = V + ((size_t)(b * Tsz + tglob)) * Dsz + h * DIMh;
            unsigned short* k0h = (unsigned short*)(smw + OFF_KT0);
            unsigned short* k1h = (unsigned short*)(smw + OFF_KT1);
            unsigned short* v0h = (unsigned short*)(smw + OFF_VT0);
            unsigned short* v1h = (unsigned short*)(smw + OFF_VT1);
            #pragma unroll
            for (int i4 = 0; i4 < 4; i4++) {
                float4 kv = *(const float4*)(kr + dqq + i4 * 4);
                float4 vv = *(const float4*)(vr + dqq + i4 * 4);
                float kf[4] = {kv.x, kv.y, kv.z, kv.w};
                float vf[4] = {vv.x, vv.y, vv.z, vv.w};
                #pragma unroll
                for (int e = 0; e < 4; e++) {
                    const int d = dqq + i4 * 4 + e;
                    const int widx = (tp_w * 72 + d) * 2 + half_w;
                    __nv_bfloat16 k0 = __float2bfloat16_rn(kf[e]);
                    __nv_bfloat16 k1 = __float2bfloat16_rn(kf[e] - __bfloat162float(k0));
                    __nv_bfloat16 v0 = __float2bfloat16_rn(vf[e]);
                    __nv_bfloat16 v1 = __float2bfloat16_rn(vf[e] - __bfloat162float(v0));
                    k0h[widx] = __bfloat16_as_ushort(k0);
                    k1h[widx] = __bfloat16_as_ushort(k1);
                    v0h[widx] = __bfloat16_as_ushort(v0);
                    v1h[widx] = __bfloat16_as_ushort(v1);
                }
            }
        }
        __syncthreads();

        // MMA: 4 k16-steps over 64 tokens
        const unsigned* asg0 = smw + OFF_ASG0;
        const unsigned* asg1 = smw + OFF_ASG1;
        const unsigned* kt0  = smw + OFF_KT0;
        const unsigned* kt1  = smw + OFF_KT1;
        const unsigned* vt0  = smw + OFF_VT0;
        const unsigned* vt1  = smw + OFF_VT1;
        #pragma unroll
        for (int ks = 0; ks < 4; ks++) {
            const int r0 = ks * 8 + tig, r1 = ks * 8 + tig + 4;
            const int mb = warp * 16 + gid;
            unsigned a0f[4], a1f[4];
            a0f[0] = asg0[r0 * 136 + mb]; a0f[1] = asg0[r0 * 136 + mb + 8];
            a0f[2] = asg0[r1 * 136 + mb]; a0f[3] = asg0[r1 * 136 + mb + 8];
            a1f[0] = asg1[r0 * 136 + mb]; a1f[1] = asg1[r0 * 136 + mb + 8];
            a1f[2] = asg1[r1 * 136 + mb]; a1f[3] = asg1[r1 * 136 + mb + 8];
            #pragma unroll
            for (int nt = 0; nt < 8; nt++) {
                const int nb = nt * 8 + gid;
                unsigned bk0[2], bk1[2], bv0[2], bv1[2];
                bk0[0] = kt0[r0 * 72 + nb]; bk0[1] = kt0[r1 * 72 + nb];
                bk1[0] = kt1[r0 * 72 + nb]; bk1[1] = kt1[r1 * 72 + nb];
                bv0[0] = vt0[r0 * 72 + nb]; bv0[1] = vt0[r1 * 72 + nb];
                bv1[0] = vt1[r0 * 72 + nb]; bv1[1] = vt1[r1 * 72 + nb];
                mma_bf16(acc[nt], a0f, bk0);
                mma_bf16(acc[nt], a0f, bk1);
                mma_bf16(acc[nt], a1f, bk0);
                mma_bf16(acc[8 + nt], a0f, bv0);
                mma_bf16(acc[8 + nt], a0f, bv1);
                mma_bf16(acc[8 + nt], a1f, bv0);
            }
        }
    }

    // flush accumulators
    {
        const size_t base = (size_t)bh * Sn * DIMh;
        const int s0 = warp * 16 + gid, s1 = s0 + 8;
        #pragma unroll
        for (int nt = 0; nt < 8; nt++) {
            const int d = nt * 8 + tig * 2;
            atomicAdd(&bK[base + s0 * 64 + d],     acc[nt][0]);
            atomicAdd(&bK[base + s0 * 64 + d + 1], acc[nt][1]);
            atomicAdd(&bK[base + s1 * 64 + d],     acc[nt][2]);
            atomicAdd(&bK[base + s1 * 64 + d + 1], acc[nt][3]);
            atomicAdd(&bV[base + s0 * 64 + d],     acc[8 + nt][0]);
            atomicAdd(&bV[base + s0 * 64 + d + 1], acc[8 + nt][1]);
            atomicAdd(&bV[base + s1 * 64 + d],     acc[8 + nt][2]);
            atomicAdd(&bV[base + s1 * 64 + d + 1], acc[8 + nt][3]);
        }
    }
}

// ---------------- bucket attention (warp per token) ------------------------
#define AT_TPC    512
#define AT_CHUNKS (Tsz / AT_TPC)    // 8
#define AT_SMEM   ((2*Sn*65 + 8*Sn) * sizeof(float))

__global__ void __launch_bounds__(256)
attn_kernel(const float* __restrict__ Q,
            const float* __restrict__ bK, const float* __restrict__ bV,
            const float* __restrict__ bA, float* __restrict__ outp)
{
    extern __shared__ float sm[];
    float* sK = sm;
    float* sV = sK + Sn * 65;
    float* sp = sV + Sn * 65;

    const int tid   = threadIdx.x;
    const int bh    = blockIdx.x / AT_CHUNKS;
    const int chunk = blockIdx.x % AT_CHUNKS;
    const int b = bh / Hn, h = bh % Hn;

    const size_t base = (size_t)bh * Sn * DIMh;
    for (int i = tid; i < Sn * DIMh; i += blockDim.x) {
        int s = i / DIMh, d = i % DIMh;
        float inv = 1.0f / (bA[(size_t)bh * Sn + s] + 1e-6f);
        sK[s * 65 + d] = bK[base + i] * inv;
        sV[s * 65 + d] = bV[base + i] * inv;
    }
    __syncthreads();

    const int warp = tid >> 5, lane = tid & 31;
    float* pwarp = sp + warp * Sn;

    for (int tt = warp; tt < AT_TPC; tt += 8) {
        const int t = chunk * AT_TPC + tt;
        const float* qrow = Q + ((size_t)(b * Tsz + t)) * Dsz + h * DIMh;
        float q0 = qrow[lane], q1 = qrow[lane + 32];

        float a0 = 0.f, a1 = 0.f, a2 = 0.f, a3 = 0.f;
        #pragma unroll
        for (int d = 0; d < 32; d++) {
            float qd = __shfl_sync(0xffffffffu, q0, d);
            a0 += qd * sK[(lane      ) * 65 + d];
            a1 += qd * sK[(lane + 32 ) * 65 + d];
            a2 += qd * sK[(lane + 64 ) * 65 + d];
            a3 += qd * sK[(lane + 96 ) * 65 + d];
        }
        #pragma unroll
        for (int d = 0; d < 32; d++) {
            float qd = __shfl_sync(0xffffffffu, q1, d);
            a0 += qd * sK[(lane      ) * 65 + 32 + d];
            a1 += qd * sK[(lane + 32 ) * 65 + 32 + d];
            a2 += qd * sK[(lane + 64 ) * 65 + 32 + d];
            a3 += qd * sK[(lane + 96 ) * 65 + 32 + d];
        }
        const float sc = 0.125f;
        a0 *= sc; a1 *= sc; a2 *= sc; a3 *= sc;

        float lm = fmaxf(fmaxf(a0, a1), fmaxf(a2, a3));
        #pragma unroll
        for (int o = 16; o; o >>= 1) lm = fmaxf(lm, __shfl_xor_sync(0xffffffffu, lm, o));
        float e0 = expf(a0 - lm), e1 = expf(a1 - lm), e2 = expf(a2 - lm), e3 = expf(a3 - lm);
        float z = e0 + e1 + e2 + e3;
        #pragma unroll
        for (int o = 16; o; o >>= 1) z += __shfl_xor_sync(0xffffffffu, z, o);
        float invz = 1.0f / z;

        pwarp[lane]      = e0 * invz;
        pwarp[lane + 32] = e1 * invz;
        pwarp[lane + 64] = e2 * invz;
        pwarp[lane + 96] = e3 * invz;
        __syncwarp();

        float o0 = 0.f, o1 = 0.f;
        #pragma unroll 8
        for (int s = 0; s < Sn; s++) {
            float p = pwarp[s];
            o0 += p * sV[s * 65 + lane];
            o1 += p * sV[s * 65 + lane + 32];
        }
        size_t obase = ((size_t)(b * Tsz + t)) * Dsz + h * DIMh;
        outp[obase + lane]      = o0;
        outp[obase + lane + 32] = o1;
        __syncwarp();
    }
}

// ---------------- launch ----------------------------------------------------
extern "C" void kernel_launch(void* const* d_in, const int* in_sizes, int n_in,
                              void* d_out, int out_size)
{
    const float* x      = (const float*)d_in[0];
    const float* mask   = (const float*)d_in[1];
    const float* Wq     = (const float*)d_in[2];
    const float* Wk     = (const float*)d_in[3];
    const float* Wv     = (const float*)d_in[4];
    const float* Wout   = (const float*)d_in[5];
    const float* b_out  = (const float*)d_in[6];
    const float* planes = (const float*)d_in[7];
    const float* protos = (const float*)d_in[8];
    const float* ltemp  = (const float*)d_in[9];
    float* out = (float*)d_out;

    void *pQ, *pK, *pV, *pATT, *pbK, *pbV, *pbA;
    cudaGetSymbolAddress(&pQ,  g_Q);
    cudaGetSymbolAddress(&pK,  g_K);
    cudaGetSymbolAddress(&pV,  g_V);
    cudaGetSymbolAddress(&pATT,g_ATT);
    cudaGetSymbolAddress(&pbK, g_bK);
    cudaGetSymbolAddress(&pbV, g_bV);
    cudaGetSymbolAddress(&pbA, g_bA);

    const int GSMEM = 128 * 129 * 4;   // 66048 B
    cudaFuncSetAttribute(bf_gemm<2,3>, cudaFuncAttributeMaxDynamicSharedMemorySize, GSMEM);
    cudaFuncSetAttribute(bf_gemm<3,6>, cudaFuncAttributeMaxDynamicSharedMemorySize, GSMEM);
    cudaFuncSetAttribute(route2_kernel, cudaFuncAttributeMaxDynamicSharedMemorySize, RT2_SMEM);
    cudaFuncSetAttribute(attn_kernel,  cudaFuncAttributeMaxDynamicSharedMemorySize, AT_SMEM);

    dim3 gblk(256);
    dim3 ggrid(Dsz / 128, BT / 128);   // (8, 128)

    zero_buckets<<<256, 256>>>((float*)pbK, (float*)pbV, (float*)pbA);

    // Q/V: bf16x2 3-pass. K: bf16x3 6-pass (routing-critical).
    bf_gemm<2,3><<<ggrid, gblk, GSMEM>>>(x, Wq, (float*)pQ, mask, nullptr);
    bf_gemm<3,6><<<ggrid, gblk, GSMEM>>>(x, Wk, (float*)pK, mask, nullptr);
    bf_gemm<2,3><<<ggrid, gblk, GSMEM>>>(x, Wv, (float*)pV, mask, nullptr);

    // routing + MMA bucketing
    route2_kernel<<<BHn * RT_NCHUNK, 256, RT2_SMEM>>>(
        (const float*)pK, (const float*)pV, planes, protos, ltemp,
        (float*)pbK, (float*)pbV, (float*)pbA);

    attn_kernel<<<BHn * AT_CHUNKS, 256, AT_SMEM>>>(
        (const float*)pQ, (const float*)pbK, (const float*)pbV, (const float*)pbA,
        (float*)pATT);

    bf_gemm<2,3><<<ggrid, gblk, GSMEM>>>((const float*)pATT, Wout, out,
                                         nullptr, b_out);
}

// round 11
// speedup vs baseline: 1.1499x; 1.1499x over previous
#include <cuda_runtime.h>
#include <cuda_bf16.h>
#include <math.h>

// Problem constants
#define Bsz  4
#define Tsz  4096
#define Dsz  1024
#define Hn   16
#define DIMh 64
#define Ln   8
#define KBn  4
#define Rn   16
#define Sn   128
#define BT   (Bsz*Tsz)      // 16384
#define BHn  (Bsz*Hn)       // 64

// ---------------- scratch (device globals: no allocation allowed) ----------
__device__ float g_Q  [(size_t)BT*Dsz];
__device__ float g_K  [(size_t)BT*Dsz];
__device__ float g_V  [(size_t)BT*Dsz];
__device__ float g_ATT[(size_t)BT*Dsz];
__device__ float g_bK [(size_t)BHn*Sn*DIMh];
__device__ float g_bV [(size_t)BHn*Sn*DIMh];
__device__ float g_bA [(size_t)BHn*Sn];

// packed bf16x2 split planes (k-pair-major)
#define APL ((size_t)512*16384)     // activation plane: [kw=512][m=16384]
#define BPL ((size_t)512*1024)      // weight plane:     [kw=512][n=1024]
__device__ unsigned g_xp  [3*APL];  // x splits (3: K GEMM uses all, Q/V use 2)
__device__ unsigned g_attp[2*APL];  // attention-output splits
__device__ unsigned g_wp  [9*BPL];  // Wq(0,1) Wk(2,3,4) Wv(5,6) Wout(7,8)

// ======================= helpers ============================================
__device__ __forceinline__ unsigned smem_u32(const void* p) {
    unsigned a;
    asm("{ .reg .u64 t; cvta.to.shared.u64 t, %1; cvt.u32.u64 %0, t; }"
        : "=r"(a) : "l"(p));
    return a;
}

__device__ __forceinline__ void mma_bf16(float c[4], const unsigned a[4],
                                         const unsigned b[2]) {
    asm volatile(
        "mma.sync.aligned.m16n8k16.row.col.f32.bf16.bf16.f32 "
        "{%0,%1,%2,%3}, {%4,%5,%6,%7}, {%8,%9}, {%0,%1,%2,%3};"
        : "+f"(c[0]), "+f"(c[1]), "+f"(c[2]), "+f"(c[3])
        : "r"(a[0]), "r"(a[1]), "r"(a[2]), "r"(a[3]), "r"(b[0]), "r"(b[1]));
}

__device__ __forceinline__ void cpasync16(unsigned saddr, const void* gptr) {
    asm volatile("cp.async.cg.shared.global [%0], [%1], 16;"
                 :: "r"(saddr), "l"(gptr));
}

// ================= pack kernels (one-shot split conversion) =================
// A-side: X[M,1024] fp32 row-major -> NS planes out[s][kw*16384 + m]
// (transpose-convert through smem; word = bf16x2 of k-pair)
template<int NS>
__global__ void __launch_bounds__(256)
apackT(const float* __restrict__ X, unsigned* __restrict__ out)
{
    __shared__ float tile[32][33];
    const int tid = threadIdx.x;
    const int m0 = blockIdx.x * 32, k0 = blockIdx.y * 32;
    const int rr = tid >> 5, cc = tid & 31;

    #pragma unroll
    for (int j = 0; j < 4; j++)
        tile[rr + j * 8][cc] = X[(size_t)(m0 + rr + j * 8) * 1024 + k0 + cc];
    __syncthreads();

    #pragma unroll
    for (int j = 0; j < 2; j++) {
        const int kwl = rr + j * 8;               // 0..15
        float x0 = tile[cc][2 * kwl];
        float x1 = tile[cc][2 * kwl + 1];
        #pragma unroll
        for (int s = 0; s < NS; s++) {
            __nv_bfloat16 b0 = __float2bfloat16_rn(x0);
            __nv_bfloat16 b1 = __float2bfloat16_rn(x1);
            out[s * APL + (size_t)(k0 / 2 + kwl) * 16384 + m0 + cc] =
                (unsigned)__bfloat16_as_ushort(b0) |
                ((unsigned)__bfloat16_as_ushort(b1) << 16);
            x0 -= __bfloat162float(b0);
            x1 -= __bfloat162float(b1);
        }
    }
}

// B-side: W[1024,1024] fp32 -> NS planes out[s][kw*1024 + n]
template<int NS>
__global__ void __launch_bounds__(256)
bpack(const float* __restrict__ W, unsigned* __restrict__ out)
{
    const int idx = blockIdx.x * 256 + threadIdx.x;   // 0 .. 512*1024-1
    const int kw = idx >> 10, n = idx & 1023;
    float x0 = W[(size_t)(2 * kw) * 1024 + n];
    float x1 = W[(size_t)(2 * kw + 1) * 1024 + n];
    #pragma unroll
    for (int s = 0; s < NS; s++) {
        __nv_bfloat16 b0 = __float2bfloat16_rn(x0);
        __nv_bfloat16 b1 = __float2bfloat16_rn(x1);
        out[s * BPL + idx] =
            (unsigned)__bfloat16_as_ushort(b0) |
            ((unsigned)__bfloat16_as_ushort(b1) << 16);
        x0 -= __bfloat162float(b0);
        x1 -= __bfloat162float(b1);
    }
}

// ================= packed-input bf16 split GEMM =============================
// C[16384,1024] = sum over passes Ap[PA[p]] @ Bp[PB[p]]  (*rowscale)(+bias)
#define BTSZ 1088       // words per split tile: 8 kw rows * stride 136

template<int NSPLIT, int NPASS>
__global__ void __launch_bounds__(256, 2)
pk_gemm(const unsigned* __restrict__ Ap, const unsigned* __restrict__ Bp,
        float* __restrict__ C,
        const float* __restrict__ rowscale, const float* __restrict__ bias)
{
    extern __shared__ float sm[];
    unsigned* smu = (unsigned*)sm;
    const unsigned sbase = smem_u32(smu);
    const int tid  = threadIdx.x;
    const int warp = tid >> 5, lane = tid & 31;
    const int wm = warp >> 2, wn = warp & 3;       // 2 x 4 warp grid
    const int gid = lane >> 2, tig = lane & 3;
    const int m0 = blockIdx.y * 128, n0 = blockIdx.x * 128;

    constexpr int BUF = 2 * NSPLIT * BTSZ;         // words per buffer
    constexpr int PA[6] = {0, 0, 1, 0, 2, 1};
    constexpr int PB[6] = {0, 1, 0, 2, 0, 1};

    const int row = tid >> 5;            // 0..7 (kw row within chunk)
    const int c4  = (lane) * 4;          // word col (0..124)

    float cacc[16][4];
    #pragma unroll
    for (int i = 0; i < 16; i++)
        #pragma unroll
        for (int j = 0; j < 4; j++) cacc[i][j] = 0.f;

    // per-thread cp.async addresses
    unsigned sA[NSPLIT], sB[NSPLIT];
    #pragma unroll
    for (int s = 0; s < NSPLIT; s++) {
        sA[s] = sbase + (unsigned)(s * BTSZ + row * 136 + c4) * 4;
        sB[s] = sbase + (unsigned)((NSPLIT + s) * BTSZ + row * 136 + c4) * 4;
    }

    auto issue = [&](int i, int buf) {
        const unsigned boff = (unsigned)(buf * BUF) * 4;
        #pragma unroll
        for (int s = 0; s < NSPLIT; s++) {
            cpasync16(sA[s] + boff,
                      Ap + s * APL + (size_t)(i * 8 + row) * 16384 + m0 + c4);
            cpasync16(sB[s] + boff,
                      Bp + s * BPL + (size_t)(i * 8 + row) * 1024 + n0 + c4);
        }
        asm volatile("cp.async.commit_group;");
    };

    issue(0, 0);

    for (int i = 0; i < 64; i++) {
        const int buf = i & 1;
        if (i < 63) {
            issue(i + 1, buf ^ 1);
            asm volatile("cp.async.wait_group 1;");
        } else {
            asm volatile("cp.async.wait_group 0;");
        }
        __syncthreads();

        #pragma unroll
        for (int p = 0; p < NPASS; p++) {
            const unsigned* As = smu + buf * BUF + PA[p] * BTSZ;
            const unsigned* Bs = smu + buf * BUF + (NSPLIT + PB[p]) * BTSZ;
            unsigned af[4][4];
            #pragma unroll
            for (int mt = 0; mt < 4; mt++) {
                const int mb = wm * 64 + mt * 16 + gid;
                af[mt][0] = As[tig * 136 + mb];
                af[mt][1] = As[tig * 136 + mb + 8];
                af[mt][2] = As[(tig + 4) * 136 + mb];
                af[mt][3] = As[(tig + 4) * 136 + mb + 8];
            }
            unsigned bfr[4][2];
            #pragma unroll
            for (int nt = 0; nt < 4; nt++) {
                const int nb = wn * 32 + nt * 8 + gid;
                bfr[nt][0] = Bs[tig * 136 + nb];
                bfr[nt][1] = Bs[(tig + 4) * 136 + nb];
            }
            #pragma unroll
            for (int mt = 0; mt < 4; mt++)
                #pragma unroll
                for (int nt = 0; nt < 4; nt++)
                    mma_bf16(cacc[mt * 4 + nt], af[mt], bfr[nt]);
        }
        __syncthreads();   // MMA done before buf is overwritten by next issue
    }

    // ---- epilogue: stage C to smem, then coalesced writeout ----
    float* st = sm;
    #pragma unroll
    for (int mt = 0; mt < 4; mt++) {
        #pragma unroll
        for (int nt = 0; nt < 4; nt++) {
            const float* c = cacc[mt * 4 + nt];
            const int r  = wm * 64 + mt * 16 + gid;
            const int cc = wn * 32 + nt * 8 + (tig << 1);
            st[r * 129 + cc]           = c[0];
            st[r * 129 + cc + 1]       = c[1];
            st[(r + 8) * 129 + cc]     = c[2];
            st[(r + 8) * 129 + cc + 1] = c[3];
        }
    }
    __syncthreads();
    #pragma unroll 4
    for (int it = 0; it < 64; it++) {
        const int flat = tid + it * 256;
        const int rr = flat >> 7, cc = flat & 127;
        float v = st[rr * 129 + cc];
        if (rowscale) v *= rowscale[m0 + rr];
        if (bias)     v += bias[n0 + cc];
        C[(size_t)(m0 + rr) * 1024 + n0 + cc] = v;
    }
}

// ---------------- zero bucket accumulators (must re-zero every replay) -----
__global__ void zero_buckets(float* __restrict__ bK, float* __restrict__ bV,
                             float* __restrict__ bA)
{
    int n = BHn * Sn * DIMh;
    for (int i = blockIdx.x * blockDim.x + threadIdx.x; i < n;
         i += gridDim.x * blockDim.x) { bK[i] = 0.f; bV[i] = 0.f; }
    int na = BHn * Sn;
    for (int i = blockIdx.x * blockDim.x + threadIdx.x; i < na;
         i += gridDim.x * blockDim.x) bA[i] = 0.f;
}

// ================= routing + bucket accumulation via MMA ====================
#define RT_CHUNK   1024
#define RT_NCHUNK  (Tsz / RT_CHUNK)   // 4
#define RT_NTILE   (RT_CHUNK / 64)    // 16

#define OFF_SW    0
#define OFF_SIDX  16384
#define OFF_SA    20480
#define OFF_SPL   20608
#define OFF_SPR   22656
#define OFF_ASG0  22720
#define OFF_ASG1  27072
#define OFF_KT0   31424
#define OFF_KT1   33728
#define OFF_VT0   36032
#define OFF_VT1   38336
#define RT2_WORDS 40640
#define RT2_SMEM  (RT2_WORDS * 4)

__global__ void __launch_bounds__(256, 1)
route2_kernel(const float* __restrict__ K, const float* __restrict__ V,
              const float* __restrict__ planes_T,
              const float* __restrict__ protos_T,
              const float* __restrict__ ltemp,
              float* __restrict__ bK, float* __restrict__ bV,
              float* __restrict__ bA)
{
    extern __shared__ float smf[];
    unsigned* smw = (unsigned*)smf;
    unsigned char* sidxb = (unsigned char*)(smw + OFF_SIDX);
    unsigned* sw = smw + OFF_SW;
    float* sA  = smf + OFF_SA;
    float* spl = smf + OFF_SPL;
    float* spr = smf + OFF_SPR;

    const int tid   = threadIdx.x;
    const int warp  = tid >> 5, lane = tid & 31;
    const int gid   = lane >> 2, tig = lane & 3;
    const int bh    = blockIdx.x >> 2;
    const int chunk = blockIdx.x & 3;
    const int b = bh >> 4, h = bh & 15;

    for (int i = tid; i < Sn; i += 256) sA[i] = 0.f;
    for (int i = tid; i < DIMh * 32; i += 256) spl[i] = planes_T[i];
    for (int i = tid; i < KBn * Rn; i += 256) spr[i] = protos_T[i];
    __syncthreads();

    float scale = expf(ltemp[0]);
    scale = fminf(fmaxf(scale, 0.01f), 20.0f);
    const float inv_scale = 1.0f / scale;

    // ---------- Phase A: routing ----------
    for (int tt = 0; tt < 4; tt++) {
        const int tl = tt * 256 + tid;
        const int t  = chunk * RT_CHUNK + tl;
        const float* krow = K + ((size_t)(b * Tsz + t)) * Dsz + h * DIMh;

        float proj[32];
        #pragma unroll
        for (int p = 0; p < 32; p++) proj[p] = 0.f;
        #pragma unroll 4
        for (int d = 0; d < DIMh; d++) {
            float kd = krow[d];
            #pragma unroll
            for (int p = 0; p < 32; p++) proj[p] += kd * spl[d * 32 + p];
        }
        #pragma unroll
        for (int p = 0; p < 32; p++) proj[p] = tanhf(proj[p]) * inv_scale;

        #pragma unroll
        for (int l = 0; l < Ln; l++) {
            float e[16];
            float mx = -1e30f;
            #pragma unroll
            for (int r = 0; r < Rn; r++) {
                float lg = proj[l*4+0] * spr[0*Rn + r] + proj[l*4+1] * spr[1*Rn + r]
                         + proj[l*4+2] * spr[2*Rn + r] + proj[l*4+3] * spr[3*Rn + r];
                e[r] = lg;
                mx = fmaxf(mx, lg);
            }
            float Z = 0.f;
            #pragma unroll
            for (int r = 0; r < Rn; r++) { e[r] = expf(e[r] - mx); Z += e[r]; }
            int i1 = 0; float b1 = e[0];
            #pragma unroll
            for (int r = 1; r < Rn; r++) if (e[r] > b1) { b1 = e[r]; i1 = r; }
            int i2 = -1; float b2 = -1.f;
            #pragma unroll
            for (int r = 0; r < Rn; r++) if (r != i1 && e[r] > b2) { b2 = e[r]; i2 = r; }
            const float denom = 1.0f / (b1 + b2 + 1e-6f * Z);
            const float w1f = b1 * denom, w2f = b2 * denom;

            __nv_bfloat16 w10 = __float2bfloat16_rn(w1f);
            __nv_bfloat16 w11 = __float2bfloat16_rn(w1f - __bfloat162float(w10));
            __nv_bfloat16 w20 = __float2bfloat16_rn(w2f);
            __nv_bfloat16 w21 = __float2bfloat16_rn(w2f - __bfloat162float(w20));

            const int s1 = l * Rn + i1, s2 = l * Rn + i2;
            sidxb[tl * 16 + l * 2]     = (unsigned char)s1;
            sidxb[tl * 16 + l * 2 + 1] = (unsigned char)s2;
            sw[tl * 16 + l * 2] =
                (unsigned)__bfloat16_as_ushort(w10) |
                ((unsigned)__bfloat16_as_ushort(w11) << 16);
            sw[tl * 16 + l * 2 + 1] =
                (unsigned)__bfloat16_as_ushort(w20) |
                ((unsigned)__bfloat16_as_ushort(w21) << 16);
            atomicAdd(&sA[s1], w1f);
            atomicAdd(&sA[s2], w2f);
        }
    }
    __syncthreads();
    if (tid < Sn) atomicAdd(&bA[(size_t)bh * Sn + tid], sA[tid]);

    // ---------- Phase B: MMA bucketing ----------
    float acc[16][4];
    #pragma unroll
    for (int i = 0; i < 16; i++)
        #pragma unroll
        for (int j = 0; j < 4; j++) acc[i][j] = 0.f;

    const int tok  = tid >> 2;
    const int dqq  = (tid & 3) * 16;
    const int tp_w = tok >> 1, half_w = tok & 1;

    for (int tile = 0; tile < RT_NTILE; tile++) {
        __syncthreads();
        {
            uint4 z = make_uint4(0u, 0u, 0u, 0u);
            uint4* a0 = (uint4*)(smw + OFF_ASG0);
            uint4* a1 = (uint4*)(smw + OFF_ASG1);
            for (int i = tid; i < 1088; i += 256) { a0[i] = z; a1[i] = z; }
        }
        __syncthreads();

        {
            unsigned short* a0h = (unsigned short*)(smw + OFF_ASG0);
            unsigned short* a1h = (unsigned short*)(smw + OFF_ASG1);
            #pragma unroll
            for (int it = 0; it < 4; it++) {
                const int e  = tid + it * 256;
                const int tl = tile * 64 + (e >> 4);
                const int j  = e & 15;
                const int s  = sidxb[tl * 16 + j];
                const unsigned wp = sw[tl * 16 + j];
                const int tt2 = e >> 4;
                const int widx = ((tt2 >> 1) * 136 + s) * 2 + (tt2 & 1);
                a0h[widx] = (unsigned short)(wp & 0xffffu);
                a1h[widx] = (unsigned short)(wp >> 16);
            }
        }

        {
            const int tglob = chunk * RT_CHUNK + tile * 64 + tok;
            const float* kr = K + ((size_t)(b * Tsz + tglob)) * Dsz + h * DIMh;
            const float* vr = V + ((size_t)(b * Tsz + tglob)) * Dsz + h * DIMh;
            unsigned short* k0h = (unsigned short*)(smw + OFF_KT0);
            unsigned short* k1h = (unsigned short*)(smw + OFF_KT1);
            unsigned short* v0h = (unsigned short*)(smw + OFF_VT0);
            unsigned short* v1h = (unsigned short*)(smw + OFF_VT1);
            #pragma unroll
            for (int i4 = 0; i4 < 4; i4++) {
                float4 kv = *(const float4*)(kr + dqq + i4 * 4);
                float4 vv = *(const float4*)(vr + dqq + i4 * 4);
                float kf[4] = {kv.x, kv.y, kv.z, kv.w};
                float vf[4] = {vv.x, vv.y, vv.z, vv.w};
                #pragma unroll
                for (int e = 0; e < 4; e++) {
                    const int d = dqq + i4 * 4 + e;
                    const int widx = (tp_w * 72 + d) * 2 + half_w;
                    __nv_bfloat16 k0 = __float2bfloat16_rn(kf[e]);
                    __nv_bfloat16 k1 = __float2bfloat16_rn(kf[e] - __bfloat162float(k0));
                    __nv_bfloat16 v0 = __float2bfloat16_rn(vf[e]);
                    __nv_bfloat16 v1 = __float2bfloat16_rn(vf[e] - __bfloat162float(v0));
                    k0h[widx] = __bfloat16_as_ushort(k0);
                    k1h[widx] = __bfloat16_as_ushort(k1);
                    v0h[widx] = __bfloat16_as_ushort(v0);
                    v1h[widx] = __bfloat16_as_ushort(v1);
                }
            }
        }
        __syncthreads();

        const unsigned* asg0 = smw + OFF_ASG0;
        const unsigned* asg1 = smw + OFF_ASG1;
        const unsigned* kt0  = smw + OFF_KT0;
        const unsigned* kt1  = smw + OFF_KT1;
        const unsigned* vt0  = smw + OFF_VT0;
        const unsigned* vt1  = smw + OFF_VT1;
        #pragma unroll
        for (int ks = 0; ks < 4; ks++) {
            const int r0 = ks * 8 + tig, r1 = ks * 8 + tig + 4;
            const int mb = warp * 16 + gid;
            unsigned a0f[4], a1f[4];
            a0f[0] = asg0[r0 * 136 + mb]; a0f[1] = asg0[r0 * 136 + mb + 8];
            a0f[2] = asg0[r1 * 136 + mb]; a0f[3] = asg0[r1 * 136 + mb + 8];
            a1f[0] = asg1[r0 * 136 + mb]; a1f[1] = asg1[r0 * 136 + mb + 8];
            a1f[2] = asg1[r1 * 136 + mb]; a1f[3] = asg1[r1 * 136 + mb + 8];
            #pragma unroll
            for (int nt = 0; nt < 8; nt++) {
                const int nb = nt * 8 + gid;
                unsigned bk0[2], bk1[2], bv0[2], bv1[2];
                bk0[0] = kt0[r0 * 72 + nb]; bk0[1] = kt0[r1 * 72 + nb];
                bk1[0] = kt1[r0 * 72 + nb]; bk1[1] = kt1[r1 * 72 + nb];
                bv0[0] = vt0[r0 * 72 + nb]; bv0[1] = vt0[r1 * 72 + nb];
                bv1[0] = vt1[r0 * 72 + nb]; bv1[1] = vt1[r1 * 72 + nb];
                mma_bf16(acc[nt], a0f, bk0);
                mma_bf16(acc[nt], a0f, bk1);
                mma_bf16(acc[nt], a1f, bk0);
                mma_bf16(acc[8 + nt], a0f, bv0);
                mma_bf16(acc[8 + nt], a0f, bv1);
                mma_bf16(acc[8 + nt], a1f, bv0);
            }
        }
    }

    {
        const size_t base = (size_t)bh * Sn * DIMh;
        const int s0 = warp * 16 + gid, s1 = s0 + 8;
        #pragma unroll
        for (int nt = 0; nt < 8; nt++) {
            const int d = nt * 8 + tig * 2;
            atomicAdd(&bK[base + s0 * 64 + d],     acc[nt][0]);
            atomicAdd(&bK[base + s0 * 64 + d + 1], acc[nt][1]);
            atomicAdd(&bK[base + s1 * 64 + d],     acc[nt][2]);
            atomicAdd(&bK[base + s1 * 64 + d + 1], acc[nt][3]);
            atomicAdd(&bV[base + s0 * 64 + d],     acc[8 + nt][0]);
            atomicAdd(&bV[base + s0 * 64 + d + 1], acc[8 + nt][1]);
            atomicAdd(&bV[base + s1 * 64 + d],     acc[8 + nt][2]);
            atomicAdd(&bV[base + s1 * 64 + d + 1], acc[8 + nt][3]);
        }
    }
}

// ---------------- bucket attention (warp per token) ------------------------
#define AT_TPC    512
#define AT_CHUNKS (Tsz / AT_TPC)    // 8
#define AT_SMEM   ((2*Sn*65 + 8*Sn) * sizeof(float))

__global__ void __launch_bounds__(256)
attn_kernel(const float* __restrict__ Q,
            const float* __restrict__ bK, const float* __restrict__ bV,
            const float* __restrict__ bA, float* __restrict__ outp)
{
    extern __shared__ float sm[];
    float* sK = sm;
    float* sV = sK + Sn * 65;
    float* sp = sV + Sn * 65;

    const int tid   = threadIdx.x;
    const int bh    = blockIdx.x / AT_CHUNKS;
    const int chunk = blockIdx.x % AT_CHUNKS;
    const int b = bh / Hn, h = bh % Hn;

    const size_t base = (size_t)bh * Sn * DIMh;
    for (int i = tid; i < Sn * DIMh; i += blockDim.x) {
        int s = i / DIMh, d = i % DIMh;
        float inv = 1.0f / (bA[(size_t)bh * Sn + s] + 1e-6f);
        sK[s * 65 + d] = bK[base + i] * inv;
        sV[s * 65 + d] = bV[base + i] * inv;
    }
    __syncthreads();

    const int warp = tid >> 5, lane = tid & 31;
    float* pwarp = sp + warp * Sn;

    for (int tt = warp; tt < AT_TPC; tt += 8) {
        const int t = chunk * AT_TPC + tt;
        const float* qrow = Q + ((size_t)(b * Tsz + t)) * Dsz + h * DIMh;
        float q0 = qrow[lane], q1 = qrow[lane + 32];

        float a0 = 0.f, a1 = 0.f, a2 = 0.f, a3 = 0.f;
        #pragma unroll
        for (int d = 0; d < 32; d++) {
            float qd = __shfl_sync(0xffffffffu, q0, d);
            a0 += qd * sK[(lane      ) * 65 + d];
            a1 += qd * sK[(lane + 32 ) * 65 + d];
            a2 += qd * sK[(lane + 64 ) * 65 + d];
            a3 += qd * sK[(lane + 96 ) * 65 + d];
        }
        #pragma unroll
        for (int d = 0; d < 32; d++) {
            float qd = __shfl_sync(0xffffffffu, q1, d);
            a0 += qd * sK[(lane      ) * 65 + 32 + d];
            a1 += qd * sK[(lane + 32 ) * 65 + 32 + d];
            a2 += qd * sK[(lane + 64 ) * 65 + 32 + d];
            a3 += qd * sK[(lane + 96 ) * 65 + 32 + d];
        }
        const float sc = 0.125f;
        a0 *= sc; a1 *= sc; a2 *= sc; a3 *= sc;

        float lm = fmaxf(fmaxf(a0, a1), fmaxf(a2, a3));
        #pragma unroll
        for (int o = 16; o; o >>= 1) lm = fmaxf(lm, __shfl_xor_sync(0xffffffffu, lm, o));
        float e0 = expf(a0 - lm), e1 = expf(a1 - lm), e2 = expf(a2 - lm), e3 = expf(a3 - lm);
        float z = e0 + e1 + e2 + e3;
        #pragma unroll
        for (int o = 16; o; o >>= 1) z += __shfl_xor_sync(0xffffffffu, z, o);
        float invz = 1.0f / z;

        pwarp[lane]      = e0 * invz;
        pwarp[lane + 32] = e1 * invz;
        pwarp[lane + 64] = e2 * invz;
        pwarp[lane + 96] = e3 * invz;
        __syncwarp();

        float o0 = 0.f, o1 = 0.f;
        #pragma unroll 8
        for (int s = 0; s < Sn; s++) {
            float p = pwarp[s];
            o0 += p * sV[s * 65 + lane];
            o1 += p * sV[s * 65 + lane + 32];
        }
        size_t obase = ((size_t)(b * Tsz + t)) * Dsz + h * DIMh;
        outp[obase + lane]      = o0;
        outp[obase + lane + 32] = o1;
        __syncwarp();
    }
}

// ---------------- launch ----------------------------------------------------
extern "C" void kernel_launch(void* const* d_in, const int* in_sizes, int n_in,
                              void* d_out, int out_size)
{
    const float* x      = (const float*)d_in[0];
    const float* mask   = (const float*)d_in[1];
    const float* Wq     = (const float*)d_in[2];
    const float* Wk     = (const float*)d_in[3];
    const float* Wv     = (const float*)d_in[4];
    const float* Wout   = (const float*)d_in[5];
    const float* b_out  = (const float*)d_in[6];
    const float* planes = (const float*)d_in[7];
    const float* protos = (const float*)d_in[8];
    const float* ltemp  = (const float*)d_in[9];
    float* out = (float*)d_out;

    void *pQ, *pK, *pV, *pATT, *pbK, *pbV, *pbA, *pxp, *pattp, *pwp;
    cudaGetSymbolAddress(&pQ,  g_Q);
    cudaGetSymbolAddress(&pK,  g_K);
    cudaGetSymbolAddress(&pV,  g_V);
    cudaGetSymbolAddress(&pATT,g_ATT);
    cudaGetSymbolAddress(&pbK, g_bK);
    cudaGetSymbolAddress(&pbV, g_bV);
    cudaGetSymbolAddress(&pbA, g_bA);
    cudaGetSymbolAddress(&pxp,  g_xp);
    cudaGetSymbolAddress(&pattp,g_attp);
    cudaGetSymbolAddress(&pwp,  g_wp);
    unsigned* xp   = (unsigned*)pxp;
    unsigned* attp = (unsigned*)pattp;
    unsigned* wp   = (unsigned*)pwp;

    const int GSMEM = 128 * 129 * 4;   // 66048 B (epilogue staging dominates)
    cudaFuncSetAttribute(pk_gemm<2,3>, cudaFuncAttributeMaxDynamicSharedMemorySize, GSMEM);
    cudaFuncSetAttribute(pk_gemm<3,6>, cudaFuncAttributeMaxDynamicSharedMemorySize, GSMEM);
    cudaFuncSetAttribute(route2_kernel, cudaFuncAttributeMaxDynamicSharedMemorySize, RT2_SMEM);
    cudaFuncSetAttribute(attn_kernel,  cudaFuncAttributeMaxDynamicSharedMemorySize, AT_SMEM);

    dim3 gblk(256);
    dim3 ggrid(Dsz / 128, BT / 128);       // (8, 128)
    dim3 apgrid(BT / 32, Dsz / 32);        // (512, 32)

    zero_buckets<<<256, 256>>>((float*)pbK, (float*)pbV, (float*)pbA);

    // one-shot packing
    apackT<3><<<apgrid, 256>>>(x, xp);
    bpack<2><<<2048, 256>>>(Wq,   wp + 0 * BPL);
    bpack<3><<<2048, 256>>>(Wk,   wp + 2 * BPL);
    bpack<2><<<2048, 256>>>(Wv,   wp + 5 * BPL);
    bpack<2><<<2048, 256>>>(Wout, wp + 7 * BPL);

    // projections from packed inputs
    pk_gemm<2,3><<<ggrid, gblk, GSMEM>>>(xp, wp + 0 * BPL, (float*)pQ, mask, nullptr);
    pk_gemm<3,6><<<ggrid, gblk, GSMEM>>>(xp, wp + 2 * BPL, (float*)pK, mask, nullptr);
    pk_gemm<2,3><<<ggrid, gblk, GSMEM>>>(xp, wp + 5 * BPL, (float*)pV, mask, nullptr);

    route2_kernel<<<BHn * RT_NCHUNK, 256, RT2_SMEM>>>(
        (const float*)pK, (const float*)pV, planes, protos, ltemp,
        (float*)pbK, (float*)pbV, (float*)pbA);

    attn_kernel<<<BHn * AT_CHUNKS, 256, AT_SMEM>>>(
        (const float*)pQ, (const float*)pbK, (const float*)pbV, (const float*)pbA,
        (float*)pATT);

    // pack attention output, then output projection
    apackT<2><<<apgrid, 256>>>((const float*)pATT, attp);
    pk_gemm<2,3><<<ggrid, gblk, GSMEM>>>(attp, wp + 7 * BPL, out, nullptr, b_out);
}

// round 12
// speedup vs baseline: 1.5092x; 1.3125x over previous
#include <cuda_runtime.h>
#include <cuda_bf16.h>
#include <math.h>

// Problem constants
#define Bsz  4
#define Tsz  4096
#define Dsz  1024
#define Hn   16
#define DIMh 64
#define Ln   8
#define KBn  4
#define Rn   16
#define Sn   128
#define BT   (Bsz*Tsz)      // 16384
#define BHn  (Bsz*Hn)       // 64

// ---------------- scratch (device globals: no allocation allowed) ----------
__device__ float g_Q  [(size_t)BT*Dsz];
__device__ float g_K  [(size_t)BT*Dsz];
__device__ float g_V  [(size_t)BT*Dsz];
__device__ float g_ATT[(size_t)BT*Dsz];
__device__ float g_bK [(size_t)BHn*Sn*DIMh];
__device__ float g_bV [(size_t)BHn*Sn*DIMh];
__device__ float g_bA [(size_t)BHn*Sn];

// packed bf16x2 split planes (k-pair-major)
#define APL ((size_t)512*16384)     // activation plane: [kw=512][m=16384]
#define BPL ((size_t)512*1024)      // weight plane:     [kw=512][n=1024]
__device__ unsigned g_xp  [3*APL];
__device__ unsigned g_attp[2*APL];
__device__ unsigned g_wp  [9*BPL];

// normalized bucket split planes
#define KPL ((size_t)BHn*32*Sn)     // [bh][kw=32][bucket=128]
#define VPL ((size_t)BHn*64*DIMh)   // [bh][kwb=64][dim=64]
__device__ unsigned g_nK[2*KPL];
__device__ unsigned g_nV[2*VPL];

// ======================= helpers ============================================
__device__ __forceinline__ unsigned smem_u32(const void* p) {
    unsigned a;
    asm("{ .reg .u64 t; cvta.to.shared.u64 t, %1; cvt.u32.u64 %0, t; }"
        : "=r"(a) : "l"(p));
    return a;
}

__device__ __forceinline__ void mma_bf16(float c[4], const unsigned a[4],
                                         const unsigned b[2]) {
    asm volatile(
        "mma.sync.aligned.m16n8k16.row.col.f32.bf16.bf16.f32 "
        "{%0,%1,%2,%3}, {%4,%5,%6,%7}, {%8,%9}, {%0,%1,%2,%3};"
        : "+f"(c[0]), "+f"(c[1]), "+f"(c[2]), "+f"(c[3])
        : "r"(a[0]), "r"(a[1]), "r"(a[2]), "r"(a[3]), "r"(b[0]), "r"(b[1]));
}

__device__ __forceinline__ void cpasync16(unsigned saddr, const void* gptr) {
    asm volatile("cp.async.cg.shared.global [%0], [%1], 16;"
                 :: "r"(saddr), "l"(gptr));
}

__device__ __forceinline__ unsigned pack2bf(float x0, float x1) {
    __nv_bfloat16 b0 = __float2bfloat16_rn(x0);
    __nv_bfloat16 b1 = __float2bfloat16_rn(x1);
    return (unsigned)__bfloat16_as_ushort(b0) |
           ((unsigned)__bfloat16_as_ushort(b1) << 16);
}

// ================= pack kernels (one-shot split conversion) =================
template<int NS>
__global__ void __launch_bounds__(256)
apackT(const float* __restrict__ X, unsigned* __restrict__ out)
{
    __shared__ float tile[32][33];
    const int tid = threadIdx.x;
    const int m0 = blockIdx.x * 32, k0 = blockIdx.y * 32;
    const int rr = tid >> 5, cc = tid & 31;

    #pragma unroll
    for (int j = 0; j < 4; j++)
        tile[rr + j * 8][cc] = X[(size_t)(m0 + rr + j * 8) * 1024 + k0 + cc];
    __syncthreads();

    #pragma unroll
    for (int j = 0; j < 2; j++) {
        const int kwl = rr + j * 8;
        float x0 = tile[cc][2 * kwl];
        float x1 = tile[cc][2 * kwl + 1];
        #pragma unroll
        for (int s = 0; s < NS; s++) {
            __nv_bfloat16 b0 = __float2bfloat16_rn(x0);
            __nv_bfloat16 b1 = __float2bfloat16_rn(x1);
            out[s * APL + (size_t)(k0 / 2 + kwl) * 16384 + m0 + cc] =
                (unsigned)__bfloat16_as_ushort(b0) |
                ((unsigned)__bfloat16_as_ushort(b1) << 16);
            x0 -= __bfloat162float(b0);
            x1 -= __bfloat162float(b1);
        }
    }
}

template<int NS>
__global__ void __launch_bounds__(256)
bpack(const float* __restrict__ W, unsigned* __restrict__ out)
{
    const int idx = blockIdx.x * 256 + threadIdx.x;
    const int kw = idx >> 10, n = idx & 1023;
    float x0 = W[(size_t)(2 * kw) * 1024 + n];
    float x1 = W[(size_t)(2 * kw + 1) * 1024 + n];
    #pragma unroll
    for (int s = 0; s < NS; s++) {
        __nv_bfloat16 b0 = __float2bfloat16_rn(x0);
        __nv_bfloat16 b1 = __float2bfloat16_rn(x1);
        out[s * BPL + idx] =
            (unsigned)__bfloat16_as_ushort(b0) |
            ((unsigned)__bfloat16_as_ushort(b1) << 16);
        x0 -= __bfloat162float(b0);
        x1 -= __bfloat162float(b1);
    }
}

// ================= packed-input bf16 split GEMM =============================
#define BTSZ 1088

template<int NSPLIT, int NPASS>
__global__ void __launch_bounds__(256, 2)
pk_gemm(const unsigned* __restrict__ Ap, const unsigned* __restrict__ Bp,
        float* __restrict__ C,
        const float* __restrict__ rowscale, const float* __restrict__ bias)
{
    extern __shared__ float sm[];
    unsigned* smu = (unsigned*)sm;
    const unsigned sbase = smem_u32(smu);
    const int tid  = threadIdx.x;
    const int warp = tid >> 5, lane = tid & 31;
    const int wm = warp >> 2, wn = warp & 3;
    const int gid = lane >> 2, tig = lane & 3;
    const int m0 = blockIdx.y * 128, n0 = blockIdx.x * 128;

    constexpr int BUF = 2 * NSPLIT * BTSZ;
    constexpr int PA[6] = {0, 0, 1, 0, 2, 1};
    constexpr int PB[6] = {0, 1, 0, 2, 0, 1};

    const int row = tid >> 5;
    const int c4  = lane * 4;

    float cacc[16][4];
    #pragma unroll
    for (int i = 0; i < 16; i++)
        #pragma unroll
        for (int j = 0; j < 4; j++) cacc[i][j] = 0.f;

    unsigned sA[NSPLIT], sB[NSPLIT];
    #pragma unroll
    for (int s = 0; s < NSPLIT; s++) {
        sA[s] = sbase + (unsigned)(s * BTSZ + row * 136 + c4) * 4;
        sB[s] = sbase + (unsigned)((NSPLIT + s) * BTSZ + row * 136 + c4) * 4;
    }

    auto issue = [&](int i, int buf) {
        const unsigned boff = (unsigned)(buf * BUF) * 4;
        #pragma unroll
        for (int s = 0; s < NSPLIT; s++) {
            cpasync16(sA[s] + boff,
                      Ap + s * APL + (size_t)(i * 8 + row) * 16384 + m0 + c4);
            cpasync16(sB[s] + boff,
                      Bp + s * BPL + (size_t)(i * 8 + row) * 1024 + n0 + c4);
        }
        asm volatile("cp.async.commit_group;");
    };

    issue(0, 0);

    for (int i = 0; i < 64; i++) {
        const int buf = i & 1;
        if (i < 63) {
            issue(i + 1, buf ^ 1);
            asm volatile("cp.async.wait_group 1;");
        } else {
            asm volatile("cp.async.wait_group 0;");
        }
        __syncthreads();

        #pragma unroll
        for (int p = 0; p < NPASS; p++) {
            const unsigned* As = smu + buf * BUF + PA[p] * BTSZ;
            const unsigned* Bs = smu + buf * BUF + (NSPLIT + PB[p]) * BTSZ;
            unsigned af[4][4];
            #pragma unroll
            for (int mt = 0; mt < 4; mt++) {
                const int mb = wm * 64 + mt * 16 + gid;
                af[mt][0] = As[tig * 136 + mb];
                af[mt][1] = As[tig * 136 + mb + 8];
                af[mt][2] = As[(tig + 4) * 136 + mb];
                af[mt][3] = As[(tig + 4) * 136 + mb + 8];
            }
            unsigned bfr[4][2];
            #pragma unroll
            for (int nt = 0; nt < 4; nt++) {
                const int nb = wn * 32 + nt * 8 + gid;
                bfr[nt][0] = Bs[tig * 136 + nb];
                bfr[nt][1] = Bs[(tig + 4) * 136 + nb];
            }
            #pragma unroll
            for (int mt = 0; mt < 4; mt++)
                #pragma unroll
                for (int nt = 0; nt < 4; nt++)
                    mma_bf16(cacc[mt * 4 + nt], af[mt], bfr[nt]);
        }
        __syncthreads();
    }

    float* st = sm;
    #pragma unroll
    for (int mt = 0; mt < 4; mt++) {
        #pragma unroll
        for (int nt = 0; nt < 4; nt++) {
            const float* c = cacc[mt * 4 + nt];
            const int r  = wm * 64 + mt * 16 + gid;
            const int cc = wn * 32 + nt * 8 + (tig << 1);
            st[r * 129 + cc]           = c[0];
            st[r * 129 + cc + 1]       = c[1];
            st[(r + 8) * 129 + cc]     = c[2];
            st[(r + 8) * 129 + cc + 1] = c[3];
        }
    }
    __syncthreads();
    #pragma unroll 4
    for (int it = 0; it < 64; it++) {
        const int flat = tid + it * 256;
        const int rr = flat >> 7, cc = flat & 127;
        float v = st[rr * 129 + cc];
        if (rowscale) v *= rowscale[m0 + rr];
        if (bias)     v += bias[n0 + cc];
        C[(size_t)(m0 + rr) * 1024 + n0 + cc] = v;
    }
}

// ---------------- zero bucket accumulators ---------------------------------
__global__ void zero_buckets(float* __restrict__ bK, float* __restrict__ bV,
                             float* __restrict__ bA)
{
    int n = BHn * Sn * DIMh;
    for (int i = blockIdx.x * blockDim.x + threadIdx.x; i < n;
         i += gridDim.x * blockDim.x) { bK[i] = 0.f; bV[i] = 0.f; }
    int na = BHn * Sn;
    for (int i = blockIdx.x * blockDim.x + threadIdx.x; i < na;
         i += gridDim.x * blockDim.x) bA[i] = 0.f;
}

// ================= routing + bucket accumulation via MMA ====================
#define RT_CHUNK   1024
#define RT_NCHUNK  (Tsz / RT_CHUNK)   // 4
#define RT_NTILE   (RT_CHUNK / 64)    // 16

#define OFF_SW    0
#define OFF_SIDX  16384
#define OFF_SA    20480
#define OFF_SPL   20608
#define OFF_SPR   22656
#define OFF_ASG0  22720
#define OFF_ASG1  27072
#define OFF_KT0   31424
#define OFF_KT1   33728
#define OFF_VT0   36032
#define OFF_VT1   38336
#define RT2_WORDS 40640
#define RT2_SMEM  (RT2_WORDS * 4)

__global__ void __launch_bounds__(256, 1)
route2_kernel(const float* __restrict__ K, const float* __restrict__ V,
              const float* __restrict__ planes_T,
              const float* __restrict__ protos_T,
              const float* __restrict__ ltemp,
              float* __restrict__ bK, float* __restrict__ bV,
              float* __restrict__ bA)
{
    extern __shared__ float smf[];
    unsigned* smw = (unsigned*)smf;
    unsigned char* sidxb = (unsigned char*)(smw + OFF_SIDX);
    unsigned* sw = smw + OFF_SW;
    float* sA  = smf + OFF_SA;
    float* spl = smf + OFF_SPL;
    float* spr = smf + OFF_SPR;

    const int tid   = threadIdx.x;
    const int warp  = tid >> 5, lane = tid & 31;
    const int gid   = lane >> 2, tig = lane & 3;
    const int bh    = blockIdx.x >> 2;
    const int chunk = blockIdx.x & 3;
    const int b = bh >> 4, h = bh & 15;

    for (int i = tid; i < Sn; i += 256) sA[i] = 0.f;
    for (int i = tid; i < DIMh * 32; i += 256) spl[i] = planes_T[i];
    for (int i = tid; i < KBn * Rn; i += 256) spr[i] = protos_T[i];
    __syncthreads();

    float scale = expf(ltemp[0]);
    scale = fminf(fmaxf(scale, 0.01f), 20.0f);
    const float inv_scale = 1.0f / scale;

    for (int tt = 0; tt < 4; tt++) {
        const int tl = tt * 256 + tid;
        const int t  = chunk * RT_CHUNK + tl;
        const float* krow = K + ((size_t)(b * Tsz + t)) * Dsz + h * DIMh;

        float proj[32];
        #pragma unroll
        for (int p = 0; p < 32; p++) proj[p] = 0.f;
        #pragma unroll 4
        for (int d = 0; d < DIMh; d++) {
            float kd = krow[d];
            #pragma unroll
            for (int p = 0; p < 32; p++) proj[p] += kd * spl[d * 32 + p];
        }
        #pragma unroll
        for (int p = 0; p < 32; p++) proj[p] = tanhf(proj[p]) * inv_scale;

        #pragma unroll
        for (int l = 0; l < Ln; l++) {
            float e[16];
            float mx = -1e30f;
            #pragma unroll
            for (int r = 0; r < Rn; r++) {
                float lg = proj[l*4+0] * spr[0*Rn + r] + proj[l*4+1] * spr[1*Rn + r]
                         + proj[l*4+2] * spr[2*Rn + r] + proj[l*4+3] * spr[3*Rn + r];
                e[r] = lg;
                mx = fmaxf(mx, lg);
            }
            float Z = 0.f;
            #pragma unroll
            for (int r = 0; r < Rn; r++) { e[r] = expf(e[r] - mx); Z += e[r]; }
            int i1 = 0; float b1 = e[0];
            #pragma unroll
            for (int r = 1; r < Rn; r++) if (e[r] > b1) { b1 = e[r]; i1 = r; }
            int i2 = -1; float b2 = -1.f;
            #pragma unroll
            for (int r = 0; r < Rn; r++) if (r != i1 && e[r] > b2) { b2 = e[r]; i2 = r; }
            const float denom = 1.0f / (b1 + b2 + 1e-6f * Z);
            const float w1f = b1 * denom, w2f = b2 * denom;

            __nv_bfloat16 w10 = __float2bfloat16_rn(w1f);
            __nv_bfloat16 w11 = __float2bfloat16_rn(w1f - __bfloat162float(w10));
            __nv_bfloat16 w20 = __float2bfloat16_rn(w2f);
            __nv_bfloat16 w21 = __float2bfloat16_rn(w2f - __bfloat162float(w20));

            const int s1 = l * Rn + i1, s2 = l * Rn + i2;
            sidxb[tl * 16 + l * 2]     = (unsigned char)s1;
            sidxb[tl * 16 + l * 2 + 1] = (unsigned char)s2;
            sw[tl * 16 + l * 2] =
                (unsigned)__bfloat16_as_ushort(w10) |
                ((unsigned)__bfloat16_as_ushort(w11) << 16);
            sw[tl * 16 + l * 2 + 1] =
                (unsigned)__bfloat16_as_ushort(w20) |
                ((unsigned)__bfloat16_as_ushort(w21) << 16);
            atomicAdd(&sA[s1], w1f);
            atomicAdd(&sA[s2], w2f);
        }
    }
    __syncthreads();
    if (tid < Sn) atomicAdd(&bA[(size_t)bh * Sn + tid], sA[tid]);

    float acc[16][4];
    #pragma unroll
    for (int i = 0; i < 16; i++)
        #pragma unroll
        for (int j = 0; j < 4; j++) acc[i][j] = 0.f;

    const int tok  = tid >> 2;
    const int dqq  = (tid & 3) * 16;
    const int tp_w = tok >> 1, half_w = tok & 1;

    for (int tile = 0; tile < RT_NTILE; tile++) {
        __syncthreads();
        {
            uint4 z = make_uint4(0u, 0u, 0u, 0u);
            uint4* a0 = (uint4*)(smw + OFF_ASG0);
            uint4* a1 = (uint4*)(smw + OFF_ASG1);
            for (int i = tid; i < 1088; i += 256) { a0[i] = z; a1[i] = z; }
        }
        __syncthreads();

        {
            unsigned short* a0h = (unsigned short*)(smw + OFF_ASG0);
            unsigned short* a1h = (unsigned short*)(smw + OFF_ASG1);
            #pragma unroll
            for (int it = 0; it < 4; it++) {
                const int e  = tid + it * 256;
                const int tl = tile * 64 + (e >> 4);
                const int j  = e & 15;
                const int s  = sidxb[tl * 16 + j];
                const unsigned wp = sw[tl * 16 + j];
                const int tt2 = e >> 4;
                const int widx = ((tt2 >> 1) * 136 + s) * 2 + (tt2 & 1);
                a0h[widx] = (unsigned short)(wp & 0xffffu);
                a1h[widx] = (unsigned short)(wp >> 16);
            }
        }

        {
            const int tglob = chunk * RT_CHUNK + tile * 64 + tok;
            const float* kr = K + ((size_t)(b * Tsz + tglob)) * Dsz + h * DIMh;
            const float* vr = V + ((size_t)(b * Tsz + tglob)) * Dsz + h * DIMh;
            unsigned short* k0h = (unsigned short*)(smw + OFF_KT0);
            unsigned short* k1h = (unsigned short*)(smw + OFF_KT1);
            unsigned short* v0h = (unsigned short*)(smw + OFF_VT0);
            unsigned short* v1h = (unsigned short*)(smw + OFF_VT1);
            #pragma unroll
            for (int i4 = 0; i4 < 4; i4++) {
                float4 kv = *(const float4*)(kr + dqq + i4 * 4);
                float4 vv = *(const float4*)(vr + dqq + i4 * 4);
                float kf[4] = {kv.x, kv.y, kv.z, kv.w};
                float vf[4] = {vv.x, vv.y, vv.z, vv.w};
                #pragma unroll
                for (int e = 0; e < 4; e++) {
                    const int d = dqq + i4 * 4 + e;
                    const int widx = (tp_w * 72 + d) * 2 + half_w;
                    __nv_bfloat16 k0 = __float2bfloat16_rn(kf[e]);
                    __nv_bfloat16 k1 = __float2bfloat16_rn(kf[e] - __bfloat162float(k0));
                    __nv_bfloat16 v0 = __float2bfloat16_rn(vf[e]);
                    __nv_bfloat16 v1 = __float2bfloat16_rn(vf[e] - __bfloat162float(v0));
                    k0h[widx] = __bfloat16_as_ushort(k0);
                    k1h[widx] = __bfloat16_as_ushort(k1);
                    v0h[widx] = __bfloat16_as_ushort(v0);
                    v1h[widx] = __bfloat16_as_ushort(v1);
                }
            }
        }
        __syncthreads();

        const unsigned* asg0 = smw + OFF_ASG0;
        const unsigned* asg1 = smw + OFF_ASG1;
        const unsigned* kt0  = smw + OFF_KT0;
        const unsigned* kt1  = smw + OFF_KT1;
        const unsigned* vt0  = smw + OFF_VT0;
        const unsigned* vt1  = smw + OFF_VT1;
        #pragma unroll
        for (int ks = 0; ks < 4; ks++) {
            const int r0 = ks * 8 + tig, r1 = ks * 8 + tig + 4;
            const int mb = warp * 16 + gid;
            unsigned a0f[4], a1f[4];
            a0f[0] = asg0[r0 * 136 + mb]; a0f[1] = asg0[r0 * 136 + mb + 8];
            a0f[2] = asg0[r1 * 136 + mb]; a0f[3] = asg0[r1 * 136 + mb + 8];
            a1f[0] = asg1[r0 * 136 + mb]; a1f[1] = asg1[r0 * 136 + mb + 8];
            a1f[2] = asg1[r1 * 136 + mb]; a1f[3] = asg1[r1 * 136 + mb + 8];
            #pragma unroll
            for (int nt = 0; nt < 8; nt++) {
                const int nb = nt * 8 + gid;
                unsigned bk0[2], bk1[2], bv0[2], bv1[2];
                bk0[0] = kt0[r0 * 72 + nb]; bk0[1] = kt0[r1 * 72 + nb];
                bk1[0] = kt1[r0 * 72 + nb]; bk1[1] = kt1[r1 * 72 + nb];
                bv0[0] = vt0[r0 * 72 + nb]; bv0[1] = vt0[r1 * 72 + nb];
                bv1[0] = vt1[r0 * 72 + nb]; bv1[1] = vt1[r1 * 72 + nb];
                mma_bf16(acc[nt], a0f, bk0);
                mma_bf16(acc[nt], a0f, bk1);
                mma_bf16(acc[nt], a1f, bk0);
                mma_bf16(acc[8 + nt], a0f, bv0);
                mma_bf16(acc[8 + nt], a0f, bv1);
                mma_bf16(acc[8 + nt], a1f, bv0);
            }
        }
    }

    {
        const size_t base = (size_t)bh * Sn * DIMh;
        const int s0 = warp * 16 + gid, s1 = s0 + 8;
        #pragma unroll
        for (int nt = 0; nt < 8; nt++) {
            const int d = nt * 8 + tig * 2;
            atomicAdd(&bK[base + s0 * 64 + d],     acc[nt][0]);
            atomicAdd(&bK[base + s0 * 64 + d + 1], acc[nt][1]);
            atomicAdd(&bK[base + s1 * 64 + d],     acc[nt][2]);
            atomicAdd(&bK[base + s1 * 64 + d + 1], acc[nt][3]);
            atomicAdd(&bV[base + s0 * 64 + d],     acc[8 + nt][0]);
            atomicAdd(&bV[base + s0 * 64 + d + 1], acc[8 + nt][1]);
            atomicAdd(&bV[base + s1 * 64 + d],     acc[8 + nt][2]);
            atomicAdd(&bV[base + s1 * 64 + d + 1], acc[8 + nt][3]);
        }
    }
}

// ============ normalize buckets + split-pack for MMA attention ==============
// Kp word layout: [bh][kw=dim-pair 0..31][bucket 0..127]
// Vp word layout: [bh][kwb=bucket-pair 0..63][dim 0..63]
__global__ void __launch_bounds__(256)
bnorm_kernel(const float* __restrict__ bK, const float* __restrict__ bV,
             const float* __restrict__ bA,
             unsigned* __restrict__ Kp, unsigned* __restrict__ Vp)
{
    __shared__ float inv[Sn];
    const int bh = blockIdx.x;
    const int tid = threadIdx.x;
    if (tid < Sn) inv[tid] = 1.0f / (bA[(size_t)bh * Sn + tid] + 1e-6f);
    __syncthreads();

    const size_t base = (size_t)bh * Sn * DIMh;
    for (int i = tid; i < 32 * Sn; i += 256) {
        const int kw = i >> 7, s = i & 127;
        float x0 = bK[base + s * 64 + 2 * kw]     * inv[s];
        float x1 = bK[base + s * 64 + 2 * kw + 1] * inv[s];
        __nv_bfloat16 b0 = __float2bfloat16_rn(x0);
        __nv_bfloat16 b1 = __float2bfloat16_rn(x1);
        Kp[0 * KPL + (size_t)bh * (32 * Sn) + i] = pack2bf(x0, x1);
        Kp[1 * KPL + (size_t)bh * (32 * Sn) + i] =
            pack2bf(x0 - __bfloat162float(b0), x1 - __bfloat162float(b1));
    }
    for (int i = tid; i < 64 * DIMh; i += 256) {
        const int kwb = i >> 6, d = i & 63;
        float x0 = bV[base + (2 * kwb) * 64 + d]     * inv[2 * kwb];
        float x1 = bV[base + (2 * kwb + 1) * 64 + d] * inv[2 * kwb + 1];
        __nv_bfloat16 b0 = __float2bfloat16_rn(x0);
        __nv_bfloat16 b1 = __float2bfloat16_rn(x1);
        Vp[0 * VPL + (size_t)bh * (64 * DIMh) + i] = pack2bf(x0, x1);
        Vp[1 * VPL + (size_t)bh * (64 * DIMh) + i] =
            pack2bf(x0 - __bfloat162float(b0), x1 - __bfloat162float(b1));
    }
}

// ================= MMA bucket attention =====================================
// Block = (bh, 1024-token chunk); 8 warps x 16 token rows = 128-token tiles.
#define A2_QS0  0
#define A2_QS1  4352                  // 32*136
#define A2_KS0  8704
#define A2_KS1  13056
#define A2_VS0  17408                 // 64*72 each
#define A2_VS1  22016
#define A2_WORDS 26624
#define A2_SMEM  (A2_WORDS * 4)

__global__ void __launch_bounds__(256, 1)
attn2_kernel(const float* __restrict__ Q,
             const unsigned* __restrict__ Kp, const unsigned* __restrict__ Vp,
             float* __restrict__ outp)
{
    extern __shared__ float smf[];
    unsigned* smw = (unsigned*)smf;
    const int tid   = threadIdx.x;
    const int warp  = tid >> 5, lane = tid & 31;
    const int gid   = lane >> 2, tig = lane & 3;
    const int bh    = blockIdx.x >> 2;
    const int chunk = blockIdx.x & 3;
    const int b = bh >> 4, h = bh & 15;

    // load normalized bucket K/V splits into strided smem
    {
        const unsigned* kp0 = Kp + 0 * KPL + (size_t)bh * (32 * Sn);
        const unsigned* kp1 = Kp + 1 * KPL + (size_t)bh * (32 * Sn);
        for (int i = tid; i < 32 * Sn; i += 256) {
            const int kw = i >> 7, n = i & 127;
            smw[A2_KS0 + kw * 136 + n] = kp0[i];
            smw[A2_KS1 + kw * 136 + n] = kp1[i];
        }
        const unsigned* vp0 = Vp + 0 * VPL + (size_t)bh * (64 * DIMh);
        const unsigned* vp1 = Vp + 1 * VPL + (size_t)bh * (64 * DIMh);
        for (int i = tid; i < 64 * DIMh; i += 256) {
            const int kwb = i >> 6, n = i & 63;
            smw[A2_VS0 + kwb * 72 + n] = vp0[i];
            smw[A2_VS1 + kwb * 72 + n] = vp1[i];
        }
    }

    const int qm   = tid >> 1;          // token row within tile (0..127)
    const int qhalf = (tid & 1) * 32;   // dim half handled by this thread

    for (int tile = 0; tile < 8; tile++) {
        const int t0 = chunk * 1024 + tile * 128;
        __syncthreads();   // smem tiles free (also covers initial K/V load)

        // load + split-convert Q tile (scale 1/8 folded in)
        {
            const float* qr = Q + ((size_t)(b * Tsz + t0 + qm)) * Dsz + h * DIMh + qhalf;
            #pragma unroll
            for (int j4 = 0; j4 < 8; j4++) {
                float4 qv = *(const float4*)(qr + j4 * 4);
                float qf[4] = {qv.x * 0.125f, qv.y * 0.125f, qv.z * 0.125f, qv.w * 0.125f};
                #pragma unroll
                for (int w = 0; w < 2; w++) {
                    const int kw = (qhalf >> 1) + j4 * 2 + w;
                    float x0 = qf[2 * w], x1 = qf[2 * w + 1];
                    __nv_bfloat16 b0 = __float2bfloat16_rn(x0);
                    __nv_bfloat16 b1 = __float2bfloat16_rn(x1);
                    smw[A2_QS0 + kw * 136 + qm] = pack2bf(x0, x1);
                    smw[A2_QS1 + kw * 136 + qm] =
                        pack2bf(x0 - __bfloat162float(b0), x1 - __bfloat162float(b1));
                }
            }
        }
        __syncthreads();

        // ---- S = Q @ bK^T : c[16 n-tiles][4], 3 split passes ----
        float c[16][4];
        #pragma unroll
        for (int i = 0; i < 16; i++)
            #pragma unroll
            for (int j = 0; j < 4; j++) c[i][j] = 0.f;

        #pragma unroll
        for (int ks = 0; ks < 4; ks++) {
            const int r0 = ks * 8 + tig, r1 = ks * 8 + tig + 4;
            const int mb = warp * 16 + gid;
            unsigned aq0[4], aq1[4];
            aq0[0] = smw[A2_QS0 + r0 * 136 + mb]; aq0[1] = smw[A2_QS0 + r0 * 136 + mb + 8];
            aq0[2] = smw[A2_QS0 + r1 * 136 + mb]; aq0[3] = smw[A2_QS0 + r1 * 136 + mb + 8];
            aq1[0] = smw[A2_QS1 + r0 * 136 + mb]; aq1[1] = smw[A2_QS1 + r0 * 136 + mb + 8];
            aq1[2] = smw[A2_QS1 + r1 * 136 + mb]; aq1[3] = smw[A2_QS1 + r1 * 136 + mb + 8];
            #pragma unroll
            for (int nt = 0; nt < 16; nt++) {
                const int nb = nt * 8 + gid;
                unsigned bk0[2], bk1[2];
                bk0[0] = smw[A2_KS0 + r0 * 136 + nb]; bk0[1] = smw[A2_KS0 + r1 * 136 + nb];
                bk1[0] = smw[A2_KS1 + r0 * 136 + nb]; bk1[1] = smw[A2_KS1 + r1 * 136 + nb];
                mma_bf16(c[nt], aq0, bk0);
                mma_bf16(c[nt], aq0, bk1);
                mma_bf16(c[nt], aq1, bk0);
            }
        }

        // ---- softmax over 128 buckets (rows gid and gid+8) ----
        float mx0 = -1e30f, mx1 = -1e30f;
        #pragma unroll
        for (int nt = 0; nt < 16; nt++) {
            mx0 = fmaxf(mx0, fmaxf(c[nt][0], c[nt][1]));
            mx1 = fmaxf(mx1, fmaxf(c[nt][2], c[nt][3]));
        }
        #pragma unroll
        for (int o = 1; o < 4; o <<= 1) {
            mx0 = fmaxf(mx0, __shfl_xor_sync(0xffffffffu, mx0, o));
            mx1 = fmaxf(mx1, __shfl_xor_sync(0xffffffffu, mx1, o));
        }
        float z0 = 0.f, z1 = 0.f;
        #pragma unroll
        for (int nt = 0; nt < 16; nt++) {
            c[nt][0] = expf(c[nt][0] - mx0); z0 += c[nt][0];
            c[nt][1] = expf(c[nt][1] - mx0); z0 += c[nt][1];
            c[nt][2] = expf(c[nt][2] - mx1); z1 += c[nt][2];
            c[nt][3] = expf(c[nt][3] - mx1); z1 += c[nt][3];
        }
        #pragma unroll
        for (int o = 1; o < 4; o <<= 1) {
            z0 += __shfl_xor_sync(0xffffffffu, z0, o);
            z1 += __shfl_xor_sync(0xffffffffu, z1, o);
        }
        const float rz0 = 1.0f / z0, rz1 = 1.0f / z1;

        // ---- O = E @ bV : 8 k-groups of 16 buckets, split E & V ----
        float o[8][4];
        #pragma unroll
        for (int i = 0; i < 8; i++)
            #pragma unroll
            for (int j = 0; j < 4; j++) o[i][j] = 0.f;

        #pragma unroll
        for (int ki = 0; ki < 8; ki++) {
            unsigned e0[4], e1[4];
            #pragma unroll
            for (int half = 0; half < 2; half++) {
                const float* cc0 = c[2 * ki + half];
                // rows gid (c0,c1) and gid+8 (c2,c3)
                __nv_bfloat16 p00 = __float2bfloat16_rn(cc0[0]);
                __nv_bfloat16 p01 = __float2bfloat16_rn(cc0[1]);
                __nv_bfloat16 p10 = __float2bfloat16_rn(cc0[2]);
                __nv_bfloat16 p11 = __float2bfloat16_rn(cc0[3]);
                e0[half * 2 + 0] = (unsigned)__bfloat16_as_ushort(p00) |
                                   ((unsigned)__bfloat16_as_ushort(p01) << 16);
                e0[half * 2 + 1] = (unsigned)__bfloat16_as_ushort(p10) |
                                   ((unsigned)__bfloat16_as_ushort(p11) << 16);
                e1[half * 2 + 0] = pack2bf(cc0[0] - __bfloat162float(p00),
                                           cc0[1] - __bfloat162float(p01));
                e1[half * 2 + 1] = pack2bf(cc0[2] - __bfloat162float(p10),
                                           cc0[3] - __bfloat162float(p11));
            }
            // reorder to A-fragment: a0=row gid k-lo, a1=row gid+8 k-lo,
            // a2=row gid k-hi, a3=row gid+8 k-hi  (already in that order:
            // e[0]=half0 rows gid, e[1]=half0 rows gid+8, e[2]=half1 ...)
            #pragma unroll
            for (int nt = 0; nt < 8; nt++) {
                const int nb = nt * 8 + gid;
                const int r0 = ki * 8 + tig, r1 = ki * 8 + tig + 4;
                unsigned bv0[2], bv1[2];
                bv0[0] = smw[A2_VS0 + r0 * 72 + nb]; bv0[1] = smw[A2_VS0 + r1 * 72 + nb];
                bv1[0] = smw[A2_VS1 + r0 * 72 + nb]; bv1[1] = smw[A2_VS1 + r1 * 72 + nb];
                mma_bf16(o[nt], e0, bv0);
                mma_bf16(o[nt], e0, bv1);
                mma_bf16(o[nt], e1, bv0);
            }
        }

        // ---- write O (scaled by 1/z) ----
        {
            const int row0 = t0 + warp * 16 + gid;
            float* out0 = outp + ((size_t)(b * Tsz + row0)) * Dsz + h * DIMh;
            float* out1 = out0 + (size_t)8 * Dsz;
            #pragma unroll
            for (int nt = 0; nt < 8; nt++) {
                const int d = nt * 8 + tig * 2;
                float2 v0 = make_float2(o[nt][0] * rz0, o[nt][1] * rz0);
                float2 v1 = make_float2(o[nt][2] * rz1, o[nt][3] * rz1);
                *(float2*)(out0 + d) = v0;
                *(float2*)(out1 + d) = v1;
            }
        }
    }
}

// ---------------- launch ----------------------------------------------------
extern "C" void kernel_launch(void* const* d_in, const int* in_sizes, int n_in,
                              void* d_out, int out_size)
{
    const float* x      = (const float*)d_in[0];
    const float* mask   = (const float*)d_in[1];
    const float* Wq     = (const float*)d_in[2];
    const float* Wk     = (const float*)d_in[3];
    const float* Wv     = (const float*)d_in[4];
    const float* Wout   = (const float*)d_in[5];
    const float* b_out  = (const float*)d_in[6];
    const float* planes = (const float*)d_in[7];
    const float* protos = (const float*)d_in[8];
    const float* ltemp  = (const float*)d_in[9];
    float* out = (float*)d_out;

    void *pQ, *pK, *pV, *pATT, *pbK, *pbV, *pbA, *pxp, *pattp, *pwp, *pnK, *pnV;
    cudaGetSymbolAddress(&pQ,  g_Q);
    cudaGetSymbolAddress(&pK,  g_K);
    cudaGetSymbolAddress(&pV,  g_V);
    cudaGetSymbolAddress(&pATT,g_ATT);
    cudaGetSymbolAddress(&pbK, g_bK);
    cudaGetSymbolAddress(&pbV, g_bV);
    cudaGetSymbolAddress(&pbA, g_bA);
    cudaGetSymbolAddress(&pxp,  g_xp);
    cudaGetSymbolAddress(&pattp,g_attp);
    cudaGetSymbolAddress(&pwp,  g_wp);
    cudaGetSymbolAddress(&pnK,  g_nK);
    cudaGetSymbolAddress(&pnV,  g_nV);
    unsigned* xp   = (unsigned*)pxp;
    unsigned* attp = (unsigned*)pattp;
    unsigned* wp   = (unsigned*)pwp;

    const int GSMEM = 128 * 129 * 4;
    cudaFuncSetAttribute(pk_gemm<2,3>, cudaFuncAttributeMaxDynamicSharedMemorySize, GSMEM);
    cudaFuncSetAttribute(pk_gemm<3,6>, cudaFuncAttributeMaxDynamicSharedMemorySize, GSMEM);
    cudaFuncSetAttribute(route2_kernel, cudaFuncAttributeMaxDynamicSharedMemorySize, RT2_SMEM);
    cudaFuncSetAttribute(attn2_kernel,  cudaFuncAttributeMaxDynamicSharedMemorySize, A2_SMEM);

    dim3 gblk(256);
    dim3 ggrid(Dsz / 128, BT / 128);
    dim3 apgrid(BT / 32, Dsz / 32);

    zero_buckets<<<256, 256>>>((float*)pbK, (float*)pbV, (float*)pbA);

    apackT<3><<<apgrid, 256>>>(x, xp);
    bpack<2><<<2048, 256>>>(Wq,   wp + 0 * BPL);
    bpack<3><<<2048, 256>>>(Wk,   wp + 2 * BPL);
    bpack<2><<<2048, 256>>>(Wv,   wp + 5 * BPL);
    bpack<2><<<2048, 256>>>(Wout, wp + 7 * BPL);

    pk_gemm<2,3><<<ggrid, gblk, GSMEM>>>(xp, wp + 0 * BPL, (float*)pQ, mask, nullptr);
    pk_gemm<3,6><<<ggrid, gblk, GSMEM>>>(xp, wp + 2 * BPL, (float*)pK, mask, nullptr);
    pk_gemm<2,3><<<ggrid, gblk, GSMEM>>>(xp, wp + 5 * BPL, (float*)pV, mask, nullptr);

    route2_kernel<<<BHn * RT_NCHUNK, 256, RT2_SMEM>>>(
        (const float*)pK, (const float*)pV, planes, protos, ltemp,
        (float*)pbK, (float*)pbV, (float*)pbA);

    bnorm_kernel<<<BHn, 256>>>((const float*)pbK, (const float*)pbV,
                               (const float*)pbA,
                               (unsigned*)pnK, (unsigned*)pnV);

    attn2_kernel<<<BHn * 4, 256, A2_SMEM>>>(
        (const float*)pQ, (const unsigned*)pnK, (const unsigned*)pnV,
        (float*)pATT);

    apackT<2><<<apgrid, 256>>>((const float*)pATT, attp);
    pk_gemm<2,3><<<ggrid, gblk, GSMEM>>>(attp, wp + 7 * BPL, out, nullptr, b_out);
}

// round 14
// speedup vs baseline: 1.5670x; 1.0383x over previous
#include <cuda_runtime.h>
#include <cuda_bf16.h>
#include <math.h>

// Problem constants
#define Bsz  4
#define Tsz  4096
#define Dsz  1024
#define Hn   16
#define DIMh 64
#define Ln   8
#define KBn  4
#define Rn   16
#define Sn   128
#define BT   (Bsz*Tsz)      // 16384
#define BHn  (Bsz*Hn)       // 64

// ---------------- scratch (device globals: no allocation allowed) ----------
__device__ float g_Q  [(size_t)BT*Dsz];
__device__ float g_K  [(size_t)BT*Dsz];
__device__ float g_V  [(size_t)BT*Dsz];
__device__ float g_ATT[(size_t)BT*Dsz];
__device__ float g_bK [(size_t)BHn*Sn*DIMh];
__device__ float g_bV [(size_t)BHn*Sn*DIMh];
__device__ float g_bA [(size_t)BHn*Sn];

// packed bf16x2 split planes, FRAGMENT-NATIVE layout:
// A plane word addr = (kchunk*8192 + mf)*16 + tig*4 + slot   (mf=(m>>4)*8+(m&7))
// B plane word addr = (kchunk*1024 + n)*8  + tig*2 + slot
#define APL ((size_t)512*16384)     // words per activation plane
#define BPL ((size_t)512*1024)      // words per weight plane
__device__ unsigned g_xp  [3*APL];
__device__ unsigned g_attp[2*APL];
__device__ unsigned g_wp  [9*BPL];  // Wq(2) Wk(3) Wv(2) Wout(2)

// normalized bucket split planes
#define KPL ((size_t)BHn*32*Sn)
#define VPL ((size_t)BHn*64*DIMh)
__device__ unsigned g_nK[2*KPL];
__device__ unsigned g_nV[2*VPL];

// ======================= helpers ============================================
__device__ __forceinline__ unsigned smem_u32(const void* p) {
    unsigned a;
    asm("{ .reg .u64 t; cvta.to.shared.u64 t, %1; cvt.u32.u64 %0, t; }"
        : "=r"(a) : "l"(p));
    return a;
}

__device__ __forceinline__ void mma_bf16(float c[4], const unsigned a[4],
                                         const unsigned b[2]) {
    asm volatile(
        "mma.sync.aligned.m16n8k16.row.col.f32.bf16.bf16.f32 "
        "{%0,%1,%2,%3}, {%4,%5,%6,%7}, {%8,%9}, {%0,%1,%2,%3};"
        : "+f"(c[0]), "+f"(c[1]), "+f"(c[2]), "+f"(c[3])
        : "r"(a[0]), "r"(a[1]), "r"(a[2]), "r"(a[3]), "r"(b[0]), "r"(b[1]));
}

__device__ __forceinline__ void cpasync16(unsigned saddr, const void* gptr) {
    asm volatile("cp.async.cg.shared.global [%0], [%1], 16;"
                 :: "r"(saddr), "l"(gptr));
}

__device__ __forceinline__ unsigned pack2bf(float x0, float x1) {
    __nv_bfloat16 b0 = __float2bfloat16_rn(x0);
    __nv_bfloat16 b1 = __float2bfloat16_rn(x1);
    return (unsigned)__bfloat16_as_ushort(b0) |
           ((unsigned)__bfloat16_as_ushort(b1) << 16);
}

// ================= pack kernels (one-shot, fragment-native) =================
// A-side: X[M,1024] fp32 -> NS planes, whole uint4 fragment per thread.
template<int NS>
__global__ void __launch_bounds__(256)
apackT(const float* __restrict__ X, unsigned* __restrict__ out)
{
    __shared__ float tile[64][36];   // stride 36 floats = 144 B (16B-aligned)
    const int tid = threadIdx.x;
    const int m0 = blockIdx.x * 64, k0 = blockIdx.y * 32;

    #pragma unroll
    for (int j = 0; j < 2; j++) {
        const int flat = tid + j * 256;
        const int row = flat >> 3, c4 = (flat & 7) * 4;
        *(float4*)&tile[row][c4] =
            *(const float4*)(X + (size_t)(m0 + row) * 1024 + k0 + c4);
    }
    __syncthreads();

    const int ic   = tid >> 7;          // 0..1 (k-chunk within 32-k block)
    const int rem  = tid & 127;
    const int tigf = rem & 3;
    const int mfl  = rem >> 2;          // 0..31
    const int ml   = ((mfl >> 3) << 4) | (mfl & 7);
    const int kb   = ic * 16 + tigf * 2;

    float f[8];
    f[0] = tile[ml][kb];         f[1] = tile[ml][kb + 1];
    f[2] = tile[ml + 8][kb];     f[3] = tile[ml + 8][kb + 1];
    f[4] = tile[ml][kb + 8];     f[5] = tile[ml][kb + 9];
    f[6] = tile[ml + 8][kb + 8]; f[7] = tile[ml + 8][kb + 9];

    const size_t frag = (size_t)((k0 >> 4) + ic) * 8192 + (m0 >> 1) + mfl;
    uint4* o4 = (uint4*)out;
    #pragma unroll
    for (int s = 0; s < NS; s++) {
        uint4 v;
        unsigned* vw = (unsigned*)&v;
        #pragma unroll
        for (int w = 0; w < 4; w++) {
            __nv_bfloat16 b0 = __float2bfloat16_rn(f[2 * w]);
            __nv_bfloat16 b1 = __float2bfloat16_rn(f[2 * w + 1]);
            vw[w] = (unsigned)__bfloat16_as_ushort(b0) |
                    ((unsigned)__bfloat16_as_ushort(b1) << 16);
            f[2 * w]     -= __bfloat162float(b0);
            f[2 * w + 1] -= __bfloat162float(b1);
        }
        o4[s * (APL >> 2) + frag * 4 + tigf] = v;
    }
}

// B-side: W[1024,1024] fp32 -> NS planes, uint2 (slot pair) per thread.
template<int NS>
__global__ void __launch_bounds__(256)
bpack(const float* __restrict__ W, unsigned* __restrict__ out)
{
    const int gidx = blockIdx.x * 256 + threadIdx.x;   // 0..262143
    const int tigf = gidx & 3;
    const int n    = (gidx >> 2) & 1023;
    const int i    = gidx >> 12;
    const int kbase = i * 16 + tigf * 2;

    float f[4];
    f[0] = W[(size_t)(kbase)     * 1024 + n];
    f[1] = W[(size_t)(kbase + 1) * 1024 + n];
    f[2] = W[(size_t)(kbase + 8) * 1024 + n];
    f[3] = W[(size_t)(kbase + 9) * 1024 + n];

    uint2* o2 = (uint2*)out;
    #pragma unroll
    for (int s = 0; s < NS; s++) {
        uint2 v;
        __nv_bfloat16 a0 = __float2bfloat16_rn(f[0]);
        __nv_bfloat16 a1 = __float2bfloat16_rn(f[1]);
        __nv_bfloat16 a2 = __float2bfloat16_rn(f[2]);
        __nv_bfloat16 a3 = __float2bfloat16_rn(f[3]);
        v.x = (unsigned)__bfloat16_as_ushort(a0) |
              ((unsigned)__bfloat16_as_ushort(a1) << 16);
        v.y = (unsigned)__bfloat16_as_ushort(a2) |
              ((unsigned)__bfloat16_as_ushort(a3) << 16);
        f[0] -= __bfloat162float(a0); f[1] -= __bfloat162float(a1);
        f[2] -= __bfloat162float(a2); f[3] -= __bfloat162float(a3);
        o2[s * (BPL >> 1) + (size_t)(i * 1024 + n) * 4 + tigf] = v;
    }
}

// ================= packed-input bf16 split GEMM (fragment layout) ===========
template<int NSPLIT, int NPASS>
__global__ void __launch_bounds__(256, 2)
pk_gemm(const unsigned* __restrict__ Ap, const unsigned* __restrict__ Bp,
        float* __restrict__ C,
        const float* __restrict__ rowscale, const float* __restrict__ bias)
{
    extern __shared__ float sm[];
    unsigned* smu = (unsigned*)sm;
    const unsigned sbase = smem_u32(smu);
    const int tid  = threadIdx.x;
    const int warp = tid >> 5, lane = tid & 31;
    const int wm = warp >> 2, wn = warp & 3;
    const int gid = lane >> 2, tig = lane & 3;
    const int m0 = blockIdx.y * 128, n0 = blockIdx.x * 128;

    constexpr int BUF = NSPLIT * 2048;     // words per stage
    constexpr int PA[6] = {0, 0, 1, 0, 2, 1};
    constexpr int PB[6] = {0, 1, 0, 2, 0, 1};

    float cacc[16][4];
    #pragma unroll
    for (int i = 0; i < 16; i++)
        #pragma unroll
        for (int j = 0; j < 4; j++) cacc[i][j] = 0.f;

    const size_t aoff0 = (size_t)m0 * 8 + tid * 4;   // mf0*16 + tid*4
    const size_t boff0 = (size_t)n0 * 8 + tid * 4;

    auto issue = [&](int i, int stg) {
        const unsigned sb = sbase + (unsigned)(stg * BUF) * 4;
        #pragma unroll
        for (int s = 0; s < NSPLIT; s++) {
            cpasync16(sb + (unsigned)(s * 1024 + tid * 4) * 4,
                      Ap + s * APL + (size_t)i * 131072 + aoff0);
            cpasync16(sb + (unsigned)((NSPLIT + s) * 1024 + tid * 4) * 4,
                      Bp + s * BPL + (size_t)i * 8192 + boff0);
        }
        asm volatile("cp.async.commit_group;");
    };

    issue(0, 0); issue(1, 1); issue(2, 2);

    for (int i = 0; i < 64; i++) {
        const int stg = i & 3;
        if (i < 62)       asm volatile("cp.async.wait_group 2;");
        else if (i == 62) asm volatile("cp.async.wait_group 1;");
        else              asm volatile("cp.async.wait_group 0;");
        __syncthreads();

        const unsigned base = (unsigned)(stg * BUF);
        #pragma unroll
        for (int p = 0; p < NPASS; p++) {
            const uint4* As4 = (const uint4*)(smu + base + PA[p] * 1024);
            const uint2* Bs2 = (const uint2*)(smu + base + (NSPLIT + PB[p]) * 1024);
            uint4 af[4];
            #pragma unroll
            for (int mt = 0; mt < 4; mt++)
                af[mt] = As4[((wm * 4 + mt) * 8 + gid) * 4 + tig];
            uint2 bfr[4];
            #pragma unroll
            for (int nt = 0; nt < 4; nt++)
                bfr[nt] = Bs2[(wn * 32 + nt * 8 + gid) * 4 + tig];
            #pragma unroll
            for (int mt = 0; mt < 4; mt++)
                #pragma unroll
                for (int nt = 0; nt < 4; nt++)
                    mma_bf16(cacc[mt * 4 + nt],
                             (const unsigned*)&af[mt],
                             (const unsigned*)&bfr[nt]);
        }
        __syncthreads();
        if (i + 3 < 64) issue(i + 3, (i + 3) & 3);
    }

    // ---- epilogue: stage C to smem, then coalesced writeout ----
    float* st = sm;
    #pragma unroll
    for (int mt = 0; mt < 4; mt++) {
        #pragma unroll
        for (int nt = 0; nt < 4; nt++) {
            const float* c = cacc[mt * 4 + nt];
            const int r  = wm * 64 + mt * 16 + gid;
            const int cc = wn * 32 + nt * 8 + (tig << 1);
            st[r * 129 + cc]           = c[0];
            st[r * 129 + cc + 1]       = c[1];
            st[(r + 8) * 129 + cc]     = c[2];
            st[(r + 8) * 129 + cc + 1] = c[3];
        }
    }
    __syncthreads();
    #pragma unroll 4
    for (int it = 0; it < 64; it++) {
        const int flat = tid + it * 256;
        const int rr = flat >> 7, cc = flat & 127;
        float v = st[rr * 129 + cc];
        if (rowscale) v *= rowscale[m0 + rr];
        if (bias)     v += bias[n0 + cc];
        C[(size_t)(m0 + rr) * 1024 + n0 + cc] = v;
    }
}

// ---------------- zero bucket accumulators ---------------------------------
__global__ void zero_buckets(float* __restrict__ bK, float* __restrict__ bV,
                             float* __restrict__ bA)
{
    int n = BHn * Sn * DIMh;
    for (int i = blockIdx.x * blockDim.x + threadIdx.x; i < n;
         i += gridDim.x * blockDim.x) { bK[i] = 0.f; bV[i] = 0.f; }
    int na = BHn * Sn;
    for (int i = blockIdx.x * blockDim.x + threadIdx.x; i < na;
         i += gridDim.x * blockDim.x) bA[i] = 0.f;
}

// ================= routing + bucket accumulation via MMA ====================
#define RT_CHUNK   512
#define RT_NCHUNK  (Tsz / RT_CHUNK)   // 8
#define RT_NTILE   (RT_CHUNK / 64)    // 8

#define OFF_SW    0                    // 512*16 words
#define OFF_SIDX  8192                 // 512*16 bytes = 2048 words
#define OFF_SA    10240                // 128
#define OFF_SPL   10368                // 2048
#define OFF_SPR   12416                // 64
#define OFF_ASG0  12480                // 4352
#define OFF_ASG1  16832
#define OFF_KT0   21184                // 2304
#define OFF_KT1   23488
#define OFF_VT0   25792
#define OFF_VT1   28096
#define RT2_WORDS 30400
#define RT2_SMEM  (RT2_WORDS * 4)

__global__ void __launch_bounds__(256, 1)
route2_kernel(const float* __restrict__ K, const float* __restrict__ V,
              const float* __restrict__ planes_T,
              const float* __restrict__ protos_T,
              const float* __restrict__ ltemp,
              float* __restrict__ bK, float* __restrict__ bV,
              float* __restrict__ bA)
{
    extern __shared__ float smf[];
    unsigned* smw = (unsigned*)smf;
    unsigned char* sidxb = (unsigned char*)(smw + OFF_SIDX);
    unsigned* sw = smw + OFF_SW;
    float* sA  = smf + OFF_SA;
    float* spl = smf + OFF_SPL;
    float* spr = smf + OFF_SPR;

    const int tid   = threadIdx.x;
    const int warp  = tid >> 5, lane = tid & 31;
    const int gid   = lane >> 2, tig = lane & 3;
    const int bh    = blockIdx.x >> 3;
    const int chunk = blockIdx.x & 7;
    const int b = bh >> 4, h = bh & 15;

    for (int i = tid; i < Sn; i += 256) sA[i] = 0.f;
    for (int i = tid; i < DIMh * 32; i += 256) spl[i] = planes_T[i];
    for (int i = tid; i < KBn * Rn; i += 256) spr[i] = protos_T[i];
    __syncthreads();

    float scale = expf(ltemp[0]);
    scale = fminf(fmaxf(scale, 0.01f), 20.0f);
    const float inv_scale = 1.0f / scale;

    // ---------- Phase A: routing for 512 tokens ----------
    for (int tt = 0; tt < 2; tt++) {
        const int tl = tt * 256 + tid;
        const int t  = chunk * RT_CHUNK + tl;
        const float* krow = K + ((size_t)(b * Tsz + t)) * Dsz + h * DIMh;

        float proj[32];
        #pragma unroll
        for (int p = 0; p < 32; p++) proj[p] = 0.f;
        #pragma unroll 4
        for (int d = 0; d < DIMh; d++) {
            float kd = krow[d];
            #pragma unroll
            for (int p = 0; p < 32; p++) proj[p] += kd * spl[d * 32 + p];
        }
        #pragma unroll
        for (int p = 0; p < 32; p++) proj[p] = tanhf(proj[p]) * inv_scale;

        #pragma unroll
        for (int l = 0; l < Ln; l++) {
            float e[16];
            float mx = -1e30f;
            #pragma unroll
            for (int r = 0; r < Rn; r++) {
                float lg = proj[l*4+0] * spr[0*Rn + r] + proj[l*4+1] * spr[1*Rn + r]
                         + proj[l*4+2] * spr[2*Rn + r] + proj[l*4+3] * spr[3*Rn + r];
                e[r] = lg;
                mx = fmaxf(mx, lg);
            }
            float Z = 0.f;
            #pragma unroll
            for (int r = 0; r < Rn; r++) { e[r] = expf(e[r] - mx); Z += e[r]; }
            int i1 = 0; float b1 = e[0];
            #pragma unroll
            for (int r = 1; r < Rn; r++) if (e[r] > b1) { b1 = e[r]; i1 = r; }
            int i2 = -1; float b2 = -1.f;
            #pragma unroll
            for (int r = 0; r < Rn; r++) if (r != i1 && e[r] > b2) { b2 = e[r]; i2 = r; }
            const float denom = 1.0f / (b1 + b2 + 1e-6f * Z);
            const float w1f = b1 * denom, w2f = b2 * denom;

            __nv_bfloat16 w10 = __float2bfloat16_rn(w1f);
            __nv_bfloat16 w11 = __float2bfloat16_rn(w1f - __bfloat162float(w10));
            __nv_bfloat16 w20 = __float2bfloat16_rn(w2f);
            __nv_bfloat16 w21 = __float2bfloat16_rn(w2f - __bfloat162float(w20));

            const int s1 = l * Rn + i1, s2 = l * Rn + i2;
            sidxb[tl * 16 + l * 2]     = (unsigned char)s1;
            sidxb[tl * 16 + l * 2 + 1] = (unsigned char)s2;
            sw[tl * 16 + l * 2] =
                (unsigned)__bfloat16_as_ushort(w10) |
                ((unsigned)__bfloat16_as_ushort(w11) << 16);
            sw[tl * 16 + l * 2 + 1] =
                (unsigned)__bfloat16_as_ushort(w20) |
                ((unsigned)__bfloat16_as_ushort(w21) << 16);
            atomicAdd(&sA[s1], w1f);
            atomicAdd(&sA[s2], w2f);
        }
    }
    __syncthreads();
    if (tid < Sn) atomicAdd(&bA[(size_t)bh * Sn + tid], sA[tid]);

    // ---------- Phase B: MMA bucketing ----------
    float acc[16][4];
    #pragma unroll
    for (int i = 0; i < 16; i++)
        #pragma unroll
        for (int j = 0; j < 4; j++) acc[i][j] = 0.f;

    const int tok  = tid >> 2;
    const int dqq  = (tid & 3) * 16;
    const int tp_w = tok >> 1, half_w = tok & 1;

    for (int tile = 0; tile < RT_NTILE; tile++) {
        __syncthreads();
        {
            uint4 z = make_uint4(0u, 0u, 0u, 0u);
            uint4* a0 = (uint4*)(smw + OFF_ASG0);
            uint4* a1 = (uint4*)(smw + OFF_ASG1);
            for (int i = tid; i < 1088; i += 256) { a0[i] = z; a1[i] = z; }
        }
        __syncthreads();

        {
            unsigned short* a0h = (unsigned short*)(smw + OFF_ASG0);
            unsigned short* a1h = (unsigned short*)(smw + OFF_ASG1);
            #pragma unroll
            for (int it = 0; it < 4; it++) {
                const int e  = tid + it * 256;
                const int tl = tile * 64 + (e >> 4);
                const int j  = e & 15;
                const int s  = sidxb[tl * 16 + j];
                const unsigned wp = sw[tl * 16 + j];
                const int tt2 = e >> 4;
                const int widx = ((tt2 >> 1) * 136 + s) * 2 + (tt2 & 1);
                a0h[widx] = (unsigned short)(wp & 0xffffu);
                a1h[widx] = (unsigned short)(wp >> 16);
            }
        }

        {
            const int tglob = chunk * RT_CHUNK + tile * 64 + tok;
            const float* kr = K + ((size_t)(b * Tsz + tglob)) * Dsz + h * DIMh;
            const float* vr = V + ((size_t)(b * Tsz + tglob)) * Dsz + h * DIMh;
            unsigned short* k0h = (unsigned short*)(smw + OFF_KT0);
            unsigned short* k1h = (unsigned short*)(smw + OFF_KT1);
            unsigned short* v0h = (unsigned short*)(smw + OFF_VT0);
            unsigned short* v1h = (unsigned short*)(smw + OFF_VT1);
            #pragma unroll
            for (int i4 = 0; i4 < 4; i4++) {
                float4 kv = *(const float4*)(kr + dqq + i4 * 4);
                float4 vv = *(const float4*)(vr + dqq + i4 * 4);
                float kf[4] = {kv.x, kv.y, kv.z, kv.w};
                float vf[4] = {vv.x, vv.y, vv.z, vv.w};
                #pragma unroll
                for (int e = 0; e < 4; e++) {
                    const int d = dqq + i4 * 4 + e;
                    const int widx = (tp_w * 72 + d) * 2 + half_w;
                    __nv_bfloat16 k0 = __float2bfloat16_rn(kf[e]);
                    __nv_bfloat16 k1 = __float2bfloat16_rn(kf[e] - __bfloat162float(k0));
                    __nv_bfloat16 v0 = __float2bfloat16_rn(vf[e]);
                    __nv_bfloat16 v1 = __float2bfloat16_rn(vf[e] - __bfloat162float(v0));
                    k0h[widx] = __bfloat16_as_ushort(k0);
                    k1h[widx] = __bfloat16_as_ushort(k1);
                    v0h[widx] = __bfloat16_as_ushort(v0);
                    v1h[widx] = __bfloat16_as_ushort(v1);
                }
            }
        }
        __syncthreads();

        const unsigned* asg0 = smw + OFF_ASG0;
        const unsigned* asg1 = smw + OFF_ASG1;
        const unsigned* kt0  = smw + OFF_KT0;
        const unsigned* kt1  = smw + OFF_KT1;
        const unsigned* vt0  = smw + OFF_VT0;
        const unsigned* vt1  = smw + OFF_VT1;
        #pragma unroll
        for (int ks = 0; ks < 4; ks++) {
            const int r0 = ks * 8 + tig, r1 = ks * 8 + tig + 4;
            const int mb = warp * 16 + gid;
            unsigned a0f[4], a1f[4];
            a0f[0] = asg0[r0 * 136 + mb]; a0f[1] = asg0[r0 * 136 + mb + 8];
            a0f[2] = asg0[r1 * 136 + mb]; a0f[3] = asg0[r1 * 136 + mb + 8];
            a1f[0] = asg1[r0 * 136 + mb]; a1f[1] = asg1[r0 * 136 + mb + 8];
            a1f[2] = asg1[r1 * 136 + mb]; a1f[3] = asg1[r1 * 136 + mb + 8];
            #pragma unroll
            for (int nt = 0; nt < 8; nt++) {
                const int nb = nt * 8 + gid;
                unsigned bk0[2], bk1[2], bv0[2], bv1[2];
                bk0[0] = kt0[r0 * 72 + nb]; bk0[1] = kt0[r1 * 72 + nb];
                bk1[0] = kt1[r0 * 72 + nb]; bk1[1] = kt1[r1 * 72 + nb];
                bv0[0] = vt0[r0 * 72 + nb]; bv0[1] = vt0[r1 * 72 + nb];
                bv1[0] = vt1[r0 * 72 + nb]; bv1[1] = vt1[r1 * 72 + nb];
                mma_bf16(acc[nt], a0f, bk0);
                mma_bf16(acc[nt], a0f, bk1);
                mma_bf16(acc[nt], a1f, bk0);
                mma_bf16(acc[8 + nt], a0f, bv0);
                mma_bf16(acc[8 + nt], a0f, bv1);
                mma_bf16(acc[8 + nt], a1f, bv0);
            }
        }
    }

    {
        const size_t base = (size_t)bh * Sn * DIMh;
        const int s0 = warp * 16 + gid, s1 = s0 + 8;
        #pragma unroll
        for (int nt = 0; nt < 8; nt++) {
            const int d = nt * 8 + tig * 2;
            atomicAdd(&bK[base + s0 * 64 + d],     acc[nt][0]);
            atomicAdd(&bK[base + s0 * 64 + d + 1], acc[nt][1]);
            atomicAdd(&bK[base + s1 * 64 + d],     acc[nt][2]);
            atomicAdd(&bK[base + s1 * 64 + d + 1], acc[nt][3]);
            atomicAdd(&bV[base + s0 * 64 + d],     acc[8 + nt][0]);
            atomicAdd(&bV[base + s0 * 64 + d + 1], acc[8 + nt][1]);
            atomicAdd(&bV[base + s1 * 64 + d],     acc[8 + nt][2]);
            atomicAdd(&bV[base + s1 * 64 + d + 1], acc[8 + nt][3]);
        }
    }
}

// ============ normalize buckets + split-pack for MMA attention ==============
__global__ void __launch_bounds__(256)
bnorm_kernel(const float* __restrict__ bK, const float* __restrict__ bV,
             const float* __restrict__ bA,
             unsigned* __restrict__ Kp, unsigned* __restrict__ Vp)
{
    __shared__ float inv[Sn];
    const int bh = blockIdx.x;
    const int tid = threadIdx.x;
    if (tid < Sn) inv[tid] = 1.0f / (bA[(size_t)bh * Sn + tid] + 1e-6f);
    __syncthreads();

    const size_t base = (size_t)bh * Sn * DIMh;
    for (int i = tid; i < 32 * Sn; i += 256) {
        const int kw = i >> 7, s = i & 127;
        float x0 = bK[base + s * 64 + 2 * kw]     * inv[s];
        float x1 = bK[base + s * 64 + 2 * kw + 1] * inv[s];
        __nv_bfloat16 b0 = __float2bfloat16_rn(x0);
        __nv_bfloat16 b1 = __float2bfloat16_rn(x1);
        Kp[0 * KPL + (size_t)bh * (32 * Sn) + i] = pack2bf(x0, x1);
        Kp[1 * KPL + (size_t)bh * (32 * Sn) + i] =
            pack2bf(x0 - __bfloat162float(b0), x1 - __bfloat162float(b1));
    }
    for (int i = tid; i < 64 * DIMh; i += 256) {
        const int kwb = i >> 6, d = i & 63;
        float x0 = bV[base + (2 * kwb) * 64 + d]     * inv[2 * kwb];
        float x1 = bV[base + (2 * kwb + 1) * 64 + d] * inv[2 * kwb + 1];
        __nv_bfloat16 b0 = __float2bfloat16_rn(x0);
        __nv_bfloat16 b1 = __float2bfloat16_rn(x1);
        Vp[0 * VPL + (size_t)bh * (64 * DIMh) + i] = pack2bf(x0, x1);
        Vp[1 * VPL + (size_t)bh * (64 * DIMh) + i] =
            pack2bf(x0 - __bfloat162float(b0), x1 - __bfloat162float(b1));
    }
}

// ================= MMA bucket attention =====================================
#define A2_QS0  0
#define A2_QS1  4352
#define A2_KS0  8704
#define A2_KS1  13056
#define A2_VS0  17408
#define A2_VS1  22016
#define A2_WORDS 26624
#define A2_SMEM  (A2_WORDS * 4)

__global__ void __launch_bounds__(256, 1)
attn2_kernel(const float* __restrict__ Q,
             const unsigned* __restrict__ Kp, const unsigned* __restrict__ Vp,
             float* __restrict__ outp)
{
    extern __shared__ float smf[];
    unsigned* smw = (unsigned*)smf;
    const int tid   = threadIdx.x;
    const int warp  = tid >> 5, lane = tid & 31;
    const int gid   = lane >> 2, tig = lane & 3;
    const int bh    = blockIdx.x >> 2;
    const int chunk = blockIdx.x & 3;
    const int b = bh >> 4, h = bh & 15;

    {
        const unsigned* kp0 = Kp + 0 * KPL + (size_t)bh * (32 * Sn);
        const unsigned* kp1 = Kp + 1 * KPL + (size_t)bh * (32 * Sn);
        for (int i = tid; i < 32 * Sn; i += 256) {
            const int kw = i >> 7, n = i & 127;
            smw[A2_KS0 + kw * 136 + n] = kp0[i];
            smw[A2_KS1 + kw * 136 + n] = kp1[i];
        }
        const unsigned* vp0 = Vp + 0 * VPL + (size_t)bh * (64 * DIMh);
        const unsigned* vp1 = Vp + 1 * VPL + (size_t)bh * (64 * DIMh);
        for (int i = tid; i < 64 * DIMh; i += 256) {
            const int kwb = i >> 6, n = i & 63;
            smw[A2_VS0 + kwb * 72 + n] = vp0[i];
            smw[A2_VS1 + kwb * 72 + n] = vp1[i];
        }
    }

    const int qm    = tid >> 1;
    const int qhalf = (tid & 1) * 32;

    for (int tile = 0; tile < 8; tile++) {
        const int t0 = chunk * 1024 + tile * 128;
        __syncthreads();

        {
            const float* qr = Q + ((size_t)(b * Tsz + t0 + qm)) * Dsz + h * DIMh + qhalf;
            #pragma unroll
            for (int j4 = 0; j4 < 8; j4++) {
                float4 qv = *(const float4*)(qr + j4 * 4);
                float qf[4] = {qv.x * 0.125f, qv.y * 0.125f, qv.z * 0.125f, qv.w * 0.125f};
                #pragma unroll
                for (int w = 0; w < 2; w++) {
                    const int kw = (qhalf >> 1) + j4 * 2 + w;
                    float x0 = qf[2 * w], x1 = qf[2 * w + 1];
                    __nv_bfloat16 b0 = __float2bfloat16_rn(x0);
                    __nv_bfloat16 b1 = __float2bfloat16_rn(x1);
                    smw[A2_QS0 + kw * 136 + qm] = pack2bf(x0, x1);
                    smw[A2_QS1 + kw * 136 + qm] =
                        pack2bf(x0 - __bfloat162float(b0), x1 - __bfloat162float(b1));
                }
            }
        }
        __syncthreads();

        float c[16][4];
        #pragma unroll
        for (int i = 0; i < 16; i++)
            #pragma unroll
            for (int j = 0; j < 4; j++) c[i][j] = 0.f;

        #pragma unroll
        for (int ks = 0; ks < 4; ks++) {
            const int r0 = ks * 8 + tig, r1 = ks * 8 + tig + 4;
            const int mb = warp * 16 + gid;
            unsigned aq0[4], aq1[4];
            aq0[0] = smw[A2_QS0 + r0 * 136 + mb]; aq0[1] = smw[A2_QS0 + r0 * 136 + mb + 8];
            aq0[2] = smw[A2_QS0 + r1 * 136 + mb]; aq0[3] = smw[A2_QS0 + r1 * 136 + mb + 8];
            aq1[0] = smw[A2_QS1 + r0 * 136 + mb]; aq1[1] = smw[A2_QS1 + r0 * 136 + mb + 8];
            aq1[2] = smw[A2_QS1 + r1 * 136 + mb]; aq1[3] = smw[A2_QS1 + r1 * 136 + mb + 8];
            #pragma unroll
            for (int nt = 0; nt < 16; nt++) {
                const int nb = nt * 8 + gid;
                unsigned bk0[2], bk1[2];
                bk0[0] = smw[A2_KS0 + r0 * 136 + nb]; bk0[1] = smw[A2_KS0 + r1 * 136 + nb];
                bk1[0] = smw[A2_KS1 + r0 * 136 + nb]; bk1[1] = smw[A2_KS1 + r1 * 136 + nb];
                mma_bf16(c[nt], aq0, bk0);
                mma_bf16(c[nt], aq0, bk1);
                mma_bf16(c[nt], aq1, bk0);
            }
        }

        float mx0 = -1e30f, mx1 = -1e30f;
        #pragma unroll
        for (int nt = 0; nt < 16; nt++) {
            mx0 = fmaxf(mx0, fmaxf(c[nt][0], c[nt][1]));
            mx1 = fmaxf(mx1, fmaxf(c[nt][2], c[nt][3]));
        }
        #pragma unroll
        for (int o = 1; o < 4; o <<= 1) {
            mx0 = fmaxf(mx0, __shfl_xor_sync(0xffffffffu, mx0, o));
            mx1 = fmaxf(mx1, __shfl_xor_sync(0xffffffffu, mx1, o));
        }
        float z0 = 0.f, z1 = 0.f;
        #pragma unroll
        for (int nt = 0; nt < 16; nt++) {
            c[nt][0] = expf(c[nt][0] - mx0); z0 += c[nt][0];
            c[nt][1] = expf(c[nt][1] - mx0); z0 += c[nt][1];
            c[nt][2] = expf(c[nt][2] - mx1); z1 += c[nt][2];
            c[nt][3] = expf(c[nt][3] - mx1); z1 += c[nt][3];
        }
        #pragma unroll
        for (int o = 1; o < 4; o <<= 1) {
            z0 += __shfl_xor_sync(0xffffffffu, z0, o);
            z1 += __shfl_xor_sync(0xffffffffu, z1, o);
        }
        const float rz0 = 1.0f / z0, rz1 = 1.0f / z1;

        float o[8][4];
        #pragma unroll
        for (int i = 0; i < 8; i++)
            #pragma unroll
            for (int j = 0; j < 4; j++) o[i][j] = 0.f;

        #pragma unroll
        for (int ki = 0; ki < 8; ki++) {
            unsigned e0[4], e1[4];
            #pragma unroll
            for (int half = 0; half < 2; half++) {
                const float* cc0 = c[2 * ki + half];
                __nv_bfloat16 p00 = __float2bfloat16_rn(cc0[0]);
                __nv_bfloat16 p01 = __float2bfloat16_rn(cc0[1]);
                __nv_bfloat16 p10 = __float2bfloat16_rn(cc0[2]);
                __nv_bfloat16 p11 = __float2bfloat16_rn(cc0[3]);
                e0[half * 2 + 0] = (unsigned)__bfloat16_as_ushort(p00) |
                                   ((unsigned)__bfloat16_as_ushort(p01) << 16);
                e0[half * 2 + 1] = (unsigned)__bfloat16_as_ushort(p10) |
                                   ((unsigned)__bfloat16_as_ushort(p11) << 16);
                e1[half * 2 + 0] = pack2bf(cc0[0] - __bfloat162float(p00),
                                           cc0[1] - __bfloat162float(p01));
                e1[half * 2 + 1] = pack2bf(cc0[2] - __bfloat162float(p10),
                                           cc0[3] - __bfloat162float(p11));
            }
            #pragma unroll
            for (int nt = 0; nt < 8; nt++) {
                const int nb = nt * 8 + gid;
                const int r0 = ki * 8 + tig, r1 = ki * 8 + tig + 4;
                unsigned bv0[2], bv1[2];
                bv0[0] = smw[A2_VS0 + r0 * 72 + nb]; bv0[1] = smw[A2_VS0 + r1 * 72 + nb];
                bv1[0] = smw[A2_VS1 + r0 * 72 + nb]; bv1[1] = smw[A2_VS1 + r1 * 72 + nb];
                mma_bf16(o[nt], e0, bv0);
                mma_bf16(o[nt], e0, bv1);
                mma_bf16(o[nt], e1, bv0);
            }
        }

        {
            const int row0 = t0 + warp * 16 + gid;
            float* out0 = outp + ((size_t)(b * Tsz + row0)) * Dsz + h * DIMh;
            float* out1 = out0 + (size_t)8 * Dsz;
            #pragma unroll
            for (int nt = 0; nt < 8; nt++) {
                const int d = nt * 8 + tig * 2;
                float2 v0 = make_float2(o[nt][0] * rz0, o[nt][1] * rz0);
                float2 v1 = make_float2(o[nt][2] * rz1, o[nt][3] * rz1);
                *(float2*)(out0 + d) = v0;
                *(float2*)(out1 + d) = v1;
            }
        }
    }
}

// ---------------- launch ----------------------------------------------------
extern "C" void kernel_launch(void* const* d_in, const int* in_sizes, int n_in,
                              void* d_out, int out_size)
{
    const float* x      = (const float*)d_in[0];
    const float* mask   = (const float*)d_in[1];
    const float* Wq     = (const float*)d_in[2];
    const float* Wk     = (const float*)d_in[3];
    const float* Wv     = (const float*)d_in[4];
    const float* Wout   = (const float*)d_in[5];
    const float* b_out  = (const float*)d_in[6];
    const float* planes = (const float*)d_in[7];
    const float* protos = (const float*)d_in[8];
    const float* ltemp  = (const float*)d_in[9];
    float* out = (float*)d_out;

    void *pQ, *pK, *pV, *pATT, *pbK, *pbV, *pbA, *pxp, *pattp, *pwp, *pnK, *pnV;
    cudaGetSymbolAddress(&pQ,  g_Q);
    cudaGetSymbolAddress(&pK,  g_K);
    cudaGetSymbolAddress(&pV,  g_V);
    cudaGetSymbolAddress(&pATT,g_ATT);
    cudaGetSymbolAddress(&pbK, g_bK);
    cudaGetSymbolAddress(&pbV, g_bV);
    cudaGetSymbolAddress(&pbA, g_bA);
    cudaGetSymbolAddress(&pxp,  g_xp);
    cudaGetSymbolAddress(&pattp,g_attp);
    cudaGetSymbolAddress(&pwp,  g_wp);
    cudaGetSymbolAddress(&pnK,  g_nK);
    cudaGetSymbolAddress(&pnV,  g_nV);
    unsigned* xp   = (unsigned*)pxp;
    unsigned* attp = (unsigned*)pattp;
    unsigned* wp   = (unsigned*)pwp;

    const int GS23 = 66048;    // max(4-stage x2 pipeline 65536, epilogue 66044)
    const int GS36 = 98304;    // 4-stage x3 pipeline
    cudaFuncSetAttribute(pk_gemm<2,3>, cudaFuncAttributeMaxDynamicSharedMemorySize, GS23);
    cudaFuncSetAttribute(pk_gemm<3,6>, cudaFuncAttributeMaxDynamicSharedMemorySize, GS36);
    cudaFuncSetAttribute(route2_kernel, cudaFuncAttributeMaxDynamicSharedMemorySize, RT2_SMEM);
    cudaFuncSetAttribute(attn2_kernel,  cudaFuncAttributeMaxDynamicSharedMemorySize, A2_SMEM);

    dim3 gblk(256);
    dim3 ggrid(Dsz / 128, BT / 128);       // (8, 128)
    dim3 apgrid(BT / 64, Dsz / 32);        // (256, 32)

    zero_buckets<<<256, 256>>>((float*)pbK, (float*)pbV, (float*)pbA);

    apackT<3><<<apgrid, 256>>>(x, xp);
    bpack<2><<<1024, 256>>>(Wq,   wp + 0 * BPL);
    bpack<3><<<1024, 256>>>(Wk,   wp + 2 * BPL);
    bpack<2><<<1024, 256>>>(Wv,   wp + 5 * BPL);
    bpack<2><<<1024, 256>>>(Wout, wp + 7 * BPL);

    pk_gemm<2,3><<<ggrid, gblk, GS23>>>(xp, wp + 0 * BPL, (float*)pQ, mask, nullptr);
    pk_gemm<3,6><<<ggrid, gblk, GS36>>>(xp, wp + 2 * BPL, (float*)pK, mask, nullptr);
    pk_gemm<2,3><<<ggrid, gblk, GS23>>>(xp, wp + 5 * BPL, (float*)pV, mask, nullptr);

    route2_kernel<<<BHn * RT_NCHUNK, 256, RT2_SMEM>>>(
        (const float*)pK, (const float*)pV, planes, protos, ltemp,
        (float*)pbK, (float*)pbV, (float*)pbA);

    bnorm_kernel<<<BHn, 256>>>((const float*)pbK, (const float*)pbV,
                               (const float*)pbA,
                               (unsigned*)pnK, (unsigned*)pnV);

    attn2_kernel<<<BHn * 4, 256, A2_SMEM>>>(
        (const float*)pQ, (const unsigned*)pnK, (const unsigned*)pnV,
        (float*)pATT);

    apackT<2><<<apgrid, 256>>>((const float*)pATT, attp);
    pk_gemm<2,3><<<ggrid, gblk, GS23>>>(attp, wp + 7 * BPL, out, nullptr, b_out);
}

// round 15
// speedup vs baseline: 1.5775x; 1.0067x over previous
#include <cuda_runtime.h>
#include <cuda_bf16.h>
#include <math.h>

// Problem constants
#define Bsz  4
#define Tsz  4096
#define Dsz  1024
#define Hn   16
#define DIMh 64
#define Ln   8
#define KBn  4
#define Rn   16
#define Sn   128
#define BT   (Bsz*Tsz)      // 16384
#define BHn  (Bsz*Hn)       // 64

// ---------------- scratch (device globals: no allocation allowed) ----------
__device__ float g_Q  [(size_t)BT*Dsz];
__device__ float g_K  [(size_t)BT*Dsz];
__device__ float g_V  [(size_t)BT*Dsz];
__device__ float g_ATT[(size_t)BT*Dsz];
__device__ float g_bK [(size_t)BHn*Sn*DIMh];
__device__ float g_bV [(size_t)BHn*Sn*DIMh];
__device__ float g_bA [(size_t)BHn*Sn];

// packed bf16x2 split planes, FRAGMENT-NATIVE layout:
// A plane word addr = (kchunk*8192 + mf)*16 + tig*4 + slot   (mf=(m>>4)*8+(m&7))
// B plane word addr = (kchunk*1024 + n)*8  + tig*2 + slot
#define APL ((size_t)512*16384)     // words per activation plane
#define BPL ((size_t)512*1024)      // words per weight plane
__device__ unsigned g_xp  [3*APL];
__device__ unsigned g_attp[2*APL];
__device__ unsigned g_wp  [9*BPL];  // Wq(2) Wk(3) Wv(2) Wout(2)

// normalized bucket split planes
#define KPL ((size_t)BHn*32*Sn)
#define VPL ((size_t)BHn*64*DIMh)
__device__ unsigned g_nK[2*KPL];
__device__ unsigned g_nV[2*VPL];

// ======================= helpers ============================================
__device__ __forceinline__ unsigned smem_u32(const void* p) {
    unsigned a;
    asm("{ .reg .u64 t; cvta.to.shared.u64 t, %1; cvt.u32.u64 %0, t; }"
        : "=r"(a) : "l"(p));
    return a;
}

__device__ __forceinline__ void mma_bf16(float c[4], const unsigned a[4],
                                         const unsigned b[2]) {
    asm volatile(
        "mma.sync.aligned.m16n8k16.row.col.f32.bf16.bf16.f32 "
        "{%0,%1,%2,%3}, {%4,%5,%6,%7}, {%8,%9}, {%0,%1,%2,%3};"
        : "+f"(c[0]), "+f"(c[1]), "+f"(c[2]), "+f"(c[3])
        : "r"(a[0]), "r"(a[1]), "r"(a[2]), "r"(a[3]), "r"(b[0]), "r"(b[1]));
}

__device__ __forceinline__ void cpasync16(unsigned saddr, const void* gptr) {
    asm volatile("cp.async.cg.shared.global [%0], [%1], 16;"
                 :: "r"(saddr), "l"(gptr));
}

__device__ __forceinline__ unsigned pack2bf(float x0, float x1) {
    __nv_bfloat16 b0 = __float2bfloat16_rn(x0);
    __nv_bfloat16 b1 = __float2bfloat16_rn(x1);
    return (unsigned)__bfloat16_as_ushort(b0) |
           ((unsigned)__bfloat16_as_ushort(b1) << 16);
}

// ================= pack kernels (one-shot, fragment-native) =================
template<int NS>
__global__ void __launch_bounds__(256)
apackT(const float* __restrict__ X, unsigned* __restrict__ out)
{
    __shared__ float tile[64][36];   // 144 B stride (16B-aligned)
    const int tid = threadIdx.x;
    const int m0 = blockIdx.x * 64, k0 = blockIdx.y * 32;

    #pragma unroll
    for (int j = 0; j < 2; j++) {
        const int flat = tid + j * 256;
        const int row = flat >> 3, c4 = (flat & 7) * 4;
        *(float4*)&tile[row][c4] =
            *(const float4*)(X + (size_t)(m0 + row) * 1024 + k0 + c4);
    }
    __syncthreads();

    const int ic   = tid >> 7;
    const int rem  = tid & 127;
    const int tigf = rem & 3;
    const int mfl  = rem >> 2;
    const int ml   = ((mfl >> 3) << 4) | (mfl & 7);
    const int kb   = ic * 16 + tigf * 2;

    float f[8];
    f[0] = tile[ml][kb];         f[1] = tile[ml][kb + 1];
    f[2] = tile[ml + 8][kb];     f[3] = tile[ml + 8][kb + 1];
    f[4] = tile[ml][kb + 8];     f[5] = tile[ml][kb + 9];
    f[6] = tile[ml + 8][kb + 8]; f[7] = tile[ml + 8][kb + 9];

    const size_t frag = (size_t)((k0 >> 4) + ic) * 8192 + (m0 >> 1) + mfl;
    uint4* o4 = (uint4*)out;
    #pragma unroll
    for (int s = 0; s < NS; s++) {
        uint4 v;
        unsigned* vw = (unsigned*)&v;
        #pragma unroll
        for (int w = 0; w < 4; w++) {
            __nv_bfloat16 b0 = __float2bfloat16_rn(f[2 * w]);
            __nv_bfloat16 b1 = __float2bfloat16_rn(f[2 * w + 1]);
            vw[w] = (unsigned)__bfloat16_as_ushort(b0) |
                    ((unsigned)__bfloat16_as_ushort(b1) << 16);
            f[2 * w]     -= __bfloat162float(b0);
            f[2 * w + 1] -= __bfloat162float(b1);
        }
        o4[s * (APL >> 2) + frag * 4 + tigf] = v;
    }
}

template<int NS>
__global__ void __launch_bounds__(256)
bpack(const float* __restrict__ W, unsigned* __restrict__ out)
{
    const int gidx = blockIdx.x * 256 + threadIdx.x;
    const int tigf = gidx & 3;
    const int n    = (gidx >> 2) & 1023;
    const int i    = gidx >> 12;
    const int kbase = i * 16 + tigf * 2;

    float f[4];
    f[0] = W[(size_t)(kbase)     * 1024 + n];
    f[1] = W[(size_t)(kbase + 1) * 1024 + n];
    f[2] = W[(size_t)(kbase + 8) * 1024 + n];
    f[3] = W[(size_t)(kbase + 9) * 1024 + n];

    uint2* o2 = (uint2*)out;
    #pragma unroll
    for (int s = 0; s < NS; s++) {
        uint2 v;
        __nv_bfloat16 a0 = __float2bfloat16_rn(f[0]);
        __nv_bfloat16 a1 = __float2bfloat16_rn(f[1]);
        __nv_bfloat16 a2 = __float2bfloat16_rn(f[2]);
        __nv_bfloat16 a3 = __float2bfloat16_rn(f[3]);
        v.x = (unsigned)__bfloat16_as_ushort(a0) |
              ((unsigned)__bfloat16_as_ushort(a1) << 16);
        v.y = (unsigned)__bfloat16_as_ushort(a2) |
              ((unsigned)__bfloat16_as_ushort(a3) << 16);
        f[0] -= __bfloat162float(a0); f[1] -= __bfloat162float(a1);
        f[2] -= __bfloat162float(a2); f[3] -= __bfloat162float(a3);
        o2[s * (BPL >> 1) + (size_t)(i * 1024 + n) * 4 + tigf] = v;
    }
}

// ================= packed-input bf16 split GEMM (single-sync pipeline) ======
template<int NSPLIT, int NPASS>
__global__ void __launch_bounds__(256, 2)
pk_gemm(const unsigned* __restrict__ Ap, const unsigned* __restrict__ Bp,
        float* __restrict__ C,
        const float* __restrict__ rowscale, const float* __restrict__ bias)
{
    extern __shared__ float sm[];
    unsigned* smu = (unsigned*)sm;
    const unsigned sbase = smem_u32(smu);
    const int tid  = threadIdx.x;
    const int warp = tid >> 5, lane = tid & 31;
    const int wm = warp >> 2, wn = warp & 3;
    const int gid = lane >> 2, tig = lane & 3;
    const int m0 = blockIdx.y * 128, n0 = blockIdx.x * 128;

    constexpr int BUF = NSPLIT * 2048;     // words per stage
    constexpr int PA[6] = {0, 0, 1, 0, 2, 1};
    constexpr int PB[6] = {0, 1, 0, 2, 0, 1};

    float cacc[16][4];
    #pragma unroll
    for (int i = 0; i < 16; i++)
        #pragma unroll
        for (int j = 0; j < 4; j++) cacc[i][j] = 0.f;

    const size_t aoff0 = (size_t)m0 * 8 + tid * 4;
    const size_t boff0 = (size_t)n0 * 8 + tid * 4;

    auto issue = [&](int i, int stg) {
        const unsigned sb = sbase + (unsigned)(stg * BUF) * 4;
        #pragma unroll
        for (int s = 0; s < NSPLIT; s++) {
            cpasync16(sb + (unsigned)(s * 1024 + tid * 4) * 4,
                      Ap + s * APL + (size_t)i * 131072 + aoff0);
            cpasync16(sb + (unsigned)((NSPLIT + s) * 1024 + tid * 4) * 4,
                      Bp + s * BPL + (size_t)i * 8192 + boff0);
        }
        asm volatile("cp.async.commit_group;");
    };

    issue(0, 0); issue(1, 1); issue(2, 2);

    for (int i = 0; i < 64; i++) {
        const int stg = i & 3;
        // canonical single-sync pipeline:
        // wait own groups (stage i done), sync (all threads' stage-i data
        // visible AND compute(i-1) retired), then refill stage (i+3)&3.
        if (i < 62)       asm volatile("cp.async.wait_group 2;");
        else if (i == 62) asm volatile("cp.async.wait_group 1;");
        else              asm volatile("cp.async.wait_group 0;");
        __syncthreads();
        if (i + 3 < 64) issue(i + 3, (i + 3) & 3);

        const unsigned base = (unsigned)(stg * BUF);
        #pragma unroll
        for (int p = 0; p < NPASS; p++) {
            const uint4* As4 = (const uint4*)(smu + base + PA[p] * 1024);
            const uint2* Bs2 = (const uint2*)(smu + base + (NSPLIT + PB[p]) * 1024);
            uint4 af[4];
            #pragma unroll
            for (int mt = 0; mt < 4; mt++)
                af[mt] = As4[((wm * 4 + mt) * 8 + gid) * 4 + tig];
            uint2 bfr[4];
            #pragma unroll
            for (int nt = 0; nt < 4; nt++)
                bfr[nt] = Bs2[(wn * 32 + nt * 8 + gid) * 4 + tig];
            #pragma unroll
            for (int mt = 0; mt < 4; mt++)
                #pragma unroll
                for (int nt = 0; nt < 4; nt++)
                    mma_bf16(cacc[mt * 4 + nt],
                             (const unsigned*)&af[mt],
                             (const unsigned*)&bfr[nt]);
        }
    }
    __syncthreads();   // all MMAs done before epilogue reuses smem

    // ---- epilogue: stage C to smem, then coalesced writeout ----
    float* st = sm;
    #pragma unroll
    for (int mt = 0; mt < 4; mt++) {
        #pragma unroll
        for (int nt = 0; nt < 4; nt++) {
            const float* c = cacc[mt * 4 + nt];
            const int r  = wm * 64 + mt * 16 + gid;
            const int cc = wn * 32 + nt * 8 + (tig << 1);
            st[r * 129 + cc]           = c[0];
            st[r * 129 + cc + 1]       = c[1];
            st[(r + 8) * 129 + cc]     = c[2];
            st[(r + 8) * 129 + cc + 1] = c[3];
        }
    }
    __syncthreads();
    #pragma unroll 4
    for (int it = 0; it < 64; it++) {
        const int flat = tid + it * 256;
        const int rr = flat >> 7, cc = flat & 127;
        float v = st[rr * 129 + cc];
        if (rowscale) v *= rowscale[m0 + rr];
        if (bias)     v += bias[n0 + cc];
        C[(size_t)(m0 + rr) * 1024 + n0 + cc] = v;
    }
}

// ---------------- zero bucket accumulators ---------------------------------
__global__ void zero_buckets(float* __restrict__ bK, float* __restrict__ bV,
                             float* __restrict__ bA)
{
    int n = BHn * Sn * DIMh;
    for (int i = blockIdx.x * blockDim.x + threadIdx.x; i < n;
         i += gridDim.x * blockDim.x) { bK[i] = 0.f; bV[i] = 0.f; }
    int na = BHn * Sn;
    for (int i = blockIdx.x * blockDim.x + threadIdx.x; i < na;
         i += gridDim.x * blockDim.x) bA[i] = 0.f;
}

// ================= routing + bucket accumulation via MMA ====================
#define RT_CHUNK   512
#define RT_NCHUNK  (Tsz / RT_CHUNK)   // 8
#define RT_NTILE   (RT_CHUNK / 64)    // 8

#define OFF_SW    0
#define OFF_SIDX  8192
#define OFF_SA    10240
#define OFF_SPL   10368
#define OFF_SPR   12416
#define OFF_ASG0  12480
#define OFF_ASG1  16832
#define OFF_KT0   21184
#define OFF_KT1   23488
#define OFF_VT0   25792
#define OFF_VT1   28096
#define RT2_WORDS 30400
#define RT2_SMEM  (RT2_WORDS * 4)

__global__ void __launch_bounds__(256, 1)
route2_kernel(const float* __restrict__ K, const float* __restrict__ V,
              const float* __restrict__ planes_T,
              const float* __restrict__ protos_T,
              const float* __restrict__ ltemp,
              float* __restrict__ bK, float* __restrict__ bV,
              float* __restrict__ bA)
{
    extern __shared__ float smf[];
    unsigned* smw = (unsigned*)smf;
    unsigned char* sidxb = (unsigned char*)(smw + OFF_SIDX);
    unsigned* sw = smw + OFF_SW;
    float* sA  = smf + OFF_SA;
    float* spl = smf + OFF_SPL;
    float* spr = smf + OFF_SPR;

    const int tid   = threadIdx.x;
    const int warp  = tid >> 5, lane = tid & 31;
    const int gid   = lane >> 2, tig = lane & 3;
    const int bh    = blockIdx.x >> 3;
    const int chunk = blockIdx.x & 7;
    const int b = bh >> 4, h = bh & 15;

    for (int i = tid; i < Sn; i += 256) sA[i] = 0.f;
    for (int i = tid; i < DIMh * 32; i += 256) spl[i] = planes_T[i];
    for (int i = tid; i < KBn * Rn; i += 256) spr[i] = protos_T[i];
    __syncthreads();

    float scale = expf(ltemp[0]);
    scale = fminf(fmaxf(scale, 0.01f), 20.0f);
    const float inv_scale = 1.0f / scale;

    // ---------- Phase A: routing for 512 tokens ----------
    for (int tt = 0; tt < 2; tt++) {
        const int tl = tt * 256 + tid;
        const int t  = chunk * RT_CHUNK + tl;
        const float* krow = K + ((size_t)(b * Tsz + t)) * Dsz + h * DIMh;

        float proj[32];
        #pragma unroll
        for (int p = 0; p < 32; p++) proj[p] = 0.f;
        #pragma unroll 4
        for (int d = 0; d < DIMh; d++) {
            float kd = krow[d];
            #pragma unroll
            for (int p = 0; p < 32; p++) proj[p] += kd * spl[d * 32 + p];
        }
        #pragma unroll
        for (int p = 0; p < 32; p++) proj[p] = tanhf(proj[p]) * inv_scale;

        #pragma unroll
        for (int l = 0; l < Ln; l++) {
            float e[16];
            float mx = -1e30f;
            #pragma unroll
            for (int r = 0; r < Rn; r++) {
                float lg = proj[l*4+0] * spr[0*Rn + r] + proj[l*4+1] * spr[1*Rn + r]
                         + proj[l*4+2] * spr[2*Rn + r] + proj[l*4+3] * spr[3*Rn + r];
                e[r] = lg;
                mx = fmaxf(mx, lg);
            }
            float Z = 0.f;
            #pragma unroll
            for (int r = 0; r < Rn; r++) { e[r] = expf(e[r] - mx); Z += e[r]; }
            int i1 = 0; float b1 = e[0];
            #pragma unroll
            for (int r = 1; r < Rn; r++) if (e[r] > b1) { b1 = e[r]; i1 = r; }
            int i2 = -1; float b2 = -1.f;
            #pragma unroll
            for (int r = 0; r < Rn; r++) if (r != i1 && e[r] > b2) { b2 = e[r]; i2 = r; }
            const float denom = 1.0f / (b1 + b2 + 1e-6f * Z);
            const float w1f = b1 * denom, w2f = b2 * denom;

            __nv_bfloat16 w10 = __float2bfloat16_rn(w1f);
            __nv_bfloat16 w11 = __float2bfloat16_rn(w1f - __bfloat162float(w10));
            __nv_bfloat16 w20 = __float2bfloat16_rn(w2f);
            __nv_bfloat16 w21 = __float2bfloat16_rn(w2f - __bfloat162float(w20));

            const int s1 = l * Rn + i1, s2 = l * Rn + i2;
            sidxb[tl * 16 + l * 2]     = (unsigned char)s1;
            sidxb[tl * 16 + l * 2 + 1] = (unsigned char)s2;
            sw[tl * 16 + l * 2] =
                (unsigned)__bfloat16_as_ushort(w10) |
                ((unsigned)__bfloat16_as_ushort(w11) << 16);
            sw[tl * 16 + l * 2 + 1] =
                (unsigned)__bfloat16_as_ushort(w20) |
                ((unsigned)__bfloat16_as_ushort(w21) << 16);
            atomicAdd(&sA[s1], w1f);
            atomicAdd(&sA[s2], w2f);
        }
    }
    __syncthreads();
    if (tid < Sn) atomicAdd(&bA[(size_t)bh * Sn + tid], sA[tid]);

    // ---------- Phase B: MMA bucketing ----------
    float acc[16][4];
    #pragma unroll
    for (int i = 0; i < 16; i++)
        #pragma unroll
        for (int j = 0; j < 4; j++) acc[i][j] = 0.f;

    const int tok  = tid >> 2;
    const int dqq  = (tid & 3) * 16;
    const int tp_w = tok >> 1, half_w = tok & 1;

    for (int tile = 0; tile < RT_NTILE; tile++) {
        __syncthreads();   // prior MMA done: ASG + KT/VT free

        // zero assign tiles AND load K/V tile (disjoint smem regions)
        {
            uint4 z = make_uint4(0u, 0u, 0u, 0u);
            uint4* a0 = (uint4*)(smw + OFF_ASG0);
            uint4* a1 = (uint4*)(smw + OFF_ASG1);
            for (int i = tid; i < 1088; i += 256) { a0[i] = z; a1[i] = z; }

            const int tglob = chunk * RT_CHUNK + tile * 64 + tok;
            const float* kr = K + ((size_t)(b * Tsz + tglob)) * Dsz + h * DIMh;
            const float* vr = V + ((size_t)(b * Tsz + tglob)) * Dsz + h * DIMh;
            unsigned short* k0h = (unsigned short*)(smw + OFF_KT0);
            unsigned short* k1h = (unsigned short*)(smw + OFF_KT1);
            unsigned short* v0h = (unsigned short*)(smw + OFF_VT0);
            unsigned short* v1h = (unsigned short*)(smw + OFF_VT1);
            #pragma unroll
            for (int i4 = 0; i4 < 4; i4++) {
                float4 kv = *(const float4*)(kr + dqq + i4 * 4);
                float4 vv = *(const float4*)(vr + dqq + i4 * 4);
                float kf[4] = {kv.x, kv.y, kv.z, kv.w};
                float vf[4] = {vv.x, vv.y, vv.z, vv.w};
                #pragma unroll
                for (int e = 0; e < 4; e++) {
                    const int d = dqq + i4 * 4 + e;
                    const int widx = (tp_w * 72 + d) * 2 + half_w;
                    __nv_bfloat16 k0 = __float2bfloat16_rn(kf[e]);
                    __nv_bfloat16 k1 = __float2bfloat16_rn(kf[e] - __bfloat162float(k0));
                    __nv_bfloat16 v0 = __float2bfloat16_rn(vf[e]);
                    __nv_bfloat16 v1 = __float2bfloat16_rn(vf[e] - __bfloat162float(v0));
                    k0h[widx] = __bfloat16_as_ushort(k0);
                    k1h[widx] = __bfloat16_as_ushort(k1);
                    v0h[widx] = __bfloat16_as_ushort(v0);
                    v1h[widx] = __bfloat16_as_ushort(v1);
                }
            }
        }
        __syncthreads();   // zero complete before scatter

        {
            unsigned short* a0h = (unsigned short*)(smw + OFF_ASG0);
            unsigned short* a1h = (unsigned short*)(smw + OFF_ASG1);
            #pragma unroll
            for (int it = 0; it < 4; it++) {
                const int e  = tid + it * 256;
                const int tl = tile * 64 + (e >> 4);
                const int j  = e & 15;
                const int s  = sidxb[tl * 16 + j];
                const unsigned wp = sw[tl * 16 + j];
                const int tt2 = e >> 4;
                const int widx = ((tt2 >> 1) * 136 + s) * 2 + (tt2 & 1);
                a0h[widx] = (unsigned short)(wp & 0xffffu);
                a1h[widx] = (unsigned short)(wp >> 16);
            }
        }
        __syncthreads();   // scatter complete before MMA

        const unsigned* asg0 = smw + OFF_ASG0;
        const unsigned* asg1 = smw + OFF_ASG1;
        const unsigned* kt0  = smw + OFF_KT0;
        const unsigned* kt1  = smw + OFF_KT1;
        const unsigned* vt0  = smw + OFF_VT0;
        const unsigned* vt1  = smw + OFF_VT1;
        #pragma unroll
        for (int ks = 0; ks < 4; ks++) {
            const int r0 = ks * 8 + tig, r1 = ks * 8 + tig + 4;
            const int mb = warp * 16 + gid;
            unsigned a0f[4], a1f[4];
            a0f[0] = asg0[r0 * 136 + mb]; a0f[1] = asg0[r0 * 136 + mb + 8];
            a0f[2] = asg0[r1 * 136 + mb]; a0f[3] = asg0[r1 * 136 + mb + 8];
            a1f[0] = asg1[r0 * 136 + mb]; a1f[1] = asg1[r0 * 136 + mb + 8];
            a1f[2] = asg1[r1 * 136 + mb]; a1f[3] = asg1[r1 * 136 + mb + 8];
            #pragma unroll
            for (int nt = 0; nt < 8; nt++) {
                const int nb = nt * 8 + gid;
                unsigned bk0[2], bk1[2], bv0[2], bv1[2];
                bk0[0] = kt0[r0 * 72 + nb]; bk0[1] = kt0[r1 * 72 + nb];
                bk1[0] = kt1[r0 * 72 + nb]; bk1[1] = kt1[r1 * 72 + nb];
                bv0[0] = vt0[r0 * 72 + nb]; bv0[1] = vt0[r1 * 72 + nb];
                bv1[0] = vt1[r0 * 72 + nb]; bv1[1] = vt1[r1 * 72 + nb];
                mma_bf16(acc[nt], a0f, bk0);
                mma_bf16(acc[nt], a0f, bk1);
                mma_bf16(acc[nt], a1f, bk0);
                mma_bf16(acc[8 + nt], a0f, bv0);
                mma_bf16(acc[8 + nt], a0f, bv1);
                mma_bf16(acc[8 + nt], a1f, bv0);
            }
        }
    }

    {
        const size_t base = (size_t)bh * Sn * DIMh;
        const int s0 = warp * 16 + gid, s1 = s0 + 8;
        #pragma unroll
        for (int nt = 0; nt < 8; nt++) {
            const int d = nt * 8 + tig * 2;
            atomicAdd(&bK[base + s0 * 64 + d],     acc[nt][0]);
            atomicAdd(&bK[base + s0 * 64 + d + 1], acc[nt][1]);
            atomicAdd(&bK[base + s1 * 64 + d],     acc[nt][2]);
            atomicAdd(&bK[base + s1 * 64 + d + 1], acc[nt][3]);
            atomicAdd(&bV[base + s0 * 64 + d],     acc[8 + nt][0]);
            atomicAdd(&bV[base + s0 * 64 + d + 1], acc[8 + nt][1]);
            atomicAdd(&bV[base + s1 * 64 + d],     acc[8 + nt][2]);
            atomicAdd(&bV[base + s1 * 64 + d + 1], acc[8 + nt][3]);
        }
    }
}

// ============ normalize buckets + split-pack for MMA attention ==============
__global__ void __launch_bounds__(256)
bnorm_kernel(const float* __restrict__ bK, const float* __restrict__ bV,
             const float* __restrict__ bA,
             unsigned* __restrict__ Kp, unsigned* __restrict__ Vp)
{
    __shared__ float inv[Sn];
    const int bh = blockIdx.x;
    const int tid = threadIdx.x;
    if (tid < Sn) inv[tid] = 1.0f / (bA[(size_t)bh * Sn + tid] + 1e-6f);
    __syncthreads();

    const size_t base = (size_t)bh * Sn * DIMh;
    for (int i = tid; i < 32 * Sn; i += 256) {
        const int kw = i >> 7, s = i & 127;
        float x0 = bK[base + s * 64 + 2 * kw]     * inv[s];
        float x1 = bK[base + s * 64 + 2 * kw + 1] * inv[s];
        __nv_bfloat16 b0 = __float2bfloat16_rn(x0);
        __nv_bfloat16 b1 = __float2bfloat16_rn(x1);
        Kp[0 * KPL + (size_t)bh * (32 * Sn) + i] = pack2bf(x0, x1);
        Kp[1 * KPL + (size_t)bh * (32 * Sn) + i] =
            pack2bf(x0 - __bfloat162float(b0), x1 - __bfloat162float(b1));
    }
    for (int i = tid; i < 64 * DIMh; i += 256) {
        const int kwb = i >> 6, d = i & 63;
        float x0 = bV[base + (2 * kwb) * 64 + d]     * inv[2 * kwb];
        float x1 = bV[base + (2 * kwb + 1) * 64 + d] * inv[2 * kwb + 1];
        __nv_bfloat16 b0 = __float2bfloat16_rn(x0);
        __nv_bfloat16 b1 = __float2bfloat16_rn(x1);
        Vp[0 * VPL + (size_t)bh * (64 * DIMh) + i] = pack2bf(x0, x1);
        Vp[1 * VPL + (size_t)bh * (64 * DIMh) + i] =
            pack2bf(x0 - __bfloat162float(b0), x1 - __bfloat162float(b1));
    }
}

// ================= MMA bucket attention =====================================
#define A2_QS0  0
#define A2_QS1  4352
#define A2_KS0  8704
#define A2_KS1  13056
#define A2_VS0  17408
#define A2_VS1  22016
#define A2_WORDS 26624
#define A2_SMEM  (A2_WORDS * 4)

__global__ void __launch_bounds__(256, 1)
attn2_kernel(const float* __restrict__ Q,
             const unsigned* __restrict__ Kp, const unsigned* __restrict__ Vp,
             float* __restrict__ outp)
{
    extern __shared__ float smf[];
    unsigned* smw = (unsigned*)smf;
    const int tid   = threadIdx.x;
    const int warp  = tid >> 5, lane = tid & 31;
    const int gid   = lane >> 2, tig = lane & 3;
    const int bh    = blockIdx.x >> 2;
    const int chunk = blockIdx.x & 3;
    const int b = bh >> 4, h = bh & 15;

    {
        const unsigned* kp0 = Kp + 0 * KPL + (size_t)bh * (32 * Sn);
        const unsigned* kp1 = Kp + 1 * KPL + (size_t)bh * (32 * Sn);
        for (int i = tid; i < 32 * Sn; i += 256) {
            const int kw = i >> 7, n = i & 127;
            smw[A2_KS0 + kw * 136 + n] = kp0[i];
            smw[A2_KS1 + kw * 136 + n] = kp1[i];
        }
        const unsigned* vp0 = Vp + 0 * VPL + (size_t)bh * (64 * DIMh);
        const unsigned* vp1 = Vp + 1 * VPL + (size_t)bh * (64 * DIMh);
        for (int i = tid; i < 64 * DIMh; i += 256) {
            const int kwb = i >> 6, n = i & 63;
            smw[A2_VS0 + kwb * 72 + n] = vp0[i];
            smw[A2_VS1 + kwb * 72 + n] = vp1[i];
        }
    }

    const int qm    = tid >> 1;
    const int qhalf = (tid & 1) * 32;

    for (int tile = 0; tile < 8; tile++) {
        const int t0 = chunk * 1024 + tile * 128;
        __syncthreads();

        {
            const float* qr = Q + ((size_t)(b * Tsz + t0 + qm)) * Dsz + h * DIMh + qhalf;
            #pragma unroll
            for (int j4 = 0; j4 < 8; j4++) {
                float4 qv = *(const float4*)(qr + j4 * 4);
                float qf[4] = {qv.x * 0.125f, qv.y * 0.125f, qv.z * 0.125f, qv.w * 0.125f};
                #pragma unroll
                for (int w = 0; w < 2; w++) {
                    const int kw = (qhalf >> 1) + j4 * 2 + w;
                    float x0 = qf[2 * w], x1 = qf[2 * w + 1];
                    __nv_bfloat16 b0 = __float2bfloat16_rn(x0);
                    __nv_bfloat16 b1 = __float2bfloat16_rn(x1);
                    smw[A2_QS0 + kw * 136 + qm] = pack2bf(x0, x1);
                    smw[A2_QS1 + kw * 136 + qm] =
                        pack2bf(x0 - __bfloat162float(b0), x1 - __bfloat162float(b1));
                }
            }
        }
        __syncthreads();

        float c[16][4];
        #pragma unroll
        for (int i = 0; i < 16; i++)
            #pragma unroll
            for (int j = 0; j < 4; j++) c[i][j] = 0.f;

        #pragma unroll
        for (int ks = 0; ks < 4; ks++) {
            const int r0 = ks * 8 + tig, r1 = ks * 8 + tig + 4;
            const int mb = warp * 16 + gid;
            unsigned aq0[4], aq1[4];
            aq0[0] = smw[A2_QS0 + r0 * 136 + mb]; aq0[1] = smw[A2_QS0 + r0 * 136 + mb + 8];
            aq0[2] = smw[A2_QS0 + r1 * 136 + mb]; aq0[3] = smw[A2_QS0 + r1 * 136 + mb + 8];
            aq1[0] = smw[A2_QS1 + r0 * 136 + mb]; aq1[1] = smw[A2_QS1 + r0 * 136 + mb + 8];
            aq1[2] = smw[A2_QS1 + r1 * 136 + mb]; aq1[3] = smw[A2_QS1 + r1 * 136 + mb + 8];
            #pragma unroll
            for (int nt = 0; nt < 16; nt++) {
                const int nb = nt * 8 + gid;
                unsigned bk0[2], bk1[2];
                bk0[0] = smw[A2_KS0 + r0 * 136 + nb]; bk0[1] = smw[A2_KS0 + r1 * 136 + nb];
                bk1[0] = smw[A2_KS1 + r0 * 136 + nb]; bk1[1] = smw[A2_KS1 + r1 * 136 + nb];
                mma_bf16(c[nt], aq0, bk0);
                mma_bf16(c[nt], aq0, bk1);
                mma_bf16(c[nt], aq1, bk0);
            }
        }

        float mx0 = -1e30f, mx1 = -1e30f;
        #pragma unroll
        for (int nt = 0; nt < 16; nt++) {
            mx0 = fmaxf(mx0, fmaxf(c[nt][0], c[nt][1]));
            mx1 = fmaxf(mx1, fmaxf(c[nt][2], c[nt][3]));
        }
        #pragma unroll
        for (int o = 1; o < 4; o <<= 1) {
            mx0 = fmaxf(mx0, __shfl_xor_sync(0xffffffffu, mx0, o));
            mx1 = fmaxf(mx1, __shfl_xor_sync(0xffffffffu, mx1, o));
        }
        float z0 = 0.f, z1 = 0.f;
        #pragma unroll
        for (int nt = 0; nt < 16; nt++) {
            c[nt][0] = expf(c[nt][0] - mx0); z0 += c[nt][0];
            c[nt][1] = expf(c[nt][1] - mx0); z0 += c[nt][1];
            c[nt][2] = expf(c[nt][2] - mx1); z1 += c[nt][2];
            c[nt][3] = expf(c[nt][3] - mx1); z1 += c[nt][3];
        }
        #pragma unroll
        for (int o = 1; o < 4; o <<= 1) {
            z0 += __shfl_xor_sync(0xffffffffu, z0, o);
            z1 += __shfl_xor_sync(0xffffffffu, z1, o);
        }
        const float rz0 = 1.0f / z0, rz1 = 1.0f / z1;

        float o[8][4];
        #pragma unroll
        for (int i = 0; i < 8; i++)
            #pragma unroll
            for (int j = 0; j < 4; j++) o[i][j] = 0.f;

        #pragma unroll
        for (int ki = 0; ki < 8; ki++) {
            unsigned e0[4], e1[4];
            #pragma unroll
            for (int half = 0; half < 2; half++) {
                const float* cc0 = c[2 * ki + half];
                __nv_bfloat16 p00 = __float2bfloat16_rn(cc0[0]);
                __nv_bfloat16 p01 = __float2bfloat16_rn(cc0[1]);
                __nv_bfloat16 p10 = __float2bfloat16_rn(cc0[2]);
                __nv_bfloat16 p11 = __float2bfloat16_rn(cc0[3]);
                e0[half * 2 + 0] = (unsigned)__bfloat16_as_ushort(p00) |
                                   ((unsigned)__bfloat16_as_ushort(p01) << 16);
                e0[half * 2 + 1] = (unsigned)__bfloat16_as_ushort(p10) |
                                   ((unsigned)__bfloat16_as_ushort(p11) << 16);
                e1[half * 2 + 0] = pack2bf(cc0[0] - __bfloat162float(p00),
                                           cc0[1] - __bfloat162float(p01));
                e1[half * 2 + 1] = pack2bf(cc0[2] - __bfloat162float(p10),
                                           cc0[3] - __bfloat162float(p11));
            }
            #pragma unroll
            for (int nt = 0; nt < 8; nt++) {
                const int nb = nt * 8 + gid;
                const int r0 = ki * 8 + tig, r1 = ki * 8 + tig + 4;
                unsigned bv0[2], bv1[2];
                bv0[0] = smw[A2_VS0 + r0 * 72 + nb]; bv0[1] = smw[A2_VS0 + r1 * 72 + nb];
                bv1[0] = smw[A2_VS1 + r0 * 72 + nb]; bv1[1] = smw[A2_VS1 + r1 * 72 + nb];
                mma_bf16(o[nt], e0, bv0);
                mma_bf16(o[nt], e0, bv1);
                mma_bf16(o[nt], e1, bv0);
            }
        }

        {
            const int row0 = t0 + warp * 16 + gid;
            float* out0 = outp + ((size_t)(b * Tsz + row0)) * Dsz + h * DIMh;
            float* out1 = out0 + (size_t)8 * Dsz;
            #pragma unroll
            for (int nt = 0; nt < 8; nt++) {
                const int d = nt * 8 + tig * 2;
                float2 v0 = make_float2(o[nt][0] * rz0, o[nt][1] * rz0);
                float2 v1 = make_float2(o[nt][2] * rz1, o[nt][3] * rz1);
                *(float2*)(out0 + d) = v0;
                *(float2*)(out1 + d) = v1;
            }
        }
    }
}

// ---------------- launch ----------------------------------------------------
extern "C" void kernel_launch(void* const* d_in, const int* in_sizes, int n_in,
                              void* d_out, int out_size)
{
    const float* x      = (const float*)d_in[0];
    const float* mask   = (const float*)d_in[1];
    const float* Wq     = (const float*)d_in[2];
    const float* Wk     = (const float*)d_in[3];
    const float* Wv     = (const float*)d_in[4];
    const float* Wout   = (const float*)d_in[5];
    const float* b_out  = (const float*)d_in[6];
    const float* planes = (const float*)d_in[7];
    const float* protos = (const float*)d_in[8];
    const float* ltemp  = (const float*)d_in[9];
    float* out = (float*)d_out;

    void *pQ, *pK, *pV, *pATT, *pbK, *pbV, *pbA, *pxp, *pattp, *pwp, *pnK, *pnV;
    cudaGetSymbolAddress(&pQ,  g_Q);
    cudaGetSymbolAddress(&pK,  g_K);
    cudaGetSymbolAddress(&pV,  g_V);
    cudaGetSymbolAddress(&pATT,g_ATT);
    cudaGetSymbolAddress(&pbK, g_bK);
    cudaGetSymbolAddress(&pbV, g_bV);
    cudaGetSymbolAddress(&pbA, g_bA);
    cudaGetSymbolAddress(&pxp,  g_xp);
    cudaGetSymbolAddress(&pattp,g_attp);
    cudaGetSymbolAddress(&pwp,  g_wp);
    cudaGetSymbolAddress(&pnK,  g_nK);
    cudaGetSymbolAddress(&pnV,  g_nV);
    unsigned* xp   = (unsigned*)pxp;
    unsigned* attp = (unsigned*)pattp;
    unsigned* wp   = (unsigned*)pwp;

    const int GS23 = 66048;
    const int GS36 = 98304;
    cudaFuncSetAttribute(pk_gemm<2,3>, cudaFuncAttributeMaxDynamicSharedMemorySize, GS23);
    cudaFuncSetAttribute(pk_gemm<3,6>, cudaFuncAttributeMaxDynamicSharedMemorySize, GS36);
    cudaFuncSetAttribute(route2_kernel, cudaFuncAttributeMaxDynamicSharedMemorySize, RT2_SMEM);
    cudaFuncSetAttribute(attn2_kernel,  cudaFuncAttributeMaxDynamicSharedMemorySize, A2_SMEM);

    dim3 gblk(256);
    dim3 ggrid(Dsz / 128, BT / 128);
    dim3 apgrid(BT / 64, Dsz / 32);

    zero_buckets<<<256, 256>>>((float*)pbK, (float*)pbV, (float*)pbA);

    apackT<3><<<apgrid, 256>>>(x, xp);
    bpack<2><<<1024, 256>>>(Wq,   wp + 0 * BPL);
    bpack<3><<<1024, 256>>>(Wk,   wp + 2 * BPL);
    bpack<2><<<1024, 256>>>(Wv,   wp + 5 * BPL);
    bpack<2><<<1024, 256>>>(Wout, wp + 7 * BPL);

    pk_gemm<2,3><<<ggrid, gblk, GS23>>>(xp, wp + 0 * BPL, (float*)pQ, mask, nullptr);
    pk_gemm<3,6><<<ggrid, gblk, GS36>>>(xp, wp + 2 * BPL, (float*)pK, mask, nullptr);
    pk_gemm<2,3><<<ggrid, gblk, GS23>>>(xp, wp + 5 * BPL, (float*)pV, mask, nullptr);

    route2_kernel<<<BHn * RT_NCHUNK, 256, RT2_SMEM>>>(
        (const float*)pK, (const float*)pV, planes, protos, ltemp,
        (float*)pbK, (float*)pbV, (float*)pbA);

    bnorm_kernel<<<BHn, 256>>>((const float*)pbK, (const float*)pbV,
                               (const float*)pbA,
                               (unsigned*)pnK, (unsigned*)pnV);

    attn2_kernel<<<BHn * 4, 256, A2_SMEM>>>(
        (const float*)pQ, (const unsigned*)pnK, (const unsigned*)pnV,
        (float*)pATT);

    apackT<2><<<apgrid, 256>>>((const float*)pATT, attp);
    pk_gemm<2,3><<<ggrid, gblk, GS23>>>(attp, wp + 7 * BPL, out, nullptr, b_out);
}

// round 16
// speedup vs baseline: 1.5986x; 1.0134x over previous
#include <cuda_runtime.h>
#include <cuda_bf16.h>
#include <math.h>

// Problem constants
#define Bsz  4
#define Tsz  4096
#define Dsz  1024
#define Hn   16
#define DIMh 64
#define Ln   8
#define KBn  4
#define Rn   16
#define Sn   128
#define BT   (Bsz*Tsz)      // 16384
#define BHn  (Bsz*Hn)       // 64

// ---------------- scratch (device globals: no allocation allowed) ----------
__device__ float g_Q  [(size_t)BT*Dsz];
__device__ float g_K  [(size_t)BT*Dsz];
__device__ float g_V  [(size_t)BT*Dsz];
__device__ float g_bK [(size_t)BHn*Sn*DIMh];
__device__ float g_bV [(size_t)BHn*Sn*DIMh];
__device__ float g_bA [(size_t)BHn*Sn];

// packed bf16x2 split planes, FRAGMENT-NATIVE layout:
// A plane word addr = (kchunk*8192 + mf)*16 + tig*4 + slot   (mf=(m>>4)*8+(m&7))
// B plane word addr = (kchunk*1024 + n)*8  + tig*2 + slot
#define APL ((size_t)512*16384)     // words per activation plane
#define BPL ((size_t)512*1024)      // words per weight plane
__device__ unsigned g_xp  [3*APL];
__device__ unsigned g_attp[2*APL];
__device__ unsigned g_wp  [9*BPL];  // Wq(2) Wk(3) Wv(2) Wout(2)

// normalized bucket split planes
#define KPL ((size_t)BHn*32*Sn)
#define VPL ((size_t)BHn*64*DIMh)
__device__ unsigned g_nK[2*KPL];
__device__ unsigned g_nV[2*VPL];

// ======================= helpers ============================================
__device__ __forceinline__ unsigned smem_u32(const void* p) {
    unsigned a;
    asm("{ .reg .u64 t; cvta.to.shared.u64 t, %1; cvt.u32.u64 %0, t; }"
        : "=r"(a) : "l"(p));
    return a;
}

__device__ __forceinline__ void mma_bf16(float c[4], const unsigned a[4],
                                         const unsigned b[2]) {
    asm volatile(
        "mma.sync.aligned.m16n8k16.row.col.f32.bf16.bf16.f32 "
        "{%0,%1,%2,%3}, {%4,%5,%6,%7}, {%8,%9}, {%0,%1,%2,%3};"
        : "+f"(c[0]), "+f"(c[1]), "+f"(c[2]), "+f"(c[3])
        : "r"(a[0]), "r"(a[1]), "r"(a[2]), "r"(a[3]), "r"(b[0]), "r"(b[1]));
}

__device__ __forceinline__ void cpasync16(unsigned saddr, const void* gptr) {
    asm volatile("cp.async.cg.shared.global [%0], [%1], 16;"
                 :: "r"(saddr), "l"(gptr));
}

__device__ __forceinline__ unsigned pack2bf(float x0, float x1) {
    __nv_bfloat16 b0 = __float2bfloat16_rn(x0);
    __nv_bfloat16 b1 = __float2bfloat16_rn(x1);
    return (unsigned)__bfloat16_as_ushort(b0) |
           ((unsigned)__bfloat16_as_ushort(b1) << 16);
}

// ================= pack kernels (one-shot, fragment-native) =================
template<int NS>
__global__ void __launch_bounds__(256)
apackT(const float* __restrict__ X, unsigned* __restrict__ out)
{
    __shared__ float tile[64][36];   // 144 B stride (16B-aligned)
    const int tid = threadIdx.x;
    const int m0 = blockIdx.x * 64, k0 = blockIdx.y * 32;

    #pragma unroll
    for (int j = 0; j < 2; j++) {
        const int flat = tid + j * 256;
        const int row = flat >> 3, c4 = (flat & 7) * 4;
        *(float4*)&tile[row][c4] =
            *(const float4*)(X + (size_t)(m0 + row) * 1024 + k0 + c4);
    }
    __syncthreads();

    const int ic   = tid >> 7;
    const int rem  = tid & 127;
    const int tigf = rem & 3;
    const int mfl  = rem >> 2;
    const int ml   = ((mfl >> 3) << 4) | (mfl & 7);
    const int kb   = ic * 16 + tigf * 2;

    float f[8];
    f[0] = tile[ml][kb];         f[1] = tile[ml][kb + 1];
    f[2] = tile[ml + 8][kb];     f[3] = tile[ml + 8][kb + 1];
    f[4] = tile[ml][kb + 8];     f[5] = tile[ml][kb + 9];
    f[6] = tile[ml + 8][kb + 8]; f[7] = tile[ml + 8][kb + 9];

    const size_t frag = (size_t)((k0 >> 4) + ic) * 8192 + (m0 >> 1) + mfl;
    uint4* o4 = (uint4*)out;
    #pragma unroll
    for (int s = 0; s < NS; s++) {
        uint4 v;
        unsigned* vw = (unsigned*)&v;
        #pragma unroll
        for (int w = 0; w < 4; w++) {
            __nv_bfloat16 b0 = __float2bfloat16_rn(f[2 * w]);
            __nv_bfloat16 b1 = __float2bfloat16_rn(f[2 * w + 1]);
            vw[w] = (unsigned)__bfloat16_as_ushort(b0) |
                    ((unsigned)__bfloat16_as_ushort(b1) << 16);
            f[2 * w]     -= __bfloat162float(b0);
            f[2 * w + 1] -= __bfloat162float(b1);
        }
        o4[s * (APL >> 2) + frag * 4 + tigf] = v;
    }
}

template<int NS>
__global__ void __launch_bounds__(256)
bpack(const float* __restrict__ W, unsigned* __restrict__ out)
{
    const int gidx = blockIdx.x * 256 + threadIdx.x;
    const int tigf = gidx & 3;
    const int n    = (gidx >> 2) & 1023;
    const int i    = gidx >> 12;
    const int kbase = i * 16 + tigf * 2;

    float f[4];
    f[0] = W[(size_t)(kbase)     * 1024 + n];
    f[1] = W[(size_t)(kbase + 1) * 1024 + n];
    f[2] = W[(size_t)(kbase + 8) * 1024 + n];
    f[3] = W[(size_t)(kbase + 9) * 1024 + n];

    uint2* o2 = (uint2*)out;
    #pragma unroll
    for (int s = 0; s < NS; s++) {
        uint2 v;
        __nv_bfloat16 a0 = __float2bfloat16_rn(f[0]);
        __nv_bfloat16 a1 = __float2bfloat16_rn(f[1]);
        __nv_bfloat16 a2 = __float2bfloat16_rn(f[2]);
        __nv_bfloat16 a3 = __float2bfloat16_rn(f[3]);
        v.x = (unsigned)__bfloat16_as_ushort(a0) |
              ((unsigned)__bfloat16_as_ushort(a1) << 16);
        v.y = (unsigned)__bfloat16_as_ushort(a2) |
              ((unsigned)__bfloat16_as_ushort(a3) << 16);
        f[0] -= __bfloat162float(a0); f[1] -= __bfloat162float(a1);
        f[2] -= __bfloat162float(a2); f[3] -= __bfloat162float(a3);
        o2[s * (BPL >> 1) + (size_t)(i * 1024 + n) * 4 + tigf] = v;
    }
}

// ================= packed-input bf16 split GEMM (single-sync pipeline) ======
template<int NSPLIT>
__global__ void __launch_bounds__(256, 2)
pk_gemm(const unsigned* __restrict__ Ap, const unsigned* __restrict__ Bp,
        float* __restrict__ C,
        const float* __restrict__ rowscale, const float* __restrict__ bias)
{
    extern __shared__ float sm[];
    unsigned* smu = (unsigned*)sm;
    const unsigned sbase = smem_u32(smu);
    const int tid  = threadIdx.x;
    const int warp = tid >> 5, lane = tid & 31;
    const int wm = warp >> 2, wn = warp & 3;
    const int gid = lane >> 2, tig = lane & 3;
    const int m0 = blockIdx.y * 128, n0 = blockIdx.x * 128;

    constexpr int BUF = NSPLIT * 2048;     // words per stage

    float cacc[16][4];
    #pragma unroll
    for (int i = 0; i < 16; i++)
        #pragma unroll
        for (int j = 0; j < 4; j++) cacc[i][j] = 0.f;

    const size_t aoff0 = (size_t)m0 * 8 + tid * 4;
    const size_t boff0 = (size_t)n0 * 8 + tid * 4;

    auto issue = [&](int i, int stg) {
        const unsigned sb = sbase + (unsigned)(stg * BUF) * 4;
        #pragma unroll
        for (int s = 0; s < NSPLIT; s++) {
            cpasync16(sb + (unsigned)(s * 1024 + tid * 4) * 4,
                      Ap + s * APL + (size_t)i * 131072 + aoff0);
            cpasync16(sb + (unsigned)((NSPLIT + s) * 1024 + tid * 4) * 4,
                      Bp + s * BPL + (size_t)i * 8192 + boff0);
        }
        asm volatile("cp.async.commit_group;");
    };

    issue(0, 0); issue(1, 1); issue(2, 2);

    for (int i = 0; i < 64; i++) {
        const int stg = i & 3;
        if (i < 62)       asm volatile("cp.async.wait_group 2;");
        else if (i == 62) asm volatile("cp.async.wait_group 1;");
        else              asm volatile("cp.async.wait_group 0;");
        __syncthreads();
        if (i + 3 < 64) issue(i + 3, (i + 3) & 3);

        const unsigned base = (unsigned)(stg * BUF);
        // grouped passes: load each A-split fragment once, sweep its B-splits
        #pragma unroll
        for (int a = 0; a < NSPLIT; a++) {
            const uint4* As4 = (const uint4*)(smu + base + a * 1024);
            uint4 af[4];
            #pragma unroll
            for (int mt = 0; mt < 4; mt++)
                af[mt] = As4[((wm * 4 + mt) * 8 + gid) * 4 + tig];
            #pragma unroll
            for (int bs = 0; bs < NSPLIT - a; bs++) {
                const uint2* Bs2 = (const uint2*)(smu + base + (NSPLIT + bs) * 1024);
                uint2 bfr[4];
                #pragma unroll
                for (int nt = 0; nt < 4; nt++)
                    bfr[nt] = Bs2[(wn * 32 + nt * 8 + gid) * 4 + tig];
                #pragma unroll
                for (int mt = 0; mt < 4; mt++)
                    #pragma unroll
                    for (int nt = 0; nt < 4; nt++)
                        mma_bf16(cacc[mt * 4 + nt],
                                 (const unsigned*)&af[mt],
                                 (const unsigned*)&bfr[nt]);
            }
        }
    }
    __syncthreads();   // all MMAs done before epilogue reuses smem

    // ---- epilogue: stage C to smem, then coalesced writeout ----
    float* st = sm;
    #pragma unroll
    for (int mt = 0; mt < 4; mt++) {
        #pragma unroll
        for (int nt = 0; nt < 4; nt++) {
            const float* c = cacc[mt * 4 + nt];
            const int r  = wm * 64 + mt * 16 + gid;
            const int cc = wn * 32 + nt * 8 + (tig << 1);
            st[r * 129 + cc]           = c[0];
            st[r * 129 + cc + 1]       = c[1];
            st[(r + 8) * 129 + cc]     = c[2];
            st[(r + 8) * 129 + cc + 1] = c[3];
        }
    }
    __syncthreads();
    #pragma unroll 4
    for (int it = 0; it < 64; it++) {
        const int flat = tid + it * 256;
        const int rr = flat >> 7, cc = flat & 127;
        float v = st[rr * 129 + cc];
        if (rowscale) v *= rowscale[m0 + rr];
        if (bias)     v += bias[n0 + cc];
        C[(size_t)(m0 + rr) * 1024 + n0 + cc] = v;
    }
}

// ---------------- zero bucket accumulators ---------------------------------
__global__ void zero_buckets(float* __restrict__ bK, float* __restrict__ bV,
                             float* __restrict__ bA)
{
    int n = BHn * Sn * DIMh;
    for (int i = blockIdx.x * blockDim.x + threadIdx.x; i < n;
         i += gridDim.x * blockDim.x) { bK[i] = 0.f; bV[i] = 0.f; }
    int na = BHn * Sn;
    for (int i = blockIdx.x * blockDim.x + threadIdx.x; i < na;
         i += gridDim.x * blockDim.x) bA[i] = 0.f;
}

// ================= routing + bucket accumulation via MMA ====================
#define RT_CHUNK   512
#define RT_NCHUNK  (Tsz / RT_CHUNK)   // 8
#define RT_NTILE   (RT_CHUNK / 64)    // 8

#define OFF_SW    0
#define OFF_SIDX  8192
#define OFF_SA    10240
#define OFF_SPL   10368
#define OFF_SPR   12416
#define OFF_ASG0  12480
#define OFF_ASG1  16832
#define OFF_KT0   21184
#define OFF_KT1   23488
#define OFF_VT0   25792
#define OFF_VT1   28096
#define RT2_WORDS 30400
#define RT2_SMEM  (RT2_WORDS * 4)

__global__ void __launch_bounds__(256, 1)
route2_kernel(const float* __restrict__ K, const float* __restrict__ V,
              const float* __restrict__ planes_T,
              const float* __restrict__ protos_T,
              const float* __restrict__ ltemp,
              float* __restrict__ bK, float* __restrict__ bV,
              float* __restrict__ bA)
{
    extern __shared__ float smf[];
    unsigned* smw = (unsigned*)smf;
    unsigned char* sidxb = (unsigned char*)(smw + OFF_SIDX);
    unsigned* sw = smw + OFF_SW;
    float* sA  = smf + OFF_SA;
    float* spl = smf + OFF_SPL;
    float* spr = smf + OFF_SPR;

    const int tid   = threadIdx.x;
    const int warp  = tid >> 5, lane = tid & 31;
    const int gid   = lane >> 2, tig = lane & 3;
    const int bh    = blockIdx.x >> 3;
    const int chunk = blockIdx.x & 7;
    const int b = bh >> 4, h = bh & 15;

    for (int i = tid; i < Sn; i += 256) sA[i] = 0.f;
    for (int i = tid; i < DIMh * 32; i += 256) spl[i] = planes_T[i];
    for (int i = tid; i < KBn * Rn; i += 256) spr[i] = protos_T[i];
    __syncthreads();

    float scale = expf(ltemp[0]);
    scale = fminf(fmaxf(scale, 0.01f), 20.0f);
    const float inv_scale = 1.0f / scale;

    // ---------- Phase A: routing for 512 tokens ----------
    for (int tt = 0; tt < 2; tt++) {
        const int tl = tt * 256 + tid;
        const int t  = chunk * RT_CHUNK + tl;
        const float* krow = K + ((size_t)(b * Tsz + t)) * Dsz + h * DIMh;

        float proj[32];
        #pragma unroll
        for (int p = 0; p < 32; p++) proj[p] = 0.f;
        #pragma unroll 4
        for (int d = 0; d < DIMh; d++) {
            float kd = krow[d];
            #pragma unroll
            for (int p = 0; p < 32; p++) proj[p] += kd * spl[d * 32 + p];
        }
        #pragma unroll
        for (int p = 0; p < 32; p++) proj[p] = tanhf(proj[p]) * inv_scale;

        #pragma unroll
        for (int l = 0; l < Ln; l++) {
            float e[16];
            float mx = -1e30f;
            #pragma unroll
            for (int r = 0; r < Rn; r++) {
                float lg = proj[l*4+0] * spr[0*Rn + r] + proj[l*4+1] * spr[1*Rn + r]
                         + proj[l*4+2] * spr[2*Rn + r] + proj[l*4+3] * spr[3*Rn + r];
                e[r] = lg;
                mx = fmaxf(mx, lg);
            }
            float Z = 0.f;
            #pragma unroll
            for (int r = 0; r < Rn; r++) { e[r] = expf(e[r] - mx); Z += e[r]; }
            int i1 = 0; float b1 = e[0];
            #pragma unroll
            for (int r = 1; r < Rn; r++) if (e[r] > b1) { b1 = e[r]; i1 = r; }
            int i2 = -1; float b2 = -1.f;
            #pragma unroll
            for (int r = 0; r < Rn; r++) if (r != i1 && e[r] > b2) { b2 = e[r]; i2 = r; }
            const float denom = 1.0f / (b1 + b2 + 1e-6f * Z);
            const float w1f = b1 * denom, w2f = b2 * denom;

            __nv_bfloat16 w10 = __float2bfloat16_rn(w1f);
            __nv_bfloat16 w11 = __float2bfloat16_rn(w1f - __bfloat162float(w10));
            __nv_bfloat16 w20 = __float2bfloat16_rn(w2f);
            __nv_bfloat16 w21 = __float2bfloat16_rn(w2f - __bfloat162float(w20));

            const int s1 = l * Rn + i1, s2 = l * Rn + i2;
            sidxb[tl * 16 + l * 2]     = (unsigned char)s1;
            sidxb[tl * 16 + l * 2 + 1] = (unsigned char)s2;
            sw[tl * 16 + l * 2] =
                (unsigned)__bfloat16_as_ushort(w10) |
                ((unsigned)__bfloat16_as_ushort(w11) << 16);
            sw[tl * 16 + l * 2 + 1] =
                (unsigned)__bfloat16_as_ushort(w20) |
                ((unsigned)__bfloat16_as_ushort(w21) << 16);
            atomicAdd(&sA[s1], w1f);
            atomicAdd(&sA[s2], w2f);
        }
    }
    __syncthreads();
    if (tid < Sn) atomicAdd(&bA[(size_t)bh * Sn + tid], sA[tid]);

    // ---------- Phase B: MMA bucketing ----------
    float acc[16][4];
    #pragma unroll
    for (int i = 0; i < 16; i++)
        #pragma unroll
        for (int j = 0; j < 4; j++) acc[i][j] = 0.f;

    const int tok  = tid >> 2;
    const int dqq  = (tid & 3) * 16;
    const int tp_w = tok >> 1, half_w = tok & 1;

    for (int tile = 0; tile < RT_NTILE; tile++) {
        __syncthreads();   // prior MMA done: ASG + KT/VT free

        {
            uint4 z = make_uint4(0u, 0u, 0u, 0u);
            uint4* a0 = (uint4*)(smw + OFF_ASG0);
            uint4* a1 = (uint4*)(smw + OFF_ASG1);
            for (int i = tid; i < 1088; i += 256) { a0[i] = z; a1[i] = z; }

            const int tglob = chunk * RT_CHUNK + tile * 64 + tok;
            const float* kr = K + ((size_t)(b * Tsz + tglob)) * Dsz + h * DIMh;
            const float* vr = V + ((size_t)(b * Tsz + tglob)) * Dsz + h * DIMh;
            unsigned short* k0h = (unsigned short*)(smw + OFF_KT0);
            unsigned short* k1h = (unsigned short*)(smw + OFF_KT1);
            unsigned short* v0h = (unsigned short*)(smw + OFF_VT0);
            unsigned short* v1h = (unsigned short*)(smw + OFF_VT1);
            #pragma unroll
            for (int i4 = 0; i4 < 4; i4++) {
                float4 kv = *(const float4*)(kr + dqq + i4 * 4);
                float4 vv = *(const float4*)(vr + dqq + i4 * 4);
                float kf[4] = {kv.x, kv.y, kv.z, kv.w};
                float vf[4] = {vv.x, vv.y, vv.z, vv.w};
                #pragma unroll
                for (int e = 0; e < 4; e++) {
                    const int d = dqq + i4 * 4 + e;
                    const int widx = (tp_w * 72 + d) * 2 + half_w;
                    __nv_bfloat16 k0 = __float2bfloat16_rn(kf[e]);
                    __nv_bfloat16 k1 = __float2bfloat16_rn(kf[e] - __bfloat162float(k0));
                    __nv_bfloat16 v0 = __float2bfloat16_rn(vf[e]);
                    __nv_bfloat16 v1 = __float2bfloat16_rn(vf[e] - __bfloat162float(v0));
                    k0h[widx] = __bfloat16_as_ushort(k0);
                    k1h[widx] = __bfloat16_as_ushort(k1);
                    v0h[widx] = __bfloat16_as_ushort(v0);
                    v1h[widx] = __bfloat16_as_ushort(v1);
                }
            }
        }
        __syncthreads();

        {
            unsigned short* a0h = (unsigned short*)(smw + OFF_ASG0);
            unsigned short* a1h = (unsigned short*)(smw + OFF_ASG1);
            #pragma unroll
            for (int it = 0; it < 4; it++) {
                const int e  = tid + it * 256;
                const int tl = tile * 64 + (e >> 4);
                const int j  = e & 15;
                const int s  = sidxb[tl * 16 + j];
                const unsigned wp = sw[tl * 16 + j];
                const int tt2 = e >> 4;
                const int widx = ((tt2 >> 1) * 136 + s) * 2 + (tt2 & 1);
                a0h[widx] = (unsigned short)(wp & 0xffffu);
                a1h[widx] = (unsigned short)(wp >> 16);
            }
        }
        __syncthreads();

        const unsigned* asg0 = smw + OFF_ASG0;
        const unsigned* asg1 = smw + OFF_ASG1;
        const unsigned* kt0  = smw + OFF_KT0;
        const unsigned* kt1  = smw + OFF_KT1;
        const unsigned* vt0  = smw + OFF_VT0;
        const unsigned* vt1  = smw + OFF_VT1;
        #pragma unroll
        for (int ks = 0; ks < 4; ks++) {
            const int r0 = ks * 8 + tig, r1 = ks * 8 + tig + 4;
            const int mb = warp * 16 + gid;
            unsigned a0f[4], a1f[4];
            a0f[0] = asg0[r0 * 136 + mb]; a0f[1] = asg0[r0 * 136 + mb + 8];
            a0f[2] = asg0[r1 * 136 + mb]; a0f[3] = asg0[r1 * 136 + mb + 8];
            a1f[0] = asg1[r0 * 136 + mb]; a1f[1] = asg1[r0 * 136 + mb + 8];
            a1f[2] = asg1[r1 * 136 + mb]; a1f[3] = asg1[r1 * 136 + mb + 8];
            #pragma unroll
            for (int nt = 0; nt < 8; nt++) {
                const int nb = nt * 8 + gid;
                unsigned bk0[2], bk1[2], bv0[2], bv1[2];
                bk0[0] = kt0[r0 * 72 + nb]; bk0[1] = kt0[r1 * 72 + nb];
                bk1[0] = kt1[r0 * 72 + nb]; bk1[1] = kt1[r1 * 72 + nb];
                bv0[0] = vt0[r0 * 72 + nb]; bv0[1] = vt0[r1 * 72 + nb];
                bv1[0] = vt1[r0 * 72 + nb]; bv1[1] = vt1[r1 * 72 + nb];
                mma_bf16(acc[nt], a0f, bk0);
                mma_bf16(acc[nt], a0f, bk1);
                mma_bf16(acc[nt], a1f, bk0);
                mma_bf16(acc[8 + nt], a0f, bv0);
                mma_bf16(acc[8 + nt], a0f, bv1);
                mma_bf16(acc[8 + nt], a1f, bv0);
            }
        }
    }

    {
        const size_t base = (size_t)bh * Sn * DIMh;
        const int s0 = warp * 16 + gid, s1 = s0 + 8;
        #pragma unroll
        for (int nt = 0; nt < 8; nt++) {
            const int d = nt * 8 + tig * 2;
            atomicAdd(&bK[base + s0 * 64 + d],     acc[nt][0]);
            atomicAdd(&bK[base + s0 * 64 + d + 1], acc[nt][1]);
            atomicAdd(&bK[base + s1 * 64 + d],     acc[nt][2]);
            atomicAdd(&bK[base + s1 * 64 + d + 1], acc[nt][3]);
            atomicAdd(&bV[base + s0 * 64 + d],     acc[8 + nt][0]);
            atomicAdd(&bV[base + s0 * 64 + d + 1], acc[8 + nt][1]);
            atomicAdd(&bV[base + s1 * 64 + d],     acc[8 + nt][2]);
            atomicAdd(&bV[base + s1 * 64 + d + 1], acc[8 + nt][3]);
        }
    }
}

// ============ normalize buckets + split-pack for MMA attention ==============
__global__ void __launch_bounds__(256)
bnorm_kernel(const float* __restrict__ bK, const float* __restrict__ bV,
             const float* __restrict__ bA,
             unsigned* __restrict__ Kp, unsigned* __restrict__ Vp)
{
    __shared__ float inv[Sn];
    const int bh = blockIdx.x;
    const int tid = threadIdx.x;
    if (tid < Sn) inv[tid] = 1.0f / (bA[(size_t)bh * Sn + tid] + 1e-6f);
    __syncthreads();

    const size_t base = (size_t)bh * Sn * DIMh;
    for (int i = tid; i < 32 * Sn; i += 256) {
        const int kw = i >> 7, s = i & 127;
        float x0 = bK[base + s * 64 + 2 * kw]     * inv[s];
        float x1 = bK[base + s * 64 + 2 * kw + 1] * inv[s];
        __nv_bfloat16 b0 = __float2bfloat16_rn(x0);
        __nv_bfloat16 b1 = __float2bfloat16_rn(x1);
        Kp[0 * KPL + (size_t)bh * (32 * Sn) + i] = pack2bf(x0, x1);
        Kp[1 * KPL + (size_t)bh * (32 * Sn) + i] =
            pack2bf(x0 - __bfloat162float(b0), x1 - __bfloat162float(b1));
    }
    for (int i = tid; i < 64 * DIMh; i += 256) {
        const int kwb = i >> 6, d = i & 63;
        float x0 = bV[base + (2 * kwb) * 64 + d]     * inv[2 * kwb];
        float x1 = bV[base + (2 * kwb + 1) * 64 + d] * inv[2 * kwb + 1];
        __nv_bfloat16 b0 = __float2bfloat16_rn(x0);
        __nv_bfloat16 b1 = __float2bfloat16_rn(x1);
        Vp[0 * VPL + (size_t)bh * (64 * DIMh) + i] = pack2bf(x0, x1);
        Vp[1 * VPL + (size_t)bh * (64 * DIMh) + i] =
            pack2bf(x0 - __bfloat162float(b0), x1 - __bfloat162float(b1));
    }
}

// ================= MMA bucket attention (emits packed attp directly) ========
#define A2_QS0  0
#define A2_QS1  4352
#define A2_KS0  8704
#define A2_KS1  13056
#define A2_VS0  17408
#define A2_VS1  22016
#define A2_WORDS 26624
#define A2_SMEM  (A2_WORDS * 4)

__global__ void __launch_bounds__(256, 1)
attn2_kernel(const float* __restrict__ Q,
             const unsigned* __restrict__ Kp, const unsigned* __restrict__ Vp,
             unsigned* __restrict__ attp)
{
    extern __shared__ float smf[];
    unsigned* smw = (unsigned*)smf;
    const int tid   = threadIdx.x;
    const int warp  = tid >> 5, lane = tid & 31;
    const int gid   = lane >> 2, tig = lane & 3;
    const int bh    = blockIdx.x >> 2;
    const int chunk = blockIdx.x & 3;
    const int b = bh >> 4, h = bh & 15;

    {
        const unsigned* kp0 = Kp + 0 * KPL + (size_t)bh * (32 * Sn);
        const unsigned* kp1 = Kp + 1 * KPL + (size_t)bh * (32 * Sn);
        for (int i = tid; i < 32 * Sn; i += 256) {
            const int kw = i >> 7, n = i & 127;
            smw[A2_KS0 + kw * 136 + n] = kp0[i];
            smw[A2_KS1 + kw * 136 + n] = kp1[i];
        }
        const unsigned* vp0 = Vp + 0 * VPL + (size_t)bh * (64 * DIMh);
        const unsigned* vp1 = Vp + 1 * VPL + (size_t)bh * (64 * DIMh);
        for (int i = tid; i < 64 * DIMh; i += 256) {
            const int kwb = i >> 6, n = i & 63;
            smw[A2_VS0 + kwb * 72 + n] = vp0[i];
            smw[A2_VS1 + kwb * 72 + n] = vp1[i];
        }
    }

    const int qm    = tid >> 1;
    const int qhalf = (tid & 1) * 32;

    for (int tile = 0; tile < 8; tile++) {
        const int t0 = chunk * 1024 + tile * 128;
        __syncthreads();

        {
            const float* qr = Q + ((size_t)(b * Tsz + t0 + qm)) * Dsz + h * DIMh + qhalf;
            #pragma unroll
            for (int j4 = 0; j4 < 8; j4++) {
                float4 qv = *(const float4*)(qr + j4 * 4);
                float qf[4] = {qv.x * 0.125f, qv.y * 0.125f, qv.z * 0.125f, qv.w * 0.125f};
                #pragma unroll
                for (int w = 0; w < 2; w++) {
                    const int kw = (qhalf >> 1) + j4 * 2 + w;
                    float x0 = qf[2 * w], x1 = qf[2 * w + 1];
                    __nv_bfloat16 b0 = __float2bfloat16_rn(x0);
                    __nv_bfloat16 b1 = __float2bfloat16_rn(x1);
                    smw[A2_QS0 + kw * 136 + qm] = pack2bf(x0, x1);
                    smw[A2_QS1 + kw * 136 + qm] =
                        pack2bf(x0 - __bfloat162float(b0), x1 - __bfloat162float(b1));
                }
            }
        }
        __syncthreads();

        float c[16][4];
        #pragma unroll
        for (int i = 0; i < 16; i++)
            #pragma unroll
            for (int j = 0; j < 4; j++) c[i][j] = 0.f;

        #pragma unroll
        for (int ks = 0; ks < 4; ks++) {
            const int r0 = ks * 8 + tig, r1 = ks * 8 + tig + 4;
            const int mb = warp * 16 + gid;
            unsigned aq0[4], aq1[4];
            aq0[0] = smw[A2_QS0 + r0 * 136 + mb]; aq0[1] = smw[A2_QS0 + r0 * 136 + mb + 8];
            aq0[2] = smw[A2_QS0 + r1 * 136 + mb]; aq0[3] = smw[A2_QS0 + r1 * 136 + mb + 8];
            aq1[0] = smw[A2_QS1 + r0 * 136 + mb]; aq1[1] = smw[A2_QS1 + r0 * 136 + mb + 8];
            aq1[2] = smw[A2_QS1 + r1 * 136 + mb]; aq1[3] = smw[A2_QS1 + r1 * 136 + mb + 8];
            #pragma unroll
            for (int nt = 0; nt < 16; nt++) {
                const int nb = nt * 8 + gid;
                unsigned bk0[2], bk1[2];
                bk0[0] = smw[A2_KS0 + r0 * 136 + nb]; bk0[1] = smw[A2_KS0 + r1 * 136 + nb];
                bk1[0] = smw[A2_KS1 + r0 * 136 + nb]; bk1[1] = smw[A2_KS1 + r1 * 136 + nb];
                mma_bf16(c[nt], aq0, bk0);
                mma_bf16(c[nt], aq0, bk1);
                mma_bf16(c[nt], aq1, bk0);
            }
        }

        float mx0 = -1e30f, mx1 = -1e30f;
        #pragma unroll
        for (int nt = 0; nt < 16; nt++) {
            mx0 = fmaxf(mx0, fmaxf(c[nt][0], c[nt][1]));
            mx1 = fmaxf(mx1, fmaxf(c[nt][2], c[nt][3]));
        }
        #pragma unroll
        for (int o = 1; o < 4; o <<= 1) {
            mx0 = fmaxf(mx0, __shfl_xor_sync(0xffffffffu, mx0, o));
            mx1 = fmaxf(mx1, __shfl_xor_sync(0xffffffffu, mx1, o));
        }
        float z0 = 0.f, z1 = 0.f;
        #pragma unroll
        for (int nt = 0; nt < 16; nt++) {
            c[nt][0] = expf(c[nt][0] - mx0); z0 += c[nt][0];
            c[nt][1] = expf(c[nt][1] - mx0); z0 += c[nt][1];
            c[nt][2] = expf(c[nt][2] - mx1); z1 += c[nt][2];
            c[nt][3] = expf(c[nt][3] - mx1); z1 += c[nt][3];
        }
        #pragma unroll
        for (int o = 1; o < 4; o <<= 1) {
            z0 += __shfl_xor_sync(0xffffffffu, z0, o);
            z1 += __shfl_xor_sync(0xffffffffu, z1, o);
        }
        const float rz0 = 1.0f / z0, rz1 = 1.0f / z1;

        float o[8][4];
        #pragma unroll
        for (int i = 0; i < 8; i++)
            #pragma unroll
            for (int j = 0; j < 4; j++) o[i][j] = 0.f;

        #pragma unroll
        for (int ki = 0; ki < 8; ki++) {
            unsigned e0[4], e1[4];
            #pragma unroll
            for (int half = 0; half < 2; half++) {
                const float* cc0 = c[2 * ki + half];
                __nv_bfloat16 p00 = __float2bfloat16_rn(cc0[0]);
                __nv_bfloat16 p01 = __float2bfloat16_rn(cc0[1]);
                __nv_bfloat16 p10 = __float2bfloat16_rn(cc0[2]);
                __nv_bfloat16 p11 = __float2bfloat16_rn(cc0[3]);
                e0[half * 2 + 0] = (unsigned)__bfloat16_as_ushort(p00) |
                                   ((unsigned)__bfloat16_as_ushort(p01) << 16);
                e0[half * 2 + 1] = (unsigned)__bfloat16_as_ushort(p10) |
                                   ((unsigned)__bfloat16_as_ushort(p11) << 16);
                e1[half * 2 + 0] = pack2bf(cc0[0] - __bfloat162float(p00),
                                           cc0[1] - __bfloat162float(p01));
                e1[half * 2 + 1] = pack2bf(cc0[2] - __bfloat162float(p10),
                                           cc0[3] - __bfloat162float(p11));
            }
            #pragma unroll
            for (int nt = 0; nt < 8; nt++) {
                const int nb = nt * 8 + gid;
                const int r0 = ki * 8 + tig, r1 = ki * 8 + tig + 4;
                unsigned bv0[2], bv1[2];
                bv0[0] = smw[A2_VS0 + r0 * 72 + nb]; bv0[1] = smw[A2_VS0 + r1 * 72 + nb];
                bv1[0] = smw[A2_VS1 + r0 * 72 + nb]; bv1[1] = smw[A2_VS1 + r1 * 72 + nb];
                mma_bf16(o[nt], e0, bv0);
                mma_bf16(o[nt], e0, bv1);
                mma_bf16(o[nt], e1, bv0);
            }
        }

        // ---- write O directly as fragment-native bf16x2 split planes ----
        // rows (m, m+8) with m = b*Tsz + t0 + warp*16 + gid share one mf;
        // k-chunk kc covers nt = 2kc (k-lo) and 2kc+1 (k-hi): slots 0..3.
        {
            const int bt16 = (b * Tsz + t0 + warp * 16) >> 4;
            const size_t mf = (size_t)bt16 * 8 + gid;
            uint4* a0p = (uint4*)attp;
            uint4* a1p = (uint4*)(attp + APL);
            #pragma unroll
            for (int kc = 0; kc < 4; kc++) {
                const size_t idx4 = ((size_t)(h * 4 + kc) * 8192 + mf) * 4 + tig;
                float v[8] = {
                    o[2*kc][0] * rz0,   o[2*kc][1] * rz0,
                    o[2*kc][2] * rz1,   o[2*kc][3] * rz1,
                    o[2*kc+1][0] * rz0, o[2*kc+1][1] * rz0,
                    o[2*kc+1][2] * rz1, o[2*kc+1][3] * rz1 };
                uint4 w0, w1;
                unsigned* w0w = (unsigned*)&w0;
                unsigned* w1w = (unsigned*)&w1;
                #pragma unroll
                for (int j = 0; j < 4; j++) {
                    float x0 = v[2*j], x1 = v[2*j+1];
                    __nv_bfloat16 b0 = __float2bfloat16_rn(x0);
                    __nv_bfloat16 b1 = __float2bfloat16_rn(x1);
                    w0w[j] = (unsigned)__bfloat16_as_ushort(b0) |
                             ((unsigned)__bfloat16_as_ushort(b1) << 16);
                    w1w[j] = pack2bf(x0 - __bfloat162float(b0),
                                     x1 - __bfloat162float(b1));
                }
                a0p[idx4] = w0;
                a1p[idx4] = w1;
            }
        }
    }
}

// ---------------- launch ----------------------------------------------------
extern "C" void kernel_launch(void* const* d_in, const int* in_sizes, int n_in,
                              void* d_out, int out_size)
{
    const float* x      = (const float*)d_in[0];
    const float* mask   = (const float*)d_in[1];
    const float* Wq     = (const float*)d_in[2];
    const float* Wk     = (const float*)d_in[3];
    const float* Wv     = (const float*)d_in[4];
    const float* Wout   = (const float*)d_in[5];
    const float* b_out  = (const float*)d_in[6];
    const float* planes = (const float*)d_in[7];
    const float* protos = (const float*)d_in[8];
    const float* ltemp  = (const float*)d_in[9];
    float* out = (float*)d_out;

    void *pQ, *pK, *pV, *pbK, *pbV, *pbA, *pxp, *pattp, *pwp, *pnK, *pnV;
    cudaGetSymbolAddress(&pQ,  g_Q);
    cudaGetSymbolAddress(&pK,  g_K);
    cudaGetSymbolAddress(&pV,  g_V);
    cudaGetSymbolAddress(&pbK, g_bK);
    cudaGetSymbolAddress(&pbV, g_bV);
    cudaGetSymbolAddress(&pbA, g_bA);
    cudaGetSymbolAddress(&pxp,  g_xp);
    cudaGetSymbolAddress(&pattp,g_attp);
    cudaGetSymbolAddress(&pwp,  g_wp);
    cudaGetSymbolAddress(&pnK,  g_nK);
    cudaGetSymbolAddress(&pnV,  g_nV);
    unsigned* xp   = (unsigned*)pxp;
    unsigned* attp = (unsigned*)pattp;
    unsigned* wp   = (unsigned*)pwp;

    const int GS23 = 66048;
    const int GS36 = 98304;
    cudaFuncSetAttribute(pk_gemm<2>, cudaFuncAttributeMaxDynamicSharedMemorySize, GS23);
    cudaFuncSetAttribute(pk_gemm<3>, cudaFuncAttributeMaxDynamicSharedMemorySize, GS36);
    cudaFuncSetAttribute(route2_kernel, cudaFuncAttributeMaxDynamicSharedMemorySize, RT2_SMEM);
    cudaFuncSetAttribute(attn2_kernel,  cudaFuncAttributeMaxDynamicSharedMemorySize, A2_SMEM);

    dim3 gblk(256);
    dim3 ggrid(Dsz / 128, BT / 128);
    dim3 apgrid(BT / 64, Dsz / 32);

    // Launch order puts pk_gemm<2>(Q) at position 4 (ncu capture slot).
    zero_buckets<<<256, 256>>>((float*)pbK, (float*)pbV, (float*)pbA);   // 1
    apackT<3><<<apgrid, 256>>>(x, xp);                                   // 2
    bpack<2><<<1024, 256>>>(Wq, wp + 0 * BPL);                           // 3
    pk_gemm<2><<<ggrid, gblk, GS23>>>(xp, wp + 0 * BPL, (float*)pQ,      // 4
                                      mask, nullptr);
    bpack<3><<<1024, 256>>>(Wk, wp + 2 * BPL);                           // 5
    pk_gemm<3><<<ggrid, gblk, GS36>>>(xp, wp + 2 * BPL, (float*)pK,      // 6
                                      mask, nullptr);
    bpack<2><<<1024, 256>>>(Wv, wp + 5 * BPL);                           // 7
    pk_gemm<2><<<ggrid, gblk, GS23>>>(xp, wp + 5 * BPL, (float*)pV,      // 8
                                      mask, nullptr);

    route2_kernel<<<BHn * RT_NCHUNK, 256, RT2_SMEM>>>(                   // 9
        (const float*)pK, (const float*)pV, planes, protos, ltemp,
        (float*)pbK, (float*)pbV, (float*)pbA);

    bnorm_kernel<<<BHn, 256>>>((const float*)pbK, (const float*)pbV,     // 10
                               (const float*)pbA,
                               (unsigned*)pnK, (unsigned*)pnV);

    attn2_kernel<<<BHn * 4, 256, A2_SMEM>>>(                             // 11
        (const float*)pQ, (const unsigned*)pnK, (const unsigned*)pnV,
        attp);

    bpack<2><<<1024, 256>>>(Wout, wp + 7 * BPL);                         // 12
    pk_gemm<2><<<ggrid, gblk, GS23>>>(attp, wp + 7 * BPL, out,           // 13
                                      nullptr, b_out);
}

// round 17
// speedup vs baseline: 1.6639x; 1.0408x over previous
#include <cuda_runtime.h>
#include <cuda_bf16.h>
#include <math.h>

// Problem constants
#define Bsz  4
#define Tsz  4096
#define Dsz  1024
#define Hn   16
#define DIMh 64
#define Ln   8
#define KBn  4
#define Rn   16
#define Sn   128
#define BT   (Bsz*Tsz)      // 16384
#define BHn  (Bsz*Hn)       // 64

// ---------------- scratch (device globals: no allocation allowed) ----------
__device__ float g_Q  [(size_t)BT*Dsz];
__device__ float g_K  [(size_t)BT*Dsz];
__device__ float g_V  [(size_t)BT*Dsz];
__device__ float g_bK [(size_t)BHn*Sn*DIMh];
__device__ float g_bV [(size_t)BHn*Sn*DIMh];
__device__ float g_bA [(size_t)BHn*Sn];

// packed bf16x2 split planes, FRAGMENT-NATIVE layout:
// A plane word addr = (kchunk*8192 + mf)*16 + tig*4 + slot   (mf=(m>>4)*8+(m&7))
// B plane word addr = (kchunk*1024 + n)*8  + tig*2 + slot
#define APL ((size_t)512*16384)     // words per activation plane
#define BPL ((size_t)512*1024)      // words per weight plane
__device__ unsigned g_xp  [3*APL];
__device__ unsigned g_attp[2*APL];
__device__ unsigned g_wp  [9*BPL];  // Wq(2) Wk(3) Wv(2) Wout(2)

// normalized bucket split planes
#define KPL ((size_t)BHn*32*Sn)
#define VPL ((size_t)BHn*64*DIMh)
__device__ unsigned g_nK[2*KPL];
__device__ unsigned g_nV[2*VPL];

// ======================= helpers ============================================
__device__ __forceinline__ unsigned smem_u32(const void* p) {
    unsigned a;
    asm("{ .reg .u64 t; cvta.to.shared.u64 t, %1; cvt.u32.u64 %0, t; }"
        : "=r"(a) : "l"(p));
    return a;
}

__device__ __forceinline__ void mma_bf16(float c[4], const unsigned a[4],
                                         const unsigned b[2]) {
    asm volatile(
        "mma.sync.aligned.m16n8k16.row.col.f32.bf16.bf16.f32 "
        "{%0,%1,%2,%3}, {%4,%5,%6,%7}, {%8,%9}, {%0,%1,%2,%3};"
        : "+f"(c[0]), "+f"(c[1]), "+f"(c[2]), "+f"(c[3])
        : "r"(a[0]), "r"(a[1]), "r"(a[2]), "r"(a[3]), "r"(b[0]), "r"(b[1]));
}

__device__ __forceinline__ void cpasync16(unsigned saddr, const void* gptr) {
    asm volatile("cp.async.cg.shared.global [%0], [%1], 16;"
                 :: "r"(saddr), "l"(gptr));
}

__device__ __forceinline__ unsigned pack2bf(float x0, float x1) {
    __nv_bfloat16 b0 = __float2bfloat16_rn(x0);
    __nv_bfloat16 b1 = __float2bfloat16_rn(x1);
    return (unsigned)__bfloat16_as_ushort(b0) |
           ((unsigned)__bfloat16_as_ushort(b1) << 16);
}

// ================= pack kernels (one-shot, fragment-native) =================
template<int NS>
__global__ void __launch_bounds__(256)
apackT(const float* __restrict__ X, unsigned* __restrict__ out)
{
    __shared__ float tile[64][36];
    const int tid = threadIdx.x;
    const int m0 = blockIdx.x * 64, k0 = blockIdx.y * 32;

    #pragma unroll
    for (int j = 0; j < 2; j++) {
        const int flat = tid + j * 256;
        const int row = flat >> 3, c4 = (flat & 7) * 4;
        *(float4*)&tile[row][c4] =
            *(const float4*)(X + (size_t)(m0 + row) * 1024 + k0 + c4);
    }
    __syncthreads();

    const int ic   = tid >> 7;
    const int rem  = tid & 127;
    const int tigf = rem & 3;
    const int mfl  = rem >> 2;
    const int ml   = ((mfl >> 3) << 4) | (mfl & 7);
    const int kb   = ic * 16 + tigf * 2;

    float f[8];
    f[0] = tile[ml][kb];         f[1] = tile[ml][kb + 1];
    f[2] = tile[ml + 8][kb];     f[3] = tile[ml + 8][kb + 1];
    f[4] = tile[ml][kb + 8];     f[5] = tile[ml][kb + 9];
    f[6] = tile[ml + 8][kb + 8]; f[7] = tile[ml + 8][kb + 9];

    const size_t frag = (size_t)((k0 >> 4) + ic) * 8192 + (m0 >> 1) + mfl;
    uint4* o4 = (uint4*)out;
    #pragma unroll
    for (int s = 0; s < NS; s++) {
        uint4 v;
        unsigned* vw = (unsigned*)&v;
        #pragma unroll
        for (int w = 0; w < 4; w++) {
            __nv_bfloat16 b0 = __float2bfloat16_rn(f[2 * w]);
            __nv_bfloat16 b1 = __float2bfloat16_rn(f[2 * w + 1]);
            vw[w] = (unsigned)__bfloat16_as_ushort(b0) |
                    ((unsigned)__bfloat16_as_ushort(b1) << 16);
            f[2 * w]     -= __bfloat162float(b0);
            f[2 * w + 1] -= __bfloat162float(b1);
        }
        o4[s * (APL >> 2) + frag * 4 + tigf] = v;
    }
}

template<int NS>
__global__ void __launch_bounds__(256)
bpack(const float* __restrict__ W, unsigned* __restrict__ out)
{
    const int gidx = blockIdx.x * 256 + threadIdx.x;
    const int tigf = gidx & 3;
    const int n    = (gidx >> 2) & 1023;
    const int i    = gidx >> 12;
    const int kbase = i * 16 + tigf * 2;

    float f[4];
    f[0] = W[(size_t)(kbase)     * 1024 + n];
    f[1] = W[(size_t)(kbase + 1) * 1024 + n];
    f[2] = W[(size_t)(kbase + 8) * 1024 + n];
    f[3] = W[(size_t)(kbase + 9) * 1024 + n];

    uint2* o2 = (uint2*)out;
    #pragma unroll
    for (int s = 0; s < NS; s++) {
        uint2 v;
        __nv_bfloat16 a0 = __float2bfloat16_rn(f[0]);
        __nv_bfloat16 a1 = __float2bfloat16_rn(f[1]);
        __nv_bfloat16 a2 = __float2bfloat16_rn(f[2]);
        __nv_bfloat16 a3 = __float2bfloat16_rn(f[3]);
        v.x = (unsigned)__bfloat16_as_ushort(a0) |
              ((unsigned)__bfloat16_as_ushort(a1) << 16);
        v.y = (unsigned)__bfloat16_as_ushort(a2) |
              ((unsigned)__bfloat16_as_ushort(a3) << 16);
        f[0] -= __bfloat162float(a0); f[1] -= __bfloat162float(a1);
        f[2] -= __bfloat162float(a2); f[3] -= __bfloat162float(a3);
        o2[s * (BPL >> 1) + (size_t)(i * 1024 + n) * 4 + tigf] = v;
    }
}

// ================= packed-input bf16 split GEMM (single-sync pipeline) ======
// blockIdx.z selects (Bp, C) pair -> fused multi-output launches share tails.
template<int NSPLIT>
__global__ void __launch_bounds__(256, 2)
pk_gemm(const unsigned* __restrict__ Ap,
        const unsigned* __restrict__ Bp0, float* __restrict__ C0,
        const unsigned* __restrict__ Bp1, float* __restrict__ C1,
        const float* __restrict__ rowscale, const float* __restrict__ bias)
{
    extern __shared__ float sm[];
    unsigned* smu = (unsigned*)sm;
    const unsigned sbase = smem_u32(smu);
    const int tid  = threadIdx.x;
    const int warp = tid >> 5, lane = tid & 31;
    const int wm = warp >> 2, wn = warp & 3;
    const int gid = lane >> 2, tig = lane & 3;
    const int m0 = blockIdx.y * 128, n0 = blockIdx.x * 128;
    const unsigned* Bp = (blockIdx.z == 0) ? Bp0 : Bp1;
    float* C           = (blockIdx.z == 0) ? C0  : C1;

    constexpr int BUF = NSPLIT * 2048;     // words per stage

    float cacc[16][4];
    #pragma unroll
    for (int i = 0; i < 16; i++)
        #pragma unroll
        for (int j = 0; j < 4; j++) cacc[i][j] = 0.f;

    const size_t aoff0 = (size_t)m0 * 8 + tid * 4;
    const size_t boff0 = (size_t)n0 * 8 + tid * 4;

    auto issue = [&](int i, int stg) {
        const unsigned sb = sbase + (unsigned)(stg * BUF) * 4;
        #pragma unroll
        for (int s = 0; s < NSPLIT; s++) {
            cpasync16(sb + (unsigned)(s * 1024 + tid * 4) * 4,
                      Ap + s * APL + (size_t)i * 131072 + aoff0);
            cpasync16(sb + (unsigned)((NSPLIT + s) * 1024 + tid * 4) * 4,
                      Bp + s * BPL + (size_t)i * 8192 + boff0);
        }
        asm volatile("cp.async.commit_group;");
    };

    issue(0, 0); issue(1, 1); issue(2, 2);

    for (int i = 0; i < 64; i++) {
        const int stg = i & 3;
        if (i < 62)       asm volatile("cp.async.wait_group 2;");
        else if (i == 62) asm volatile("cp.async.wait_group 1;");
        else              asm volatile("cp.async.wait_group 0;");
        __syncthreads();
        if (i + 3 < 64) issue(i + 3, (i + 3) & 3);

        const unsigned base = (unsigned)(stg * BUF);
        #pragma unroll
        for (int a = 0; a < NSPLIT; a++) {
            const uint4* As4 = (const uint4*)(smu + base + a * 1024);
            uint4 af[4];
            #pragma unroll
            for (int mt = 0; mt < 4; mt++)
                af[mt] = As4[((wm * 4 + mt) * 8 + gid) * 4 + tig];
            #pragma unroll
            for (int bs = 0; bs < NSPLIT - a; bs++) {
                const uint2* Bs2 = (const uint2*)(smu + base + (NSPLIT + bs) * 1024);
                uint2 bfr[4];
                #pragma unroll
                for (int nt = 0; nt < 4; nt++)
                    bfr[nt] = Bs2[(wn * 32 + nt * 8 + gid) * 4 + tig];
                #pragma unroll
                for (int mt = 0; mt < 4; mt++)
                    #pragma unroll
                    for (int nt = 0; nt < 4; nt++)
                        mma_bf16(cacc[mt * 4 + nt],
                                 (const unsigned*)&af[mt],
                                 (const unsigned*)&bfr[nt]);
            }
        }
    }
    __syncthreads();

    // ---- epilogue ----
    float* st = sm;
    #pragma unroll
    for (int mt = 0; mt < 4; mt++) {
        #pragma unroll
        for (int nt = 0; nt < 4; nt++) {
            const float* c = cacc[mt * 4 + nt];
            const int r  = wm * 64 + mt * 16 + gid;
            const int cc = wn * 32 + nt * 8 + (tig << 1);
            st[r * 129 + cc]           = c[0];
            st[r * 129 + cc + 1]       = c[1];
            st[(r + 8) * 129 + cc]     = c[2];
            st[(r + 8) * 129 + cc + 1] = c[3];
        }
    }
    __syncthreads();
    #pragma unroll 4
    for (int it = 0; it < 64; it++) {
        const int flat = tid + it * 256;
        const int rr = flat >> 7, cc = flat & 127;
        float v = st[rr * 129 + cc];
        if (rowscale) v *= rowscale[m0 + rr];
        if (bias)     v += bias[n0 + cc];
        C[(size_t)(m0 + rr) * 1024 + n0 + cc] = v;
    }
}

// ---------------- zero bucket accumulators ---------------------------------
__global__ void zero_buckets(float* __restrict__ bK, float* __restrict__ bV,
                             float* __restrict__ bA)
{
    int n = BHn * Sn * DIMh;
    for (int i = blockIdx.x * blockDim.x + threadIdx.x; i < n;
         i += gridDim.x * blockDim.x) { bK[i] = 0.f; bV[i] = 0.f; }
    int na = BHn * Sn;
    for (int i = blockIdx.x * blockDim.x + threadIdx.x; i < na;
         i += gridDim.x * blockDim.x) bA[i] = 0.f;
}

// ================= routing + bucket accumulation via MMA ====================
// 256-token chunks -> ~101 KB smem -> 2 CTAs/SM.
#define RT_CHUNK   256
#define RT_NCHUNK  (Tsz / RT_CHUNK)   // 16
#define RT_NTILE   (RT_CHUNK / 64)    // 4

#define OFF_SW    0                    // 256*16 = 4096 words
#define OFF_SIDX  4096                 // 256*16 B = 1024 words
#define OFF_SA    5120                 // 128
#define OFF_SPL   5248                 // 2048
#define OFF_SPR   7296                 // 64
#define OFF_ASG0  7360                 // 4352
#define OFF_ASG1  11712                // 4352
#define OFF_KT0   16064                // 2304
#define OFF_KT1   18368
#define OFF_VT0   20672
#define OFF_VT1   22976
#define RT2_WORDS 25280
#define RT2_SMEM  (RT2_WORDS * 4)      // 101120 B

__global__ void __launch_bounds__(256, 2)
route2_kernel(const float* __restrict__ K, const float* __restrict__ V,
              const float* __restrict__ planes_T,
              const float* __restrict__ protos_T,
              const float* __restrict__ ltemp,
              float* __restrict__ bK, float* __restrict__ bV,
              float* __restrict__ bA)
{
    extern __shared__ float smf[];
    unsigned* smw = (unsigned*)smf;
    unsigned char* sidxb = (unsigned char*)(smw + OFF_SIDX);
    unsigned* sw = smw + OFF_SW;
    float* sA  = smf + OFF_SA;
    float* spl = smf + OFF_SPL;
    float* spr = smf + OFF_SPR;

    const int tid   = threadIdx.x;
    const int warp  = tid >> 5, lane = tid & 31;
    const int gid   = lane >> 2, tig = lane & 3;
    const int bh    = blockIdx.x >> 4;
    const int chunk = blockIdx.x & 15;
    const int b = bh >> 4, h = bh & 15;

    for (int i = tid; i < Sn; i += 256) sA[i] = 0.f;
    for (int i = tid; i < DIMh * 32; i += 256) spl[i] = planes_T[i];
    for (int i = tid; i < KBn * Rn; i += 256) spr[i] = protos_T[i];
    __syncthreads();

    float scale = expf(ltemp[0]);
    scale = fminf(fmaxf(scale, 0.01f), 20.0f);
    const float inv_scale = 1.0f / scale;

    // ---------- Phase A: routing for 256 tokens (1 per thread) ----------
    {
        const int tl = tid;
        const int t  = chunk * RT_CHUNK + tl;
        const float* krow = K + ((size_t)(b * Tsz + t)) * Dsz + h * DIMh;

        float proj[32];
        #pragma unroll
        for (int p = 0; p < 32; p++) proj[p] = 0.f;
        #pragma unroll 4
        for (int d = 0; d < DIMh; d++) {
            float kd = krow[d];
            #pragma unroll
            for (int p = 0; p < 32; p++) proj[p] += kd * spl[d * 32 + p];
        }
        #pragma unroll
        for (int p = 0; p < 32; p++) proj[p] = tanhf(proj[p]) * inv_scale;

        #pragma unroll
        for (int l = 0; l < Ln; l++) {
            float e[16];
            float mx = -1e30f;
            #pragma unroll
            for (int r = 0; r < Rn; r++) {
                float lg = proj[l*4+0] * spr[0*Rn + r] + proj[l*4+1] * spr[1*Rn + r]
                         + proj[l*4+2] * spr[2*Rn + r] + proj[l*4+3] * spr[3*Rn + r];
                e[r] = lg;
                mx = fmaxf(mx, lg);
            }
            float Z = 0.f;
            #pragma unroll
            for (int r = 0; r < Rn; r++) { e[r] = expf(e[r] - mx); Z += e[r]; }
            int i1 = 0; float b1 = e[0];
            #pragma unroll
            for (int r = 1; r < Rn; r++) if (e[r] > b1) { b1 = e[r]; i1 = r; }
            int i2 = -1; float b2 = -1.f;
            #pragma unroll
            for (int r = 0; r < Rn; r++) if (r != i1 && e[r] > b2) { b2 = e[r]; i2 = r; }
            const float denom = 1.0f / (b1 + b2 + 1e-6f * Z);
            const float w1f = b1 * denom, w2f = b2 * denom;

            __nv_bfloat16 w10 = __float2bfloat16_rn(w1f);
            __nv_bfloat16 w11 = __float2bfloat16_rn(w1f - __bfloat162float(w10));
            __nv_bfloat16 w20 = __float2bfloat16_rn(w2f);
            __nv_bfloat16 w21 = __float2bfloat16_rn(w2f - __bfloat162float(w20));

            const int s1 = l * Rn + i1, s2 = l * Rn + i2;
            sidxb[tl * 16 + l * 2]     = (unsigned char)s1;
            sidxb[tl * 16 + l * 2 + 1] = (unsigned char)s2;
            sw[tl * 16 + l * 2] =
                (unsigned)__bfloat16_as_ushort(w10) |
                ((unsigned)__bfloat16_as_ushort(w11) << 16);
            sw[tl * 16 + l * 2 + 1] =
                (unsigned)__bfloat16_as_ushort(w20) |
                ((unsigned)__bfloat16_as_ushort(w21) << 16);
            atomicAdd(&sA[s1], w1f);
            atomicAdd(&sA[s2], w2f);
        }
    }
    __syncthreads();
    if (tid < Sn) atomicAdd(&bA[(size_t)bh * Sn + tid], sA[tid]);

    // ---------- Phase B: MMA bucketing ----------
    float acc[16][4];
    #pragma unroll
    for (int i = 0; i < 16; i++)
        #pragma unroll
        for (int j = 0; j < 4; j++) acc[i][j] = 0.f;

    const int tok  = tid >> 2;
    const int dqq  = (tid & 3) * 16;
    const int tp_w = tok >> 1, half_w = tok & 1;

    for (int tile = 0; tile < RT_NTILE; tile++) {
        __syncthreads();

        {
            uint4 z = make_uint4(0u, 0u, 0u, 0u);
            uint4* a0 = (uint4*)(smw + OFF_ASG0);
            uint4* a1 = (uint4*)(smw + OFF_ASG1);
            for (int i = tid; i < 1088; i += 256) { a0[i] = z; a1[i] = z; }

            const int tglob = chunk * RT_CHUNK + tile * 64 + tok;
            const float* kr = K + ((size_t)(b * Tsz + tglob)) * Dsz + h * DIMh;
            const float* vr = V + ((size_t)(b * Tsz + tglob)) * Dsz + h * DIMh;
            unsigned short* k0h = (unsigned short*)(smw + OFF_KT0);
            unsigned short* k1h = (unsigned short*)(smw + OFF_KT1);
            unsigned short* v0h = (unsigned short*)(smw + OFF_VT0);
            unsigned short* v1h = (unsigned short*)(smw + OFF_VT1);
            #pragma unroll
            for (int i4 = 0; i4 < 4; i4++) {
                float4 kv = *(const float4*)(kr + dqq + i4 * 4);
                float4 vv = *(const float4*)(vr + dqq + i4 * 4);
                float kf[4] = {kv.x, kv.y, kv.z, kv.w};
                float vf[4] = {vv.x, vv.y, vv.z, vv.w};
                #pragma unroll
                for (int e = 0; e < 4; e++) {
                    const int d = dqq + i4 * 4 + e;
                    const int widx = (tp_w * 72 + d) * 2 + half_w;
                    __nv_bfloat16 k0 = __float2bfloat16_rn(kf[e]);
                    __nv_bfloat16 k1 = __float2bfloat16_rn(kf[e] - __bfloat162float(k0));
                    __nv_bfloat16 v0 = __float2bfloat16_rn(vf[e]);
                    __nv_bfloat16 v1 = __float2bfloat16_rn(vf[e] - __bfloat162float(v0));
                    k0h[widx] = __bfloat16_as_ushort(k0);
                    k1h[widx] = __bfloat16_as_ushort(k1);
                    v0h[widx] = __bfloat16_as_ushort(v0);
                    v1h[widx] = __bfloat16_as_ushort(v1);
                }
            }
        }
        __syncthreads();

        {
            unsigned short* a0h = (unsigned short*)(smw + OFF_ASG0);
            unsigned short* a1h = (unsigned short*)(smw + OFF_ASG1);
            #pragma unroll
            for (int it = 0; it < 4; it++) {
                const int e  = tid + it * 256;
                const int tl = tile * 64 + (e >> 4);
                const int j  = e & 15;
                const int s  = sidxb[tl * 16 + j];
                const unsigned wp = sw[tl * 16 + j];
                const int tt2 = e >> 4;
                const int widx = ((tt2 >> 1) * 136 + s) * 2 + (tt2 & 1);
                a0h[widx] = (unsigned short)(wp & 0xffffu);
                a1h[widx] = (unsigned short)(wp >> 16);
            }
        }
        __syncthreads();

        const unsigned* asg0 = smw + OFF_ASG0;
        const unsigned* asg1 = smw + OFF_ASG1;
        const unsigned* kt0  = smw + OFF_KT0;
        const unsigned* kt1  = smw + OFF_KT1;
        const unsigned* vt0  = smw + OFF_VT0;
        const unsigned* vt1  = smw + OFF_VT1;
        #pragma unroll
        for (int ks = 0; ks < 4; ks++) {
            const int r0 = ks * 8 + tig, r1 = ks * 8 + tig + 4;
            const int mb = warp * 16 + gid;
            unsigned a0f[4], a1f[4];
            a0f[0] = asg0[r0 * 136 + mb]; a0f[1] = asg0[r0 * 136 + mb + 8];
            a0f[2] = asg0[r1 * 136 + mb]; a0f[3] = asg0[r1 * 136 + mb + 8];
            a1f[0] = asg1[r0 * 136 + mb]; a1f[1] = asg1[r0 * 136 + mb + 8];
            a1f[2] = asg1[r1 * 136 + mb]; a1f[3] = asg1[r1 * 136 + mb + 8];
            #pragma unroll
            for (int nt = 0; nt < 8; nt++) {
                const int nb = nt * 8 + gid;
                unsigned bk0[2], bk1[2], bv0[2], bv1[2];
                bk0[0] = kt0[r0 * 72 + nb]; bk0[1] = kt0[r1 * 72 + nb];
                bk1[0] = kt1[r0 * 72 + nb]; bk1[1] = kt1[r1 * 72 + nb];
                bv0[0] = vt0[r0 * 72 + nb]; bv0[1] = vt0[r1 * 72 + nb];
                bv1[0] = vt1[r0 * 72 + nb]; bv1[1] = vt1[r1 * 72 + nb];
                mma_bf16(acc[nt], a0f, bk0);
                mma_bf16(acc[nt], a0f, bk1);
                mma_bf16(acc[nt], a1f, bk0);
                mma_bf16(acc[8 + nt], a0f, bv0);
                mma_bf16(acc[8 + nt], a0f, bv1);
                mma_bf16(acc[8 + nt], a1f, bv0);
            }
        }
    }

    {
        const size_t base = (size_t)bh * Sn * DIMh;
        const int s0 = warp * 16 + gid, s1 = s0 + 8;
        #pragma unroll
        for (int nt = 0; nt < 8; nt++) {
            const int d = nt * 8 + tig * 2;
            atomicAdd(&bK[base + s0 * 64 + d],     acc[nt][0]);
            atomicAdd(&bK[base + s0 * 64 + d + 1], acc[nt][1]);
            atomicAdd(&bK[base + s1 * 64 + d],     acc[nt][2]);
            atomicAdd(&bK[base + s1 * 64 + d + 1], acc[nt][3]);
            atomicAdd(&bV[base + s0 * 64 + d],     acc[8 + nt][0]);
            atomicAdd(&bV[base + s0 * 64 + d + 1], acc[8 + nt][1]);
            atomicAdd(&bV[base + s1 * 64 + d],     acc[8 + nt][2]);
            atomicAdd(&bV[base + s1 * 64 + d + 1], acc[8 + nt][3]);
        }
    }
}

// ============ normalize buckets + split-pack for MMA attention ==============
__global__ void __launch_bounds__(256)
bnorm_kernel(const float* __restrict__ bK, const float* __restrict__ bV,
             const float* __restrict__ bA,
             unsigned* __restrict__ Kp, unsigned* __restrict__ Vp)
{
    __shared__ float inv[Sn];
    const int bh = blockIdx.x;
    const int tid = threadIdx.x;
    if (tid < Sn) inv[tid] = 1.0f / (bA[(size_t)bh * Sn + tid] + 1e-6f);
    __syncthreads();

    const size_t base = (size_t)bh * Sn * DIMh;
    for (int i = tid; i < 32 * Sn; i += 256) {
        const int kw = i >> 7, s = i & 127;
        float x0 = bK[base + s * 64 + 2 * kw]     * inv[s];
        float x1 = bK[base + s * 64 + 2 * kw + 1] * inv[s];
        __nv_bfloat16 b0 = __float2bfloat16_rn(x0);
        __nv_bfloat16 b1 = __float2bfloat16_rn(x1);
        Kp[0 * KPL + (size_t)bh * (32 * Sn) + i] = pack2bf(x0, x1);
        Kp[1 * KPL + (size_t)bh * (32 * Sn) + i] =
            pack2bf(x0 - __bfloat162float(b0), x1 - __bfloat162float(b1));
    }
    for (int i = tid; i < 64 * DIMh; i += 256) {
        const int kwb = i >> 6, d = i & 63;
        float x0 = bV[base + (2 * kwb) * 64 + d]     * inv[2 * kwb];
        float x1 = bV[base + (2 * kwb + 1) * 64 + d] * inv[2 * kwb + 1];
        __nv_bfloat16 b0 = __float2bfloat16_rn(x0);
        __nv_bfloat16 b1 = __float2bfloat16_rn(x1);
        Vp[0 * VPL + (size_t)bh * (64 * DIMh) + i] = pack2bf(x0, x1);
        Vp[1 * VPL + (size_t)bh * (64 * DIMh) + i] =
            pack2bf(x0 - __bfloat162float(b0), x1 - __bfloat162float(b1));
    }
}

// ================= MMA bucket attention (emits packed attp directly) ========
#define A2_QS0  0
#define A2_QS1  4352
#define A2_KS0  8704
#define A2_KS1  13056
#define A2_VS0  17408
#define A2_VS1  22016
#define A2_WORDS 26624
#define A2_SMEM  (A2_WORDS * 4)

__global__ void __launch_bounds__(256, 1)
attn2_kernel(const float* __restrict__ Q,
             const unsigned* __restrict__ Kp, const unsigned* __restrict__ Vp,
             unsigned* __restrict__ attp)
{
    extern __shared__ float smf[];
    unsigned* smw = (unsigned*)smf;
    const int tid   = threadIdx.x;
    const int warp  = tid >> 5, lane = tid & 31;
    const int gid   = lane >> 2, tig = lane & 3;
    const int bh    = blockIdx.x >> 2;
    const int chunk = blockIdx.x & 3;
    const int b = bh >> 4, h = bh & 15;

    {
        const unsigned* kp0 = Kp + 0 * KPL + (size_t)bh * (32 * Sn);
        const unsigned* kp1 = Kp + 1 * KPL + (size_t)bh * (32 * Sn);
        for (int i = tid; i < 32 * Sn; i += 256) {
            const int kw = i >> 7, n = i & 127;
            smw[A2_KS0 + kw * 136 + n] = kp0[i];
            smw[A2_KS1 + kw * 136 + n] = kp1[i];
        }
        const unsigned* vp0 = Vp + 0 * VPL + (size_t)bh * (64 * DIMh);
        const unsigned* vp1 = Vp + 1 * VPL + (size_t)bh * (64 * DIMh);
        for (int i = tid; i < 64 * DIMh; i += 256) {
            const int kwb = i >> 6, n = i & 63;
            smw[A2_VS0 + kwb * 72 + n] = vp0[i];
            smw[A2_VS1 + kwb * 72 + n] = vp1[i];
        }
    }

    const int qm    = tid >> 1;
    const int qhalf = (tid & 1) * 32;

    for (int tile = 0; tile < 8; tile++) {
        const int t0 = chunk * 1024 + tile * 128;
        __syncthreads();

        {
            const float* qr = Q + ((size_t)(b * Tsz + t0 + qm)) * Dsz + h * DIMh + qhalf;
            #pragma unroll
            for (int j4 = 0; j4 < 8; j4++) {
                float4 qv = *(const float4*)(qr + j4 * 4);
                float qf[4] = {qv.x * 0.125f, qv.y * 0.125f, qv.z * 0.125f, qv.w * 0.125f};
                #pragma unroll
                for (int w = 0; w < 2; w++) {
                    const int kw = (qhalf >> 1) + j4 * 2 + w;
                    float x0 = qf[2 * w], x1 = qf[2 * w + 1];
                    __nv_bfloat16 b0 = __float2bfloat16_rn(x0);
                    __nv_bfloat16 b1 = __float2bfloat16_rn(x1);
                    smw[A2_QS0 + kw * 136 + qm] = pack2bf(x0, x1);
                    smw[A2_QS1 + kw * 136 + qm] =
                        pack2bf(x0 - __bfloat162float(b0), x1 - __bfloat162float(b1));
                }
            }
        }
        __syncthreads();

        float c[16][4];
        #pragma unroll
        for (int i = 0; i < 16; i++)
            #pragma unroll
            for (int j = 0; j < 4; j++) c[i][j] = 0.f;

        #pragma unroll
        for (int ks = 0; ks < 4; ks++) {
            const int r0 = ks * 8 + tig, r1 = ks * 8 + tig + 4;
            const int mb = warp * 16 + gid;
            unsigned aq0[4], aq1[4];
            aq0[0] = smw[A2_QS0 + r0 * 136 + mb]; aq0[1] = smw[A2_QS0 + r0 * 136 + mb + 8];
            aq0[2] = smw[A2_QS0 + r1 * 136 + mb]; aq0[3] = smw[A2_QS0 + r1 * 136 + mb + 8];
            aq1[0] = smw[A2_QS1 + r0 * 136 + mb]; aq1[1] = smw[A2_QS1 + r0 * 136 + mb + 8];
            aq1[2] = smw[A2_QS1 + r1 * 136 + mb]; aq1[3] = smw[A2_QS1 + r1 * 136 + mb + 8];
            #pragma unroll
            for (int nt = 0; nt < 16; nt++) {
                const int nb = nt * 8 + gid;
                unsigned bk0[2], bk1[2];
                bk0[0] = smw[A2_KS0 + r0 * 136 + nb]; bk0[1] = smw[A2_KS0 + r1 * 136 + nb];
                bk1[0] = smw[A2_KS1 + r0 * 136 + nb]; bk1[1] = smw[A2_KS1 + r1 * 136 + nb];
                mma_bf16(c[nt], aq0, bk0);
                mma_bf16(c[nt], aq0, bk1);
                mma_bf16(c[nt], aq1, bk0);
            }
        }

        float mx0 = -1e30f, mx1 = -1e30f;
        #pragma unroll
        for (int nt = 0; nt < 16; nt++) {
            mx0 = fmaxf(mx0, fmaxf(c[nt][0], c[nt][1]));
            mx1 = fmaxf(mx1, fmaxf(c[nt][2], c[nt][3]));
        }
        #pragma unroll
        for (int o = 1; o < 4; o <<= 1) {
            mx0 = fmaxf(mx0, __shfl_xor_sync(0xffffffffu, mx0, o));
            mx1 = fmaxf(mx1, __shfl_xor_sync(0xffffffffu, mx1, o));
        }
        float z0 = 0.f, z1 = 0.f;
        #pragma unroll
        for (int nt = 0; nt < 16; nt++) {
            c[nt][0] = expf(c[nt][0] - mx0); z0 += c[nt][0];
            c[nt][1] = expf(c[nt][1] - mx0); z0 += c[nt][1];
            c[nt][2] = expf(c[nt][2] - mx1); z1 += c[nt][2];
            c[nt][3] = expf(c[nt][3] - mx1); z1 += c[nt][3];
        }
        #pragma unroll
        for (int o = 1; o < 4; o <<= 1) {
            z0 += __shfl_xor_sync(0xffffffffu, z0, o);
            z1 += __shfl_xor_sync(0xffffffffu, z1, o);
        }
        const float rz0 = 1.0f / z0, rz1 = 1.0f / z1;

        float o[8][4];
        #pragma unroll
        for (int i = 0; i < 8; i++)
            #pragma unroll
            for (int j = 0; j < 4; j++) o[i][j] = 0.f;

        #pragma unroll
        for (int ki = 0; ki < 8; ki++) {
            unsigned e0[4], e1[4];
            #pragma unroll
            for (int half = 0; half < 2; half++) {
                const float* cc0 = c[2 * ki + half];
                __nv_bfloat16 p00 = __float2bfloat16_rn(cc0[0]);
                __nv_bfloat16 p01 = __float2bfloat16_rn(cc0[1]);
                __nv_bfloat16 p10 = __float2bfloat16_rn(cc0[2]);
                __nv_bfloat16 p11 = __float2bfloat16_rn(cc0[3]);
                e0[half * 2 + 0] = (unsigned)__bfloat16_as_ushort(p00) |
                                   ((unsigned)__bfloat16_as_ushort(p01) << 16);
                e0[half * 2 + 1] = (unsigned)__bfloat16_as_ushort(p10) |
                                   ((unsigned)__bfloat16_as_ushort(p11) << 16);
                e1[half * 2 + 0] = pack2bf(cc0[0] - __bfloat162float(p00),
                                           cc0[1] - __bfloat162float(p01));
                e1[half * 2 + 1] = pack2bf(cc0[2] - __bfloat162float(p10),
                                           cc0[3] - __bfloat162float(p11));
            }
            #pragma unroll
            for (int nt = 0; nt < 8; nt++) {
                const int nb = nt * 8 + gid;
                const int r0 = ki * 8 + tig, r1 = ki * 8 + tig + 4;
                unsigned bv0[2], bv1[2];
                bv0[0] = smw[A2_VS0 + r0 * 72 + nb]; bv0[1] = smw[A2_VS0 + r1 * 72 + nb];
                bv1[0] = smw[A2_VS1 + r0 * 72 + nb]; bv1[1] = smw[A2_VS1 + r1 * 72 + nb];
                mma_bf16(o[nt], e0, bv0);
                mma_bf16(o[nt], e0, bv1);
                mma_bf16(o[nt], e1, bv0);
            }
        }

        {
            const int bt16 = (b * Tsz + t0 + warp * 16) >> 4;
            const size_t mf = (size_t)bt16 * 8 + gid;
            uint4* a0p = (uint4*)attp;
            uint4* a1p = (uint4*)(attp + APL);
            #pragma unroll
            for (int kc = 0; kc < 4; kc++) {
                const size_t idx4 = ((size_t)(h * 4 + kc) * 8192 + mf) * 4 + tig;
                float v[8] = {
                    o[2*kc][0] * rz0,   o[2*kc][1] * rz0,
                    o[2*kc][2] * rz1,   o[2*kc][3] * rz1,
                    o[2*kc+1][0] * rz0, o[2*kc+1][1] * rz0,
                    o[2*kc+1][2] * rz1, o[2*kc+1][3] * rz1 };
                uint4 w0, w1;
                unsigned* w0w = (unsigned*)&w0;
                unsigned* w1w = (unsigned*)&w1;
                #pragma unroll
                for (int j = 0; j < 4; j++) {
                    float x0 = v[2*j], x1 = v[2*j+1];
                    __nv_bfloat16 b0 = __float2bfloat16_rn(x0);
                    __nv_bfloat16 b1 = __float2bfloat16_rn(x1);
                    w0w[j] = (unsigned)__bfloat16_as_ushort(b0) |
                             ((unsigned)__bfloat16_as_ushort(b1) << 16);
                    w1w[j] = pack2bf(x0 - __bfloat162float(b0),
                                     x1 - __bfloat162float(b1));
                }
                a0p[idx4] = w0;
                a1p[idx4] = w1;
            }
        }
    }
}

// ---------------- launch ----------------------------------------------------
extern "C" void kernel_launch(void* const* d_in, const int* in_sizes, int n_in,
                              void* d_out, int out_size)
{
    const float* x      = (const float*)d_in[0];
    const float* mask   = (const float*)d_in[1];
    const float* Wq     = (const float*)d_in[2];
    const float* Wk     = (const float*)d_in[3];
    const float* Wv     = (const float*)d_in[4];
    const float* Wout   = (const float*)d_in[5];
    const float* b_out  = (const float*)d_in[6];
    const float* planes = (const float*)d_in[7];
    const float* protos = (const float*)d_in[8];
    const float* ltemp  = (const float*)d_in[9];
    float* out = (float*)d_out;

    void *pQ, *pK, *pV, *pbK, *pbV, *pbA, *pxp, *pattp, *pwp, *pnK, *pnV;
    cudaGetSymbolAddress(&pQ,  g_Q);
    cudaGetSymbolAddress(&pK,  g_K);
    cudaGetSymbolAddress(&pV,  g_V);
    cudaGetSymbolAddress(&pbK, g_bK);
    cudaGetSymbolAddress(&pbV, g_bV);
    cudaGetSymbolAddress(&pbA, g_bA);
    cudaGetSymbolAddress(&pxp,  g_xp);
    cudaGetSymbolAddress(&pattp,g_attp);
    cudaGetSymbolAddress(&pwp,  g_wp);
    cudaGetSymbolAddress(&pnK,  g_nK);
    cudaGetSymbolAddress(&pnV,  g_nV);
    unsigned* xp   = (unsigned*)pxp;
    unsigned* attp = (unsigned*)pattp;
    unsigned* wp   = (unsigned*)pwp;
    float* Qf = (float*)pQ; float* Kf = (float*)pK; float* Vf = (float*)pV;

    const int GS23 = 66048;
    const int GS36 = 98304;
    cudaFuncSetAttribute(pk_gemm<2>, cudaFuncAttributeMaxDynamicSharedMemorySize, GS23);
    cudaFuncSetAttribute(pk_gemm<3>, cudaFuncAttributeMaxDynamicSharedMemorySize, GS36);
    cudaFuncSetAttribute(route2_kernel, cudaFuncAttributeMaxDynamicSharedMemorySize, RT2_SMEM);
    cudaFuncSetAttribute(attn2_kernel,  cudaFuncAttributeMaxDynamicSharedMemorySize, A2_SMEM);

    dim3 gblk(256);
    dim3 gridQV(Dsz / 128, BT / 128, 2);   // fused Q+V
    dim3 grid1(Dsz / 128, BT / 128, 1);
    dim3 apgrid(BT / 64, Dsz / 32);

    zero_buckets<<<256, 256>>>((float*)pbK, (float*)pbV, (float*)pbA);    // 1
    apackT<3><<<apgrid, 256>>>(x, xp);                                    // 2
    bpack<2><<<1024, 256>>>(Wq, wp + 0 * BPL);                            // 3
    bpack<2><<<1024, 256>>>(Wv, wp + 5 * BPL);                            // 4
    // fused Q+V projection (launch 5; ncu slot may land here or on #4)
    pk_gemm<2><<<gridQV, gblk, GS23>>>(xp, wp + 0 * BPL, Qf,
                                       wp + 5 * BPL, Vf, mask, nullptr);  // 5
    bpack<3><<<1024, 256>>>(Wk, wp + 2 * BPL);                            // 6
    pk_gemm<3><<<grid1, gblk, GS36>>>(xp, wp + 2 * BPL, Kf,
                                      wp + 2 * BPL, Kf, mask, nullptr);   // 7

    route2_kernel<<<BHn * RT_NCHUNK, 256, RT2_SMEM>>>(                    // 8
        Kf, Vf, planes, protos, ltemp,
        (float*)pbK, (float*)pbV, (float*)pbA);

    bnorm_kernel<<<BHn, 256>>>((const float*)pbK, (const float*)pbV,      // 9
                               (const float*)pbA,
                               (unsigned*)pnK, (unsigned*)pnV);

    attn2_kernel<<<BHn * 4, 256, A2_SMEM>>>(                              // 10
        Qf, (const unsigned*)pnK, (const unsigned*)pnV, attp);

    bpack<2><<<1024, 256>>>(Wout, wp + 7 * BPL);                          // 11
    pk_gemm<2><<<grid1, gblk, GS23>>>(attp, wp + 7 * BPL, out,            // 12
                                      wp + 7 * BPL, out, nullptr, b_out);
}